// round 1
// baseline (speedup 1.0000x reference)
#include <cuda_runtime.h>
#include <math.h>

// ---------------------------------------------------------------------------
// HSTU layer, fp32 SIMT baseline.
// Pipeline: prep(valid+buckets) -> denom -> GEMM1(silu) -> attention -> LN*U
//           -> GEMM2(+bias+residual)
// ---------------------------------------------------------------------------

#define MAXB 2
#define MAXT 1024
#define MAXD 1024
#define NBUCKETS 32

__device__ float g_H4[(size_t)MAXB * MAXT * 4 * MAXD];   // h = silu(x W_in^T + b)  [BT, 4D]
__device__ float g_AV[(size_t)MAXB * MAXT * MAXD];       // attention output        [BT, D]
__device__ float g_Z[(size_t)MAXB * MAXT * MAXD];        // normed * U              [BT, D]
__device__ float g_denom[MAXB * MAXT];
__device__ unsigned char g_valid[MAXB * MAXT];
__device__ int g_bucket[MAXT];

// ---------------------------------------------------------------------------
// prep: decode key_padding_mask (dtype-sniffed) into g_valid, build T5 bucket LUT
// ---------------------------------------------------------------------------
__global__ void prep_kernel(const void* __restrict__ kpm, int B, int T) {
    const int M = B * T;
    __shared__ int oddbyte;
    if (threadIdx.x == 0) oddbyte = 0;
    __syncthreads();
    const unsigned char* bp = (const unsigned char*)kpm;
    int local = 0;
    for (int i = threadIdx.x; i < M; i += blockDim.x)
        if (bp[i] != 0 && (i & 3) != 0) local = 1;
    if (local) atomicOr(&oddbyte, 1);
    __syncthreads();
    const int isByte = oddbyte;  // 1-byte bool/int8 vs 4-byte int32/float32 elements
    const int* ip = (const int*)kpm;
    for (int i = threadIdx.x; i < M; i += blockDim.x) {
        int pad = isByte ? (bp[i] != 0) : (ip[i] != 0);  // float 0.0f == int 0 bitwise
        g_valid[i] = pad ? 0 : 1;
    }
    // T5-style log buckets, replicating jnp float32 math + int32 truncation
    for (int n = threadIdx.x; n < T; n += blockDim.x) {
        int bkt;
        if (n < 16) {
            bkt = n;
        } else {
            float v = logf((float)n / 16.0f + 1e-6f) / 2.0794415416798357f * 16.0f;
            int lg = 16 + (int)v;
            bkt = lg < (NBUCKETS - 1) ? lg : (NBUCKETS - 1);
        }
        g_bucket[n] = bkt;
    }
}

// ---------------------------------------------------------------------------
// denom: per (b, t) count of allowed keys (mask==0 && valid), clamped at 1
// ---------------------------------------------------------------------------
__global__ void denom_kernel(const float* __restrict__ amask, int B, int T) {
    const int t = blockIdx.x;
    const int b = blockIdx.y;
    int cnt = 0;
    for (int s = threadIdx.x; s < T; s += blockDim.x)
        cnt += (amask[(size_t)t * T + s] == 0.0f && g_valid[b * T + s]) ? 1 : 0;
#pragma unroll
    for (int o = 16; o; o >>= 1) cnt += __shfl_xor_sync(0xffffffffu, cnt, o);
    __shared__ int red[8];
    if ((threadIdx.x & 31) == 0) red[threadIdx.x >> 5] = cnt;
    __syncthreads();
    if (threadIdx.x == 0) {
        int tot = 0;
#pragma unroll
        for (int i = 0; i < 8; i++) tot += red[i];
        if (tot < 1) tot = 1;
        g_denom[b * T + t] = (float)tot;
    }
}

// ---------------------------------------------------------------------------
// SGEMM: C[m,n] = epilogue( sum_k A[m,k]*W[n,k] + bias[n] )
//   MODE 0: silu
//   MODE 1: + resid[m,n]
// 64x64 block tile, BK=16, 256 threads, 4x4 per-thread microtile
// ---------------------------------------------------------------------------
template <int MODE>
__global__ __launch_bounds__(256) void gemm_kernel(
    const float* __restrict__ A, const float* __restrict__ W,
    const float* __restrict__ bias, const float* __restrict__ resid,
    float* __restrict__ C, int M, int N, int K) {
    __shared__ float As[16 * 68];
    __shared__ float Bs[16 * 68];
    const int tid = threadIdx.x;
    const int ty = tid >> 4, tx = tid & 15;
    const int m0 = blockIdx.y * 64, n0 = blockIdx.x * 64;
    const int lrow = tid >> 2;
    const int lk = (tid & 3) * 4;
    const float* Ap = A + (size_t)(m0 + lrow) * K + lk;
    const float* Wp = W + (size_t)(n0 + lrow) * K + lk;

    float acc[4][4];
#pragma unroll
    for (int i = 0; i < 4; i++)
#pragma unroll
        for (int j = 0; j < 4; j++) acc[i][j] = 0.0f;

    for (int k0 = 0; k0 < K; k0 += 16) {
        float4 av = *(const float4*)(Ap + k0);
        float4 wv = *(const float4*)(Wp + k0);
        __syncthreads();
        As[(lk + 0) * 68 + lrow] = av.x;
        As[(lk + 1) * 68 + lrow] = av.y;
        As[(lk + 2) * 68 + lrow] = av.z;
        As[(lk + 3) * 68 + lrow] = av.w;
        Bs[(lk + 0) * 68 + lrow] = wv.x;
        Bs[(lk + 1) * 68 + lrow] = wv.y;
        Bs[(lk + 2) * 68 + lrow] = wv.z;
        Bs[(lk + 3) * 68 + lrow] = wv.w;
        __syncthreads();
#pragma unroll
        for (int k = 0; k < 16; k++) {
            float4 a4 = *(const float4*)&As[k * 68 + ty * 4];
            float4 b4 = *(const float4*)&Bs[k * 68 + tx * 4];
            float ar[4] = {a4.x, a4.y, a4.z, a4.w};
            float br[4] = {b4.x, b4.y, b4.z, b4.w};
#pragma unroll
            for (int i = 0; i < 4; i++)
#pragma unroll
                for (int j = 0; j < 4; j++) acc[i][j] += ar[i] * br[j];
        }
    }

    float4 bv = *(const float4*)(bias + n0 + tx * 4);
#pragma unroll
    for (int i = 0; i < 4; i++) {
        const int m = m0 + ty * 4 + i;
        float4 r;
        r.x = acc[i][0] + bv.x;
        r.y = acc[i][1] + bv.y;
        r.z = acc[i][2] + bv.z;
        r.w = acc[i][3] + bv.w;
        if (MODE == 0) {
            r.x = r.x / (1.0f + expf(-r.x));
            r.y = r.y / (1.0f + expf(-r.y));
            r.z = r.z / (1.0f + expf(-r.z));
            r.w = r.w / (1.0f + expf(-r.w));
        } else {
            float4 rv = *(const float4*)(resid + (size_t)m * N + n0 + tx * 4);
            r.x += rv.x;
            r.y += rv.y;
            r.z += rv.z;
            r.w += rv.w;
        }
        *(float4*)(C + (size_t)m * N + n0 + tx * 4) = r;
    }
}

// ---------------------------------------------------------------------------
// Attention: per block (q-tile of 64, head, batch). Causal tile loop.
//   S = Q K^T ; P = silu(alpha*S + rab)/denom (masked -> 0) ; O += P V
// ---------------------------------------------------------------------------
__global__ __launch_bounds__(256) void attn_kernel(
    const float* __restrict__ amask, const float* __restrict__ rab_emb,
    int T, int H, int D, float alpha) {
    extern __shared__ float sm[];
    float* Qs = sm;                   // [64][68] d-major
    float* Ks = Qs + 64 * 68;         // [64][68] d-major
    float* Ps = Ks + 64 * 68;         // [64][68] s-major (q contiguous)
    float* Vs = Ps + 64 * 68;         // [64][64] s-major (d contiguous)
    float* rab_s = Vs + 64 * 64;      // [32]
    float* den_s = rab_s + 32;        // [64]
    float* val_s = den_s + 64;        // [64]
    int* bkt_s = (int*)(val_s + 64);  // [T]

    const int tid = threadIdx.x;
    const int ty = tid >> 4, tx = tid & 15;
    const int qt = blockIdx.x;
    const int head = blockIdx.y;
    const int b = blockIdx.z;
    const int q0 = qt * 64;
    const int D4 = 4 * D;

    // load Q tile (transposed to d-major)
#pragma unroll
    for (int r = 0; r < 4; r++) {
        int idx = r * 256 + tid;
        int q = idx >> 4, dg = (idx & 15) * 4;
        float4 v = *(const float4*)(g_H4 + (size_t)(b * T + q0 + q) * D4 + 2 * D + head * 64 + dg);
        Qs[(dg + 0) * 68 + q] = v.x;
        Qs[(dg + 1) * 68 + q] = v.y;
        Qs[(dg + 2) * 68 + q] = v.z;
        Qs[(dg + 3) * 68 + q] = v.w;
    }
    if (tid < 32) rab_s[tid] = rab_emb[tid * H + head];
    if (tid < 64) den_s[tid] = g_denom[b * T + q0 + tid];
    for (int i = tid; i < T; i += 256) bkt_s[i] = g_bucket[i];

    float oacc[4][4];
#pragma unroll
    for (int i = 0; i < 4; i++)
#pragma unroll
        for (int j = 0; j < 4; j++) oacc[i][j] = 0.0f;

    for (int st = 0; st <= qt; st++) {
        const int s0 = st * 64;
        __syncthreads();
        // load K (transposed) and V (direct) tiles
#pragma unroll
        for (int r = 0; r < 4; r++) {
            int idx = r * 256 + tid;
            int s = idx >> 4, dg = (idx & 15) * 4;
            const float* base = g_H4 + (size_t)(b * T + s0 + s) * D4 + head * 64 + dg;
            float4 kv = *(const float4*)(base + 3 * D);
            Ks[(dg + 0) * 68 + s] = kv.x;
            Ks[(dg + 1) * 68 + s] = kv.y;
            Ks[(dg + 2) * 68 + s] = kv.z;
            Ks[(dg + 3) * 68 + s] = kv.w;
            float4 vv = *(const float4*)(base + D);
            *(float4*)&Vs[s * 64 + dg] = vv;
        }
        if (tid < 64) val_s[tid] = (float)g_valid[b * T + s0 + tid];
        __syncthreads();

        // S = Q K^T  (contract over d = 0..63)
        float sacc[4][4];
#pragma unroll
        for (int i = 0; i < 4; i++)
#pragma unroll
            for (int j = 0; j < 4; j++) sacc[i][j] = 0.0f;
#pragma unroll 8
        for (int d = 0; d < 64; d++) {
            float4 a4 = *(const float4*)&Qs[d * 68 + ty * 4];
            float4 b4 = *(const float4*)&Ks[d * 68 + tx * 4];
            float ar[4] = {a4.x, a4.y, a4.z, a4.w};
            float br[4] = {b4.x, b4.y, b4.z, b4.w};
#pragma unroll
            for (int i = 0; i < 4; i++)
#pragma unroll
                for (int j = 0; j < 4; j++) sacc[i][j] += ar[i] * br[j];
        }

        // pointwise epilogue -> Ps (transposed: [s][q])
        const bool diag = (st == qt);
#pragma unroll
        for (int j = 0; j < 4; j++) {
            const int s = s0 + tx * 4 + j;
            const float vfl = val_s[tx * 4 + j];
#pragma unroll
            for (int i = 0; i < 4; i++) {
                const int t = q0 + ty * 4 + i;
                float p = 0.0f;
                bool ok = (vfl != 0.0f);
                if (diag && ok) ok = (amask[(size_t)t * T + s] == 0.0f);
                if (ok) {
                    float xv = sacc[i][j] * alpha + rab_s[bkt_s[t - s]];
                    p = xv / (1.0f + expf(-xv)) / den_s[ty * 4 + i];
                }
                Ps[(tx * 4 + j) * 68 + ty * 4 + i] = p;
            }
        }
        __syncthreads();

        // O += P V  (contract over s = 0..63)
#pragma unroll 8
        for (int s = 0; s < 64; s++) {
            float4 p4 = *(const float4*)&Ps[s * 68 + ty * 4];
            float4 v4 = *(const float4*)&Vs[s * 64 + tx * 4];
            float pr[4] = {p4.x, p4.y, p4.z, p4.w};
            float vr[4] = {v4.x, v4.y, v4.z, v4.w};
#pragma unroll
            for (int i = 0; i < 4; i++)
#pragma unroll
                for (int j = 0; j < 4; j++) oacc[i][j] += pr[i] * vr[j];
        }
    }

#pragma unroll
    for (int i = 0; i < 4; i++) {
        float4 r = {oacc[i][0], oacc[i][1], oacc[i][2], oacc[i][3]};
        *(float4*)(g_AV + (size_t)(b * T + q0 + ty * 4 + i) * D + head * 64 + tx * 4) = r;
    }
}

// ---------------------------------------------------------------------------
// LayerNorm over D, then multiply by U (first quarter of g_H4 row)
// blockDim = D/4
// ---------------------------------------------------------------------------
__global__ void ln_kernel(const float* __restrict__ gamma, const float* __restrict__ beta, int D) {
    const int row = blockIdx.x;
    const int tid = threadIdx.x;
    const int D4 = 4 * D;
    float4 v = *(const float4*)(g_AV + (size_t)row * D + tid * 4);
    __shared__ float red[8];
    float s = v.x + v.y + v.z + v.w;
#pragma unroll
    for (int o = 16; o; o >>= 1) s += __shfl_xor_sync(0xffffffffu, s, o);
    if ((tid & 31) == 0) red[tid >> 5] = s;
    __syncthreads();
    if (tid == 0) {
        float t = 0;
#pragma unroll
        for (int i = 0; i < 8; i++) t += red[i];
        red[0] = t;
    }
    __syncthreads();
    const float mean = red[0] / (float)D;
    __syncthreads();
    float dx = v.x - mean, dy = v.y - mean, dz = v.z - mean, dw = v.w - mean;
    float s2 = dx * dx + dy * dy + dz * dz + dw * dw;
#pragma unroll
    for (int o = 16; o; o >>= 1) s2 += __shfl_xor_sync(0xffffffffu, s2, o);
    if ((tid & 31) == 0) red[tid >> 5] = s2;
    __syncthreads();
    if (tid == 0) {
        float t = 0;
#pragma unroll
        for (int i = 0; i < 8; i++) t += red[i];
        red[0] = t;
    }
    __syncthreads();
    const float var = red[0] / (float)D;
    const float rstd = rsqrtf(var + 1e-5f);
    float4 g = *(const float4*)(gamma + tid * 4);
    float4 bb = *(const float4*)(beta + tid * 4);
    float4 u = *(const float4*)(g_H4 + (size_t)row * D4 + tid * 4);
    float4 z;
    z.x = ((v.x - mean) * rstd * g.x + bb.x) * u.x;
    z.y = ((v.y - mean) * rstd * g.y + bb.y) * u.y;
    z.z = ((v.z - mean) * rstd * g.z + bb.z) * u.z;
    z.w = ((v.w - mean) * rstd * g.w + bb.w) * u.w;
    *(float4*)(g_Z + (size_t)row * D + tid * 4) = z;
}

// ---------------------------------------------------------------------------
extern "C" void kernel_launch(void* const* d_in, const int* in_sizes, int n_in,
                              void* d_out, int out_size) {
    (void)n_in;
    (void)out_size;
    const float* x = (const float*)d_in[0];
    const float* amask = (const float*)d_in[1];
    const void* kpm = d_in[2];
    const float* W_in = (const float*)d_in[3];
    const float* b_in = (const float*)d_in[4];
    const float* W_out = (const float*)d_in[5];
    const float* b_out = (const float*)d_in[6];
    const float* gamma = (const float*)d_in[7];
    const float* beta = (const float*)d_in[8];
    const float* rab = (const float*)d_in[9];
    float* out = (float*)d_out;

    const int D = in_sizes[7];  // gamma length
    int T = 1;
    while ((long long)T * T < (long long)in_sizes[1]) T++;  // amask is [T,T]
    const int B = in_sizes[0] / (T * D);
    const int H = in_sizes[9] / NBUCKETS;  // rab_emb [32, H]
    const int BT = B * T;
    const float alpha = rsqrtf((float)(D / H));

    float *pH4, *pZ;
    cudaGetSymbolAddress((void**)&pH4, g_H4);
    cudaGetSymbolAddress((void**)&pZ, g_Z);

    const int attn_smem = (3 * 64 * 68 + 64 * 64 + 32 + 64 + 64 + T) * (int)sizeof(float);
    cudaFuncSetAttribute(attn_kernel, cudaFuncAttributeMaxDynamicSharedMemorySize, attn_smem);

    prep_kernel<<<1, 256>>>(kpm, B, T);
    denom_kernel<<<dim3(T, B), 256>>>(amask, B, T);
    gemm_kernel<0><<<dim3(4 * D / 64, BT / 64), 256>>>(x, W_in, b_in, nullptr, pH4, BT, 4 * D, D);
    attn_kernel<<<dim3(T / 64, H, B), 256, attn_smem>>>(amask, rab, T, H, D, alpha);
    ln_kernel<<<BT, D / 4>>>(gamma, beta, D);
    gemm_kernel<1><<<dim3(D / 64, BT / 64), 256>>>(pZ, W_out, b_out, x, out, BT, D, D);
}

// round 7
// speedup vs baseline: 1.6254x; 1.6254x over previous
#include <cuda_runtime.h>
#include <cuda_bf16.h>
#include <cstdint>
#include <math.h>

// ---------------------------------------------------------------------------
// HSTU layer. Dense GEMMs via warp-level mma.sync bf16 (hi/lo split -> ~fp32
// accuracy). Attention/LN/denom SIMT fp32. No sm_103a-only instructions.
// ---------------------------------------------------------------------------

#define MAXB 2
#define MAXT 1024
#define MAXD 1024
#define NBUCKETS 32

__device__ float g_H4[(size_t)MAXB * MAXT * 4 * MAXD];
__device__ float g_AV[(size_t)MAXB * MAXT * MAXD];
__device__ float g_Z[(size_t)MAXB * MAXT * MAXD];
__device__ float g_denom[MAXB * MAXT];
__device__ unsigned char g_valid[MAXB * MAXT];
__device__ int g_bucket[MAXT];

__device__ __nv_bfloat16 g_xh[(size_t)MAXB * MAXT * MAXD];
__device__ __nv_bfloat16 g_xl[(size_t)MAXB * MAXT * MAXD];
__device__ __nv_bfloat16 g_wih[(size_t)4 * MAXD * MAXD];
__device__ __nv_bfloat16 g_wil[(size_t)4 * MAXD * MAXD];
__device__ __nv_bfloat16 g_woh[(size_t)MAXD * MAXD];
__device__ __nv_bfloat16 g_wol[(size_t)MAXD * MAXD];
__device__ __nv_bfloat16 g_zh[(size_t)MAXB * MAXT * MAXD];
__device__ __nv_bfloat16 g_zl[(size_t)MAXB * MAXT * MAXD];

// ======================= helpers ===========================================

__device__ __forceinline__ uint32_t smem_to_u32(const void* smem_ptr) {
    uint32_t addr;
    asm("{ .reg .u64 tmp; cvta.to.shared.u64 tmp, %1; cvt.u32.u64 %0, tmp; }"
        : "=r"(addr) : "l"(smem_ptr));
    return addr;
}

#define CP_ASYNC16(dst, src) \
    asm volatile("cp.async.cg.shared.global [%0], [%1], 16;" :: "r"(dst), "l"(src) : "memory")
#define CP_ASYNC_COMMIT() asm volatile("cp.async.commit_group;" ::: "memory")
#define CP_ASYNC_WAIT0() asm volatile("cp.async.wait_group 0;" ::: "memory")
#define CP_ASYNC_WAIT1() asm volatile("cp.async.wait_group 1;" ::: "memory")

// m16n8k16 row.col bf16 -> f32 accumulate (in place)
__device__ __forceinline__ void mma_bf16(float* c, const uint32_t* a, const uint32_t* b) {
    asm volatile(
        "mma.sync.aligned.m16n8k16.row.col.f32.bf16.bf16.f32 "
        "{%0,%1,%2,%3}, {%4,%5,%6,%7}, {%8,%9}, {%0,%1,%2,%3};"
        : "+f"(c[0]), "+f"(c[1]), "+f"(c[2]), "+f"(c[3])
        : "r"(a[0]), "r"(a[1]), "r"(a[2]), "r"(a[3]), "r"(b[0]), "r"(b[1]));
}

// ======================= split fp32 -> bf16 hi/lo ===========================
__global__ void split_kernel(const float* __restrict__ src, __nv_bfloat16* __restrict__ hi,
                             __nv_bfloat16* __restrict__ lo, int n) {
    int i = blockIdx.x * blockDim.x + threadIdx.x;
    if (i >= n / 4) return;
    float4 v = ((const float4*)src)[i];
    float a0 = v.x;
    float a1 = v.y;
    float a2 = v.z;
    float a3 = v.w;
    __nv_bfloat16 h0 = __float2bfloat16(a0);
    __nv_bfloat16 h1 = __float2bfloat16(a1);
    __nv_bfloat16 h2 = __float2bfloat16(a2);
    __nv_bfloat16 h3 = __float2bfloat16(a3);
    hi[4 * i + 0] = h0;
    hi[4 * i + 1] = h1;
    hi[4 * i + 2] = h2;
    hi[4 * i + 3] = h3;
    lo[4 * i + 0] = __float2bfloat16(a0 - __bfloat162float(h0));
    lo[4 * i + 1] = __float2bfloat16(a1 - __bfloat162float(h1));
    lo[4 * i + 2] = __float2bfloat16(a2 - __bfloat162float(h2));
    lo[4 * i + 3] = __float2bfloat16(a3 - __bfloat162float(h3));
}

// ======================= prep ==============================================
__global__ void prep_kernel(const void* __restrict__ kpm, int B, int T) {
    const int M = B * T;
    __shared__ int oddbyte;
    if (threadIdx.x == 0) oddbyte = 0;
    __syncthreads();
    const unsigned char* bp = (const unsigned char*)kpm;
    int local = 0;
    for (int i = threadIdx.x; i < M; i += blockDim.x)
        if (bp[i] != 0 && (i & 3) != 0) local = 1;
    if (local) atomicOr(&oddbyte, 1);
    __syncthreads();
    const int isByte = oddbyte;
    const int* ip = (const int*)kpm;
    for (int i = threadIdx.x; i < M; i += blockDim.x) {
        int pad = isByte ? (bp[i] != 0) : (ip[i] != 0);
        g_valid[i] = pad ? 0 : 1;
    }
    for (int n = threadIdx.x; n < T; n += blockDim.x) {
        int bkt;
        if (n < 16) {
            bkt = n;
        } else {
            float v = logf((float)n / 16.0f + 1e-6f) / 2.0794415416798357f * 16.0f;
            int lg = 16 + (int)v;
            bkt = lg < (NBUCKETS - 1) ? lg : (NBUCKETS - 1);
        }
        g_bucket[n] = bkt;
    }
}

// ======================= denom =============================================
__global__ void denom_kernel(const float* __restrict__ amask, int B, int T) {
    const int t = blockIdx.x;
    const int b = blockIdx.y;
    int cnt = 0;
    for (int s = threadIdx.x; s < T; s += blockDim.x)
        cnt += (amask[(size_t)t * T + s] == 0.0f && g_valid[b * T + s]) ? 1 : 0;
#pragma unroll
    for (int o = 16; o; o >>= 1) cnt += __shfl_xor_sync(0xffffffffu, cnt, o);
    __shared__ int red[8];
    if ((threadIdx.x & 31) == 0) red[threadIdx.x >> 5] = cnt;
    __syncthreads();
    if (threadIdx.x == 0) {
        int tot = 0;
#pragma unroll
        for (int i = 0; i < 8; i++) tot += red[i];
        if (tot < 1) tot = 1;
        g_denom[b * T + t] = (float)tot;
    }
}

// ======================= HMMA GEMM =========================================
// C[m,n] = epi( sum_k A[m,k]*B[n,k] + bias[n] ), A/B bf16 hi/lo split.
// CTA 128x128, 8 warps (4 M x 2 N), warp tile 32x64, K-chunk 32, double buffer.
// mode 0: silu ; mode 1: + resid
#define GS 40                          // smem row stride in bf16 elements
#define TILE_B (128 * GS * 2)          // one operand tile bytes = 10240
#define OFF_AH 0
#define OFF_AL (TILE_B)
#define OFF_BH (2 * TILE_B)
#define OFF_BL (3 * TILE_B)
#define STAGE_B (4 * TILE_B)           // 40960
#define GEMM_SMEM (2 * STAGE_B)        // 81920

__global__ __launch_bounds__(256) void hgemm_kernel(
    const __nv_bfloat16* __restrict__ Ah, const __nv_bfloat16* __restrict__ Al,
    const __nv_bfloat16* __restrict__ Bh, const __nv_bfloat16* __restrict__ Bl,
    const float* __restrict__ bias, const float* __restrict__ resid, float* __restrict__ C,
    int M, int N, int K, int mode) {
    extern __shared__ char dynsmem[];
    const uint32_t sbase = smem_to_u32(dynsmem);
    const int tid = threadIdx.x;
    const int wid = tid >> 5;
    const int lane = tid & 31;
    const int wm = wid & 3;       // 0..3, M direction (32 rows each)
    const int wn = wid >> 2;      // 0..1, N direction (64 cols each)
    const int m0 = blockIdx.y * 128;
    const int n0 = blockIdx.x * 128;

    // cp.async slots: per tile 128 rows x 4 x16B units = 512; 2 per thread
    uint32_t adst[2];
    const __nv_bfloat16* aH[2];
    const __nv_bfloat16* aL[2];
    const __nv_bfloat16* bH[2];
    const __nv_bfloat16* bL[2];
#pragma unroll
    for (int i = 0; i < 2; i++) {
        int u = tid + 256 * i;
        int row = u >> 2;
        int un = u & 3;
        adst[i] = (uint32_t)(row * (GS * 2) + un * 16);
        aH[i] = Ah + (size_t)(m0 + row) * K + un * 8;
        aL[i] = Al + (size_t)(m0 + row) * K + un * 8;
        bH[i] = Bh + (size_t)(n0 + row) * K + un * 8;
        bL[i] = Bl + (size_t)(n0 + row) * K + un * 8;
    }

#define ISSUE_LOADS(ch, st)                                      \
    do {                                                         \
        uint32_t _sb = sbase + (uint32_t)((st) * STAGE_B);       \
        int _k0 = (ch) * 32;                                     \
        _Pragma("unroll") for (int _i = 0; _i < 2; _i++) {       \
            CP_ASYNC16(_sb + OFF_AH + adst[_i], aH[_i] + _k0);   \
            CP_ASYNC16(_sb + OFF_AL + adst[_i], aL[_i] + _k0);   \
            CP_ASYNC16(_sb + OFF_BH + bdstv(_i), bH[_i] + _k0);  \
            CP_ASYNC16(_sb + OFF_BL + bdstv(_i), bL[_i] + _k0);  \
        }                                                        \
        CP_ASYNC_COMMIT();                                       \
    } while (0)
#define bdstv(i) adst[i]

    float acc[2][8][4];
#pragma unroll
    for (int mi = 0; mi < 2; mi++)
#pragma unroll
        for (int ni = 0; ni < 8; ni++)
#pragma unroll
            for (int j = 0; j < 4; j++) acc[mi][ni][j] = 0.0f;

    const int r = lane >> 2;         // 0..7
    const int kc = (lane & 3) * 2;   // 0,2,4,6

    const int NCH = K >> 5;
    ISSUE_LOADS(0, 0);
    for (int ch = 0; ch < NCH; ch++) {
        if (ch + 1 < NCH) {
            ISSUE_LOADS(ch + 1, (ch + 1) & 1);
            CP_ASYNC_WAIT1();
        } else {
            CP_ASYNC_WAIT0();
        }
        __syncthreads();

        const char* stb = dynsmem + (ch & 1) * STAGE_B;
        const __nv_bfloat16* sAh = (const __nv_bfloat16*)(stb + OFF_AH);
        const __nv_bfloat16* sAl = (const __nv_bfloat16*)(stb + OFF_AL);
        const __nv_bfloat16* sBh = (const __nv_bfloat16*)(stb + OFF_BH);
        const __nv_bfloat16* sBl = (const __nv_bfloat16*)(stb + OFF_BL);

#pragma unroll
        for (int ks = 0; ks < 2; ks++) {
            const int kb = ks * 16;
            uint32_t afh[2][4], afl[2][4];
#pragma unroll
            for (int mi = 0; mi < 2; mi++) {
                const int base = (wm * 32 + mi * 16 + r) * GS + kb + kc;
                afh[mi][0] = *(const uint32_t*)&sAh[base];
                afh[mi][1] = *(const uint32_t*)&sAh[base + 8 * GS];
                afh[mi][2] = *(const uint32_t*)&sAh[base + 8];
                afh[mi][3] = *(const uint32_t*)&sAh[base + 8 * GS + 8];
                afl[mi][0] = *(const uint32_t*)&sAl[base];
                afl[mi][1] = *(const uint32_t*)&sAl[base + 8 * GS];
                afl[mi][2] = *(const uint32_t*)&sAl[base + 8];
                afl[mi][3] = *(const uint32_t*)&sAl[base + 8 * GS + 8];
            }
            uint32_t bfh[8][2], bfl[8][2];
#pragma unroll
            for (int ni = 0; ni < 8; ni++) {
                const int bb = (wn * 64 + ni * 8 + r) * GS + kb + kc;
                bfh[ni][0] = *(const uint32_t*)&sBh[bb];
                bfh[ni][1] = *(const uint32_t*)&sBh[bb + 8];
                bfl[ni][0] = *(const uint32_t*)&sBl[bb];
                bfl[ni][1] = *(const uint32_t*)&sBl[bb + 8];
            }
#pragma unroll
            for (int mi = 0; mi < 2; mi++)
#pragma unroll
                for (int ni = 0; ni < 8; ni++) {
                    mma_bf16(acc[mi][ni], afh[mi], bfh[ni]);
                    mma_bf16(acc[mi][ni], afh[mi], bfl[ni]);
                    mma_bf16(acc[mi][ni], afl[mi], bfh[ni]);
                }
        }
        __syncthreads();
    }

    // epilogue
#pragma unroll
    for (int mi = 0; mi < 2; mi++) {
        const int r0 = m0 + wm * 32 + mi * 16 + r;
        const int r1 = r0 + 8;
#pragma unroll
        for (int ni = 0; ni < 8; ni++) {
            const int c0 = n0 + wn * 64 + ni * 8 + kc;
            float2 bv = *(const float2*)(bias + c0);
            float o0 = acc[mi][ni][0] + bv.x;
            float o1 = acc[mi][ni][1] + bv.y;
            float o2 = acc[mi][ni][2] + bv.x;
            float o3 = acc[mi][ni][3] + bv.y;
            if (mode == 0) {
                o0 = o0 / (1.0f + expf(-o0));
                o1 = o1 / (1.0f + expf(-o1));
                o2 = o2 / (1.0f + expf(-o2));
                o3 = o3 / (1.0f + expf(-o3));
            } else {
                float2 rv0 = *(const float2*)(resid + (size_t)r0 * N + c0);
                float2 rv1 = *(const float2*)(resid + (size_t)r1 * N + c0);
                o0 += rv0.x;
                o1 += rv0.y;
                o2 += rv1.x;
                o3 += rv1.y;
            }
            float2 w0;
            w0.x = o0;
            w0.y = o1;
            float2 w1;
            w1.x = o2;
            w1.y = o3;
            *(float2*)(C + (size_t)r0 * N + c0) = w0;
            *(float2*)(C + (size_t)r1 * N + c0) = w1;
        }
    }
}

// ======================= attention (SIMT fp32) =============================
__global__ __launch_bounds__(256) void attn_kernel(
    const float* __restrict__ amask, const float* __restrict__ rab_emb,
    int T, int H, int D, float alpha) {
    extern __shared__ float dynsmemf[];
    float* Qs = dynsmemf;
    float* Ks = Qs + 64 * 68;
    float* Ps = Ks + 64 * 68;
    float* Vs = Ps + 64 * 68;
    float* rab_s = Vs + 64 * 64;
    float* den_s = rab_s + 32;
    float* val_s = den_s + 64;
    int* bkt_s = (int*)(val_s + 64);

    const int tid = threadIdx.x;
    const int ty = tid >> 4, tx = tid & 15;
    const int qt = blockIdx.x;
    const int head = blockIdx.y;
    const int b = blockIdx.z;
    const int q0 = qt * 64;
    const int D4 = 4 * D;

#pragma unroll
    for (int r = 0; r < 4; r++) {
        int idx = r * 256 + tid;
        int q = idx >> 4, dg = (idx & 15) * 4;
        float4 v = *(const float4*)(g_H4 + (size_t)(b * T + q0 + q) * D4 + 2 * D + head * 64 + dg);
        Qs[(dg + 0) * 68 + q] = v.x;
        Qs[(dg + 1) * 68 + q] = v.y;
        Qs[(dg + 2) * 68 + q] = v.z;
        Qs[(dg + 3) * 68 + q] = v.w;
    }
    if (tid < 32) rab_s[tid] = rab_emb[tid * H + head];
    if (tid < 64) den_s[tid] = g_denom[b * T + q0 + tid];
    for (int i = tid; i < T; i += 256) bkt_s[i] = g_bucket[i];

    float oacc[4][4];
#pragma unroll
    for (int i = 0; i < 4; i++)
#pragma unroll
        for (int j = 0; j < 4; j++) oacc[i][j] = 0.0f;

    for (int st = 0; st <= qt; st++) {
        const int s0 = st * 64;
        __syncthreads();
#pragma unroll
        for (int r = 0; r < 4; r++) {
            int idx = r * 256 + tid;
            int s = idx >> 4, dg = (idx & 15) * 4;
            const float* base = g_H4 + (size_t)(b * T + s0 + s) * D4 + head * 64 + dg;
            float4 kv = *(const float4*)(base + 3 * D);
            Ks[(dg + 0) * 68 + s] = kv.x;
            Ks[(dg + 1) * 68 + s] = kv.y;
            Ks[(dg + 2) * 68 + s] = kv.z;
            Ks[(dg + 3) * 68 + s] = kv.w;
            float4 vv = *(const float4*)(base + D);
            *(float4*)&Vs[s * 64 + dg] = vv;
        }
        if (tid < 64) val_s[tid] = (float)g_valid[b * T + s0 + tid];
        __syncthreads();

        float sacc[4][4];
#pragma unroll
        for (int i = 0; i < 4; i++)
#pragma unroll
            for (int j = 0; j < 4; j++) sacc[i][j] = 0.0f;
#pragma unroll 8
        for (int d = 0; d < 64; d++) {
            float4 a4 = *(const float4*)&Qs[d * 68 + ty * 4];
            float4 b4 = *(const float4*)&Ks[d * 68 + tx * 4];
            float ar[4] = {a4.x, a4.y, a4.z, a4.w};
            float br[4] = {b4.x, b4.y, b4.z, b4.w};
#pragma unroll
            for (int i = 0; i < 4; i++)
#pragma unroll
                for (int j = 0; j < 4; j++) sacc[i][j] += ar[i] * br[j];
        }

        const bool diag = (st == qt);
#pragma unroll
        for (int j = 0; j < 4; j++) {
            const int s = s0 + tx * 4 + j;
            const float vfl = val_s[tx * 4 + j];
#pragma unroll
            for (int i = 0; i < 4; i++) {
                const int t = q0 + ty * 4 + i;
                float p = 0.0f;
                bool ok = (vfl != 0.0f);
                if (diag && ok) ok = (amask[(size_t)t * T + s] == 0.0f);
                if (ok) {
                    float xv = sacc[i][j] * alpha + rab_s[bkt_s[t - s]];
                    p = xv / (1.0f + expf(-xv)) / den_s[ty * 4 + i];
                }
                Ps[(tx * 4 + j) * 68 + ty * 4 + i] = p;
            }
        }
        __syncthreads();

#pragma unroll 8
        for (int s = 0; s < 64; s++) {
            float4 p4 = *(const float4*)&Ps[s * 68 + ty * 4];
            float4 v4 = *(const float4*)&Vs[s * 64 + tx * 4];
            float pr[4] = {p4.x, p4.y, p4.z, p4.w};
            float vr[4] = {v4.x, v4.y, v4.z, v4.w};
#pragma unroll
            for (int i = 0; i < 4; i++)
#pragma unroll
                for (int j = 0; j < 4; j++) oacc[i][j] += pr[i] * vr[j];
        }
    }

#pragma unroll
    for (int i = 0; i < 4; i++) {
        float4 r = {oacc[i][0], oacc[i][1], oacc[i][2], oacc[i][3]};
        *(float4*)(g_AV + (size_t)(b * T + q0 + ty * 4 + i) * D + head * 64 + tx * 4) = r;
    }
}

// ======================= LayerNorm * U =====================================
__global__ void ln_kernel(const float* __restrict__ gamma, const float* __restrict__ beta, int D) {
    const int row = blockIdx.x;
    const int tid = threadIdx.x;
    const int D4 = 4 * D;
    float4 v = *(const float4*)(g_AV + (size_t)row * D + tid * 4);
    __shared__ float red[8];
    float s = v.x + v.y + v.z + v.w;
#pragma unroll
    for (int o = 16; o; o >>= 1) s += __shfl_xor_sync(0xffffffffu, s, o);
    if ((tid & 31) == 0) red[tid >> 5] = s;
    __syncthreads();
    if (tid == 0) {
        float t = 0;
#pragma unroll
        for (int i = 0; i < 8; i++) t += red[i];
        red[0] = t;
    }
    __syncthreads();
    const float mean = red[0] / (float)D;
    __syncthreads();
    float dx = v.x - mean, dy = v.y - mean, dz = v.z - mean, dw = v.w - mean;
    float s2 = dx * dx + dy * dy + dz * dz + dw * dw;
#pragma unroll
    for (int o = 16; o; o >>= 1) s2 += __shfl_xor_sync(0xffffffffu, s2, o);
    if ((tid & 31) == 0) red[tid >> 5] = s2;
    __syncthreads();
    if (tid == 0) {
        float t = 0;
#pragma unroll
        for (int i = 0; i < 8; i++) t += red[i];
        red[0] = t;
    }
    __syncthreads();
    const float var = red[0] / (float)D;
    const float rstd = rsqrtf(var + 1e-5f);
    float4 g = *(const float4*)(gamma + tid * 4);
    float4 bb = *(const float4*)(beta + tid * 4);
    float4 u = *(const float4*)(g_H4 + (size_t)row * D4 + tid * 4);
    float4 z;
    z.x = ((v.x - mean) * rstd * g.x + bb.x) * u.x;
    z.y = ((v.y - mean) * rstd * g.y + bb.y) * u.y;
    z.z = ((v.z - mean) * rstd * g.z + bb.z) * u.z;
    z.w = ((v.w - mean) * rstd * g.w + bb.w) * u.w;
    *(float4*)(g_Z + (size_t)row * D + tid * 4) = z;
}

// ---------------------------------------------------------------------------
extern "C" void kernel_launch(void* const* d_in, const int* in_sizes, int n_in,
                              void* d_out, int out_size) {
    (void)n_in;
    (void)out_size;
    const float* x = (const float*)d_in[0];
    const float* amask = (const float*)d_in[1];
    const void* kpm = d_in[2];
    const float* W_in = (const float*)d_in[3];
    const float* b_in = (const float*)d_in[4];
    const float* W_out = (const float*)d_in[5];
    const float* b_out = (const float*)d_in[6];
    const float* gamma = (const float*)d_in[7];
    const float* beta = (const float*)d_in[8];
    const float* rab = (const float*)d_in[9];
    float* out = (float*)d_out;

    const int D = in_sizes[7];
    int T = 1;
    while ((long long)T * T < (long long)in_sizes[1]) T++;
    const int B = in_sizes[0] / (T * D);
    const int H = in_sizes[9] / NBUCKETS;
    const int BT = B * T;
    const float alpha = rsqrtf((float)(D / H));

    float *pH4, *pZ;
    cudaGetSymbolAddress((void**)&pH4, g_H4);
    cudaGetSymbolAddress((void**)&pZ, g_Z);
    __nv_bfloat16 *pxh, *pxl, *pwih, *pwil, *pwoh, *pwol, *pzh, *pzl;
    cudaGetSymbolAddress((void**)&pxh, g_xh);
    cudaGetSymbolAddress((void**)&pxl, g_xl);
    cudaGetSymbolAddress((void**)&pwih, g_wih);
    cudaGetSymbolAddress((void**)&pwil, g_wil);
    cudaGetSymbolAddress((void**)&pwoh, g_woh);
    cudaGetSymbolAddress((void**)&pwol, g_wol);
    cudaGetSymbolAddress((void**)&pzh, g_zh);
    cudaGetSymbolAddress((void**)&pzl, g_zl);

    const int attn_smem = (3 * 64 * 68 + 64 * 64 + 32 + 64 + 64 + T) * (int)sizeof(float);
    cudaFuncSetAttribute(attn_kernel, cudaFuncAttributeMaxDynamicSharedMemorySize, attn_smem);
    cudaFuncSetAttribute(hgemm_kernel, cudaFuncAttributeMaxDynamicSharedMemorySize, GEMM_SMEM);

    split_kernel<<<(BT * D / 4 + 255) / 256, 256>>>(x, pxh, pxl, BT * D);
    split_kernel<<<(4 * D * D / 4 + 255) / 256, 256>>>(W_in, pwih, pwil, 4 * D * D);
    split_kernel<<<(D * D / 4 + 255) / 256, 256>>>(W_out, pwoh, pwol, D * D);

    prep_kernel<<<1, 256>>>(kpm, B, T);
    denom_kernel<<<dim3(T, B), 256>>>(amask, B, T);
    hgemm_kernel<<<dim3(4 * D / 128, BT / 128), 256, GEMM_SMEM>>>(
        pxh, pxl, pwih, pwil, b_in, nullptr, pH4, BT, 4 * D, D, 0);
    attn_kernel<<<dim3(T / 64, H, B), 256, attn_smem>>>(amask, rab, T, H, D, alpha);
    ln_kernel<<<BT, D / 4>>>(gamma, beta, D);
    split_kernel<<<(BT * D / 4 + 255) / 256, 256>>>(pZ, pzh, pzl, BT * D);
    hgemm_kernel<<<dim3(D / 128, BT / 128), 256, GEMM_SMEM>>>(
        pzh, pzl, pwoh, pwol, b_out, x, out, BT, D, D, 1);
}

// round 12
// speedup vs baseline: 1.8496x; 1.1379x over previous
#include <cuda_runtime.h>
#include <cuda_bf16.h>
#include <cstdint>
#include <math.h>

// ---------------------------------------------------------------------------
// HSTU layer. Dense GEMMs + attention on warp-level mma.sync bf16 (hi/lo
// split -> ~fp32 accuracy). LN/denom/prep SIMT. No sm_103a-only instructions.
// ---------------------------------------------------------------------------

#define MAXB 2
#define MAXT 1024
#define MAXD 1024
#define NBUCKETS 32

__device__ float g_H4[(size_t)MAXB * MAXT * 4 * MAXD];
__device__ float g_AV[(size_t)MAXB * MAXT * MAXD];
__device__ float g_Z[(size_t)MAXB * MAXT * MAXD];
__device__ float g_denom[MAXB * MAXT];
__device__ unsigned char g_valid[MAXB * MAXT];
__device__ int g_bucket[MAXT];

__device__ __nv_bfloat16 g_xh[(size_t)MAXB * MAXT * MAXD];
__device__ __nv_bfloat16 g_xl[(size_t)MAXB * MAXT * MAXD];
__device__ __nv_bfloat16 g_wih[(size_t)4 * MAXD * MAXD];
__device__ __nv_bfloat16 g_wil[(size_t)4 * MAXD * MAXD];
__device__ __nv_bfloat16 g_woh[(size_t)MAXD * MAXD];
__device__ __nv_bfloat16 g_wol[(size_t)MAXD * MAXD];
__device__ __nv_bfloat16 g_zh[(size_t)MAXB * MAXT * MAXD];
__device__ __nv_bfloat16 g_zl[(size_t)MAXB * MAXT * MAXD];

// ======================= helpers ===========================================

__device__ __forceinline__ uint32_t smem_to_u32(const void* smem_ptr) {
    uint32_t addr;
    asm("{ .reg .u64 tmp; cvta.to.shared.u64 tmp, %1; cvt.u32.u64 %0, tmp; }"
        : "=r"(addr) : "l"(smem_ptr));
    return addr;
}

#define CP_ASYNC16(dst, src) \
    asm volatile("cp.async.cg.shared.global [%0], [%1], 16;" :: "r"(dst), "l"(src) : "memory")
#define CP_ASYNC_COMMIT() asm volatile("cp.async.commit_group;" ::: "memory")
#define CP_ASYNC_WAIT0() asm volatile("cp.async.wait_group 0;" ::: "memory")
#define CP_ASYNC_WAIT1() asm volatile("cp.async.wait_group 1;" ::: "memory")

// m16n8k16 row.col bf16 -> f32 accumulate (in place)
__device__ __forceinline__ void mma_bf16(float* c, const uint32_t* a, const uint32_t* b) {
    asm volatile(
        "mma.sync.aligned.m16n8k16.row.col.f32.bf16.bf16.f32 "
        "{%0,%1,%2,%3}, {%4,%5,%6,%7}, {%8,%9}, {%0,%1,%2,%3};"
        : "+f"(c[0]), "+f"(c[1]), "+f"(c[2]), "+f"(c[3])
        : "r"(a[0]), "r"(a[1]), "r"(a[2]), "r"(a[3]), "r"(b[0]), "r"(b[1]));
}

// pack two floats as bf16x2 in a uint32 (x -> low half)
__device__ __forceinline__ uint32_t pk2(float x, float y) {
    unsigned short lo = __bfloat16_as_ushort(__float2bfloat16(x));
    unsigned short hi = __bfloat16_as_ushort(__float2bfloat16(y));
    return (uint32_t)lo | ((uint32_t)hi << 16);
}
__device__ __forceinline__ float rlo(float x) {
    return x - __bfloat162float(__float2bfloat16(x));
}

// ======================= split fp32 -> bf16 hi/lo ===========================
__global__ void split_kernel(const float* __restrict__ src, __nv_bfloat16* __restrict__ hi,
                             __nv_bfloat16* __restrict__ lo, int n) {
    int i = blockIdx.x * blockDim.x + threadIdx.x;
    if (i >= n / 4) return;
    float4 v = ((const float4*)src)[i];
    float a0 = v.x;
    float a1 = v.y;
    float a2 = v.z;
    float a3 = v.w;
    __nv_bfloat16 h0 = __float2bfloat16(a0);
    __nv_bfloat16 h1 = __float2bfloat16(a1);
    __nv_bfloat16 h2 = __float2bfloat16(a2);
    __nv_bfloat16 h3 = __float2bfloat16(a3);
    hi[4 * i + 0] = h0;
    hi[4 * i + 1] = h1;
    hi[4 * i + 2] = h2;
    hi[4 * i + 3] = h3;
    lo[4 * i + 0] = __float2bfloat16(a0 - __bfloat162float(h0));
    lo[4 * i + 1] = __float2bfloat16(a1 - __bfloat162float(h1));
    lo[4 * i + 2] = __float2bfloat16(a2 - __bfloat162float(h2));
    lo[4 * i + 3] = __float2bfloat16(a3 - __bfloat162float(h3));
}

// ======================= prep ==============================================
__global__ void prep_kernel(const void* __restrict__ kpm, int B, int T) {
    const int M = B * T;
    __shared__ int oddbyte;
    if (threadIdx.x == 0) oddbyte = 0;
    __syncthreads();
    const unsigned char* bp = (const unsigned char*)kpm;
    int local = 0;
    for (int i = threadIdx.x; i < M; i += blockDim.x)
        if (bp[i] != 0 && (i & 3) != 0) local = 1;
    if (local) atomicOr(&oddbyte, 1);
    __syncthreads();
    const int isByte = oddbyte;
    const int* ip = (const int*)kpm;
    for (int i = threadIdx.x; i < M; i += blockDim.x) {
        int pad = isByte ? (bp[i] != 0) : (ip[i] != 0);
        g_valid[i] = pad ? 0 : 1;
    }
    for (int n = threadIdx.x; n < T; n += blockDim.x) {
        int bkt;
        if (n < 16) {
            bkt = n;
        } else {
            float v = logf((float)n / 16.0f + 1e-6f) / 2.0794415416798357f * 16.0f;
            int lg = 16 + (int)v;
            bkt = lg < (NBUCKETS - 1) ? lg : (NBUCKETS - 1);
        }
        g_bucket[n] = bkt;
    }
}

// ======================= denom =============================================
__global__ void denom_kernel(const float* __restrict__ amask, int B, int T) {
    const int t = blockIdx.x;
    const int b = blockIdx.y;
    int cnt = 0;
    for (int s = threadIdx.x; s < T; s += blockDim.x)
        cnt += (amask[(size_t)t * T + s] == 0.0f && g_valid[b * T + s]) ? 1 : 0;
#pragma unroll
    for (int o = 16; o; o >>= 1) cnt += __shfl_xor_sync(0xffffffffu, cnt, o);
    __shared__ int red[8];
    if ((threadIdx.x & 31) == 0) red[threadIdx.x >> 5] = cnt;
    __syncthreads();
    if (threadIdx.x == 0) {
        int tot = 0;
#pragma unroll
        for (int i = 0; i < 8; i++) tot += red[i];
        if (tot < 1) tot = 1;
        g_denom[b * T + t] = (float)tot;
    }
}

// ======================= HMMA GEMM (unchanged from passing R7) =============
#define GS 40
#define TILE_B (128 * GS * 2)
#define OFF_AH 0
#define OFF_AL (TILE_B)
#define OFF_BH (2 * TILE_B)
#define OFF_BL (3 * TILE_B)
#define STAGE_B (4 * TILE_B)
#define GEMM_SMEM (2 * STAGE_B)

__global__ __launch_bounds__(256) void hgemm_kernel(
    const __nv_bfloat16* __restrict__ Ah, const __nv_bfloat16* __restrict__ Al,
    const __nv_bfloat16* __restrict__ Bh, const __nv_bfloat16* __restrict__ Bl,
    const float* __restrict__ bias, const float* __restrict__ resid, float* __restrict__ C,
    int M, int N, int K, int mode) {
    extern __shared__ char dynsmem[];
    const uint32_t sbase = smem_to_u32(dynsmem);
    const int tid = threadIdx.x;
    const int wid = tid >> 5;
    const int lane = tid & 31;
    const int wm = wid & 3;
    const int wn = wid >> 2;
    const int m0 = blockIdx.y * 128;
    const int n0 = blockIdx.x * 128;

    uint32_t adst[2];
    const __nv_bfloat16* aH[2];
    const __nv_bfloat16* aL[2];
    const __nv_bfloat16* bH[2];
    const __nv_bfloat16* bL[2];
#pragma unroll
    for (int i = 0; i < 2; i++) {
        int u = tid + 256 * i;
        int row = u >> 2;
        int un = u & 3;
        adst[i] = (uint32_t)(row * (GS * 2) + un * 16);
        aH[i] = Ah + (size_t)(m0 + row) * K + un * 8;
        aL[i] = Al + (size_t)(m0 + row) * K + un * 8;
        bH[i] = Bh + (size_t)(n0 + row) * K + un * 8;
        bL[i] = Bl + (size_t)(n0 + row) * K + un * 8;
    }

#define ISSUE_LOADS(ch, st)                                      \
    do {                                                         \
        uint32_t _sb = sbase + (uint32_t)((st) * STAGE_B);       \
        int _k0 = (ch) * 32;                                     \
        _Pragma("unroll") for (int _i = 0; _i < 2; _i++) {       \
            CP_ASYNC16(_sb + OFF_AH + adst[_i], aH[_i] + _k0);   \
            CP_ASYNC16(_sb + OFF_AL + adst[_i], aL[_i] + _k0);   \
            CP_ASYNC16(_sb + OFF_BH + adst[_i], bH[_i] + _k0);   \
            CP_ASYNC16(_sb + OFF_BL + adst[_i], bL[_i] + _k0);   \
        }                                                        \
        CP_ASYNC_COMMIT();                                       \
    } while (0)

    float acc[2][8][4];
#pragma unroll
    for (int mi = 0; mi < 2; mi++)
#pragma unroll
        for (int ni = 0; ni < 8; ni++)
#pragma unroll
            for (int j = 0; j < 4; j++) acc[mi][ni][j] = 0.0f;

    const int r = lane >> 2;
    const int kc = (lane & 3) * 2;

    const int NCH = K >> 5;
    ISSUE_LOADS(0, 0);
    for (int ch = 0; ch < NCH; ch++) {
        if (ch + 1 < NCH) {
            ISSUE_LOADS(ch + 1, (ch + 1) & 1);
            CP_ASYNC_WAIT1();
        } else {
            CP_ASYNC_WAIT0();
        }
        __syncthreads();

        const char* stb = dynsmem + (ch & 1) * STAGE_B;
        const __nv_bfloat16* sAh = (const __nv_bfloat16*)(stb + OFF_AH);
        const __nv_bfloat16* sAl = (const __nv_bfloat16*)(stb + OFF_AL);
        const __nv_bfloat16* sBh = (const __nv_bfloat16*)(stb + OFF_BH);
        const __nv_bfloat16* sBl = (const __nv_bfloat16*)(stb + OFF_BL);

#pragma unroll
        for (int ks = 0; ks < 2; ks++) {
            const int kb = ks * 16;
            uint32_t afh[2][4], afl[2][4];
#pragma unroll
            for (int mi = 0; mi < 2; mi++) {
                const int base = (wm * 32 + mi * 16 + r) * GS + kb + kc;
                afh[mi][0] = *(const uint32_t*)&sAh[base];
                afh[mi][1] = *(const uint32_t*)&sAh[base + 8 * GS];
                afh[mi][2] = *(const uint32_t*)&sAh[base + 8];
                afh[mi][3] = *(const uint32_t*)&sAh[base + 8 * GS + 8];
                afl[mi][0] = *(const uint32_t*)&sAl[base];
                afl[mi][1] = *(const uint32_t*)&sAl[base + 8 * GS];
                afl[mi][2] = *(const uint32_t*)&sAl[base + 8];
                afl[mi][3] = *(const uint32_t*)&sAl[base + 8 * GS + 8];
            }
            uint32_t bfh[8][2], bfl[8][2];
#pragma unroll
            for (int ni = 0; ni < 8; ni++) {
                const int bb = (wn * 64 + ni * 8 + r) * GS + kb + kc;
                bfh[ni][0] = *(const uint32_t*)&sBh[bb];
                bfh[ni][1] = *(const uint32_t*)&sBh[bb + 8];
                bfl[ni][0] = *(const uint32_t*)&sBl[bb];
                bfl[ni][1] = *(const uint32_t*)&sBl[bb + 8];
            }
#pragma unroll
            for (int mi = 0; mi < 2; mi++)
#pragma unroll
                for (int ni = 0; ni < 8; ni++) {
                    mma_bf16(acc[mi][ni], afh[mi], bfh[ni]);
                    mma_bf16(acc[mi][ni], afh[mi], bfl[ni]);
                    mma_bf16(acc[mi][ni], afl[mi], bfh[ni]);
                }
        }
        __syncthreads();
    }

#pragma unroll
    for (int mi = 0; mi < 2; mi++) {
        const int r0 = m0 + wm * 32 + mi * 16 + r;
        const int r1 = r0 + 8;
#pragma unroll
        for (int ni = 0; ni < 8; ni++) {
            const int c0 = n0 + wn * 64 + ni * 8 + kc;
            float2 bv = *(const float2*)(bias + c0);
            float o0 = acc[mi][ni][0] + bv.x;
            float o1 = acc[mi][ni][1] + bv.y;
            float o2 = acc[mi][ni][2] + bv.x;
            float o3 = acc[mi][ni][3] + bv.y;
            if (mode == 0) {
                o0 = o0 / (1.0f + expf(-o0));
                o1 = o1 / (1.0f + expf(-o1));
                o2 = o2 / (1.0f + expf(-o2));
                o3 = o3 / (1.0f + expf(-o3));
            } else {
                float2 rv0 = *(const float2*)(resid + (size_t)r0 * N + c0);
                float2 rv1 = *(const float2*)(resid + (size_t)r1 * N + c0);
                o0 += rv0.x;
                o1 += rv0.y;
                o2 += rv1.x;
                o3 += rv1.y;
            }
            float2 w0;
            w0.x = o0;
            w0.y = o1;
            float2 w1;
            w1.x = o2;
            w1.y = o3;
            *(float2*)(C + (size_t)r0 * N + c0) = w0;
            *(float2*)(C + (size_t)r1 * N + c0) = w1;
        }
    }
}

// ======================= HMMA attention ====================================
// Block = (64-q-tile, head, b), 8 warps: wm=wid&3 (16 q rows), wn=wid>>2
// (32-wide N split). S = Q K^T (hi/lo, 3 mma), pointwise epilogue -> P hi/lo
// in smem, O += P V with V transposed in smem (hi/lo, 3 mma).
// g_H4 row layout: [U | V | Q | K] at offsets 0, D, 2D, 3D.
#define AST 72                       // bf16 row stride (elements)
#define ATILE (64 * AST * 2)         // 9216 bytes per bf16 tile
#define A_QH 0
#define A_QL (ATILE)
#define A_KH (2 * ATILE)
#define A_KL (3 * ATILE)
#define A_VH (4 * ATILE)
#define A_VL (5 * ATILE)
#define A_PH (6 * ATILE)
#define A_PL (7 * ATILE)
#define A_LUT (8 * ATILE)            // floats beyond
#define ATTN_SMEM (8 * ATILE + (32 + 64 + 64 + 1024) * 4)

__global__ __launch_bounds__(256) void attn_kernel(
    const float* __restrict__ amask, const float* __restrict__ rab_emb,
    int T, int H, int D, float alpha) {
    extern __shared__ char dynsmemc[];
    __nv_bfloat16* Qh = (__nv_bfloat16*)(dynsmemc + A_QH);
    __nv_bfloat16* Ql = (__nv_bfloat16*)(dynsmemc + A_QL);
    __nv_bfloat16* Kh = (__nv_bfloat16*)(dynsmemc + A_KH);
    __nv_bfloat16* Kl = (__nv_bfloat16*)(dynsmemc + A_KL);
    __nv_bfloat16* Vh = (__nv_bfloat16*)(dynsmemc + A_VH);
    __nv_bfloat16* Vl = (__nv_bfloat16*)(dynsmemc + A_VL);
    __nv_bfloat16* Ph = (__nv_bfloat16*)(dynsmemc + A_PH);
    __nv_bfloat16* Pl = (__nv_bfloat16*)(dynsmemc + A_PL);
    float* rab_s = (float*)(dynsmemc + A_LUT);
    float* den_s = rab_s + 32;
    float* val_s = den_s + 64;
    int* bkt_s = (int*)(val_s + 64);

    const int tid = threadIdx.x;
    const int wid = tid >> 5;
    const int lane = tid & 31;
    const int wm = wid & 3;
    const int wn = wid >> 2;
    const int r = lane >> 2;
    const int kc = (lane & 3) * 2;
    const int qt = blockIdx.x;
    const int head = blockIdx.y;
    const int b = blockIdx.z;
    const int q0 = qt * 64;
    const int D4 = 4 * D;

    // load Q tile (g_H4 offset +2D) -> Qh/Ql [q][d]
#pragma unroll
    for (int rr = 0; rr < 4; rr++) {
        int idx = rr * 256 + tid;
        int q = idx >> 4;
        int dg = (idx & 15) * 4;
        float4 v = *(const float4*)(g_H4 + (size_t)(b * T + q0 + q) * D4 + 2 * D + head * 64 + dg);
        *(uint32_t*)&Qh[q * AST + dg] = pk2(v.x, v.y);
        *(uint32_t*)&Qh[q * AST + dg + 2] = pk2(v.z, v.w);
        *(uint32_t*)&Ql[q * AST + dg] = pk2(rlo(v.x), rlo(v.y));
        *(uint32_t*)&Ql[q * AST + dg + 2] = pk2(rlo(v.z), rlo(v.w));
    }
    if (tid < 32) rab_s[tid] = rab_emb[tid * H + head];
    if (tid < 64) den_s[tid] = g_denom[b * T + q0 + tid];
    for (int i = tid; i < T; i += 256) bkt_s[i] = g_bucket[i];

    float oacc[4][4];
#pragma unroll
    for (int i = 0; i < 4; i++)
#pragma unroll
        for (int j = 0; j < 4; j++) oacc[i][j] = 0.0f;

    for (int st = 0; st <= qt; st++) {
        const int s0 = st * 64;
        __syncthreads();
        // K (offset +3D) -> Kh/Kl [s][d]; V (offset +1D) -> transposed Vh/Vl [d][s]
#pragma unroll
        for (int rr = 0; rr < 4; rr++) {
            int idx = rr * 256 + tid;
            int s = idx >> 4;
            int dg = (idx & 15) * 4;
            const float* base = g_H4 + (size_t)(b * T + s0 + s) * D4 + head * 64 + dg;
            float4 kv = *(const float4*)(base + 3 * D);
            *(uint32_t*)&Kh[s * AST + dg] = pk2(kv.x, kv.y);
            *(uint32_t*)&Kh[s * AST + dg + 2] = pk2(kv.z, kv.w);
            *(uint32_t*)&Kl[s * AST + dg] = pk2(rlo(kv.x), rlo(kv.y));
            *(uint32_t*)&Kl[s * AST + dg + 2] = pk2(rlo(kv.z), rlo(kv.w));
            float4 vv = *(const float4*)(base + 1 * D);
            Vh[(dg + 0) * AST + s] = __float2bfloat16(vv.x);
            Vh[(dg + 1) * AST + s] = __float2bfloat16(vv.y);
            Vh[(dg + 2) * AST + s] = __float2bfloat16(vv.z);
            Vh[(dg + 3) * AST + s] = __float2bfloat16(vv.w);
            Vl[(dg + 0) * AST + s] = __float2bfloat16(rlo(vv.x));
            Vl[(dg + 1) * AST + s] = __float2bfloat16(rlo(vv.y));
            Vl[(dg + 2) * AST + s] = __float2bfloat16(rlo(vv.z));
            Vl[(dg + 3) * AST + s] = __float2bfloat16(rlo(vv.w));
        }
        if (tid < 64) val_s[tid] = (float)g_valid[b * T + s0 + tid];
        __syncthreads();

        float sacc[4][4];
#pragma unroll
        for (int i = 0; i < 4; i++)
#pragma unroll
            for (int j = 0; j < 4; j++) sacc[i][j] = 0.0f;

#pragma unroll
        for (int ks = 0; ks < 4; ks++) {
            const int kb = ks * 16;
            uint32_t ah[4], al[4];
            const int abase = (wm * 16 + r) * AST + kb + kc;
            ah[0] = *(const uint32_t*)&Qh[abase];
            ah[1] = *(const uint32_t*)&Qh[abase + 8 * AST];
            ah[2] = *(const uint32_t*)&Qh[abase + 8];
            ah[3] = *(const uint32_t*)&Qh[abase + 8 * AST + 8];
            al[0] = *(const uint32_t*)&Ql[abase];
            al[1] = *(const uint32_t*)&Ql[abase + 8 * AST];
            al[2] = *(const uint32_t*)&Ql[abase + 8];
            al[3] = *(const uint32_t*)&Ql[abase + 8 * AST + 8];
#pragma unroll
            for (int nt = 0; nt < 4; nt++) {
                const int bb = (wn * 32 + nt * 8 + r) * AST + kb + kc;
                uint32_t bh[2], bl[2];
                bh[0] = *(const uint32_t*)&Kh[bb];
                bh[1] = *(const uint32_t*)&Kh[bb + 8];
                bl[0] = *(const uint32_t*)&Kl[bb];
                bl[1] = *(const uint32_t*)&Kl[bb + 8];
                mma_bf16(sacc[nt], ah, bh);
                mma_bf16(sacc[nt], ah, bl);
                mma_bf16(sacc[nt], al, bh);
            }
        }

        // pointwise epilogue -> P (hi/lo) in smem
        const bool diag = (st == qt);
        const float den0 = den_s[wm * 16 + r];
        const float den1 = den_s[wm * 16 + r + 8];
        const int t0 = q0 + wm * 16 + r;
        const int t1 = t0 + 8;
#pragma unroll
        for (int nt = 0; nt < 4; nt++) {
            const int col = wn * 32 + nt * 8 + kc;
            const int sA = s0 + col;
            const int sB = sA + 1;
            const float vA = val_s[col];
            const float vB = val_s[col + 1];
            float p00 = 0.0f, p01 = 0.0f, p10 = 0.0f, p11 = 0.0f;
            bool okA0 = (vA != 0.0f);
            bool okB0 = (vB != 0.0f);
            bool okA1 = okA0;
            bool okB1 = okB0;
            if (diag) {
                if (okA0) okA0 = (amask[(size_t)t0 * T + sA] == 0.0f);
                if (okB0) okB0 = (amask[(size_t)t0 * T + sB] == 0.0f);
                if (okA1) okA1 = (amask[(size_t)t1 * T + sA] == 0.0f);
                if (okB1) okB1 = (amask[(size_t)t1 * T + sB] == 0.0f);
            }
            if (okA0) {
                float xv = sacc[nt][0] * alpha + rab_s[bkt_s[t0 - sA]];
                p00 = xv / (1.0f + expf(-xv)) / den0;
            }
            if (okB0) {
                float xv = sacc[nt][1] * alpha + rab_s[bkt_s[t0 - sB]];
                p01 = xv / (1.0f + expf(-xv)) / den0;
            }
            if (okA1) {
                float xv = sacc[nt][2] * alpha + rab_s[bkt_s[t1 - sA]];
                p10 = xv / (1.0f + expf(-xv)) / den1;
            }
            if (okB1) {
                float xv = sacc[nt][3] * alpha + rab_s[bkt_s[t1 - sB]];
                p11 = xv / (1.0f + expf(-xv)) / den1;
            }
            *(uint32_t*)&Ph[(wm * 16 + r) * AST + col] = pk2(p00, p01);
            *(uint32_t*)&Ph[(wm * 16 + r + 8) * AST + col] = pk2(p10, p11);
            *(uint32_t*)&Pl[(wm * 16 + r) * AST + col] = pk2(rlo(p00), rlo(p01));
            *(uint32_t*)&Pl[(wm * 16 + r + 8) * AST + col] = pk2(rlo(p10), rlo(p11));
        }
        __syncthreads();

        // O += P V   (A = P [q][s], B = Vt [d][s])
#pragma unroll
        for (int ks = 0; ks < 4; ks++) {
            const int kb = ks * 16;
            uint32_t ah[4], al[4];
            const int abase = (wm * 16 + r) * AST + kb + kc;
            ah[0] = *(const uint32_t*)&Ph[abase];
            ah[1] = *(const uint32_t*)&Ph[abase + 8 * AST];
            ah[2] = *(const uint32_t*)&Ph[abase + 8];
            ah[3] = *(const uint32_t*)&Ph[abase + 8 * AST + 8];
            al[0] = *(const uint32_t*)&Pl[abase];
            al[1] = *(const uint32_t*)&Pl[abase + 8 * AST];
            al[2] = *(const uint32_t*)&Pl[abase + 8];
            al[3] = *(const uint32_t*)&Pl[abase + 8 * AST + 8];
#pragma unroll
            for (int nt = 0; nt < 4; nt++) {
                const int bb = (wn * 32 + nt * 8 + r) * AST + kb + kc;
                uint32_t bh[2], bl[2];
                bh[0] = *(const uint32_t*)&Vh[bb];
                bh[1] = *(const uint32_t*)&Vh[bb + 8];
                bl[0] = *(const uint32_t*)&Vl[bb];
                bl[1] = *(const uint32_t*)&Vl[bb + 8];
                mma_bf16(oacc[nt], ah, bh);
                mma_bf16(oacc[nt], ah, bl);
                mma_bf16(oacc[nt], al, bh);
            }
        }
    }

    // store O
    const int t0 = q0 + wm * 16 + r;
    const int t1 = t0 + 8;
#pragma unroll
    for (int nt = 0; nt < 4; nt++) {
        const int d0 = head * 64 + wn * 32 + nt * 8 + kc;
        float2 w0;
        w0.x = oacc[nt][0];
        w0.y = oacc[nt][1];
        float2 w1;
        w1.x = oacc[nt][2];
        w1.y = oacc[nt][3];
        *(float2*)(g_AV + (size_t)(b * T + t0) * D + d0) = w0;
        *(float2*)(g_AV + (size_t)(b * T + t1) * D + d0) = w1;
    }
}

// ======================= LayerNorm * U =====================================
__global__ void ln_kernel(const float* __restrict__ gamma, const float* __restrict__ beta, int D) {
    const int row = blockIdx.x;
    const int tid = threadIdx.x;
    const int D4 = 4 * D;
    float4 v = *(const float4*)(g_AV + (size_t)row * D + tid * 4);
    __shared__ float red[8];
    float s = v.x + v.y + v.z + v.w;
#pragma unroll
    for (int o = 16; o; o >>= 1) s += __shfl_xor_sync(0xffffffffu, s, o);
    if ((tid & 31) == 0) red[tid >> 5] = s;
    __syncthreads();
    if (tid == 0) {
        float t = 0;
#pragma unroll
        for (int i = 0; i < 8; i++) t += red[i];
        red[0] = t;
    }
    __syncthreads();
    const float mean = red[0] / (float)D;
    __syncthreads();
    float dx = v.x - mean, dy = v.y - mean, dz = v.z - mean, dw = v.w - mean;
    float s2 = dx * dx + dy * dy + dz * dz + dw * dw;
#pragma unroll
    for (int o = 16; o; o >>= 1) s2 += __shfl_xor_sync(0xffffffffu, s2, o);
    if ((tid & 31) == 0) red[tid >> 5] = s2;
    __syncthreads();
    if (tid == 0) {
        float t = 0;
#pragma unroll
        for (int i = 0; i < 8; i++) t += red[i];
        red[0] = t;
    }
    __syncthreads();
    const float var = red[0] / (float)D;
    const float rstd = rsqrtf(var + 1e-5f);
    float4 g = *(const float4*)(gamma + tid * 4);
    float4 bb = *(const float4*)(beta + tid * 4);
    float4 u = *(const float4*)(g_H4 + (size_t)row * D4 + tid * 4);
    float4 z;
    z.x = ((v.x - mean) * rstd * g.x + bb.x) * u.x;
    z.y = ((v.y - mean) * rstd * g.y + bb.y) * u.y;
    z.z = ((v.z - mean) * rstd * g.z + bb.z) * u.z;
    z.w = ((v.w - mean) * rstd * g.w + bb.w) * u.w;
    *(float4*)(g_Z + (size_t)row * D + tid * 4) = z;
}

// ---------------------------------------------------------------------------
extern "C" void kernel_launch(void* const* d_in, const int* in_sizes, int n_in,
                              void* d_out, int out_size) {
    (void)n_in;
    (void)out_size;
    const float* x = (const float*)d_in[0];
    const float* amask = (const float*)d_in[1];
    const void* kpm = d_in[2];
    const float* W_in = (const float*)d_in[3];
    const float* b_in = (const float*)d_in[4];
    const float* W_out = (const float*)d_in[5];
    const float* b_out = (const float*)d_in[6];
    const float* gamma = (const float*)d_in[7];
    const float* beta = (const float*)d_in[8];
    const float* rab = (const float*)d_in[9];
    float* out = (float*)d_out;

    const int D = in_sizes[7];
    int T = 1;
    while ((long long)T * T < (long long)in_sizes[1]) T++;
    const int B = in_sizes[0] / (T * D);
    const int H = in_sizes[9] / NBUCKETS;
    const int BT = B * T;
    const float alpha = rsqrtf((float)(D / H));

    float *pH4, *pZ;
    cudaGetSymbolAddress((void**)&pH4, g_H4);
    cudaGetSymbolAddress((void**)&pZ, g_Z);
    __nv_bfloat16 *pxh, *pxl, *pwih, *pwil, *pwoh, *pwol, *pzh, *pzl;
    cudaGetSymbolAddress((void**)&pxh, g_xh);
    cudaGetSymbolAddress((void**)&pxl, g_xl);
    cudaGetSymbolAddress((void**)&pwih, g_wih);
    cudaGetSymbolAddress((void**)&pwil, g_wil);
    cudaGetSymbolAddress((void**)&pwoh, g_woh);
    cudaGetSymbolAddress((void**)&pwol, g_wol);
    cudaGetSymbolAddress((void**)&pzh, g_zh);
    cudaGetSymbolAddress((void**)&pzl, g_zl);

    cudaFuncSetAttribute(attn_kernel, cudaFuncAttributeMaxDynamicSharedMemorySize, ATTN_SMEM);
    cudaFuncSetAttribute(hgemm_kernel, cudaFuncAttributeMaxDynamicSharedMemorySize, GEMM_SMEM);

    split_kernel<<<(BT * D / 4 + 255) / 256, 256>>>(x, pxh, pxl, BT * D);
    split_kernel<<<(4 * D * D / 4 + 255) / 256, 256>>>(W_in, pwih, pwil, 4 * D * D);
    split_kernel<<<(D * D / 4 + 255) / 256, 256>>>(W_out, pwoh, pwol, D * D);

    prep_kernel<<<1, 1024>>>(kpm, B, T);
    denom_kernel<<<dim3(T, B), 256>>>(amask, B, T);
    hgemm_kernel<<<dim3(4 * D / 128, BT / 128), 256, GEMM_SMEM>>>(
        pxh, pxl, pwih, pwil, b_in, nullptr, pH4, BT, 4 * D, D, 0);
    attn_kernel<<<dim3(T / 64, H, B), 256, ATTN_SMEM>>>(amask, rab, T, H, D, alpha);
    ln_kernel<<<BT, D / 4>>>(gamma, beta, D);
    split_kernel<<<(BT * D / 4 + 255) / 256, 256>>>(pZ, pzh, pzl, BT * D);
    hgemm_kernel<<<dim3(D / 128, BT / 128), 256, GEMM_SMEM>>>(
        pzh, pzl, pwoh, pwol, b_out, x, out, BT, D, D, 1);
}

// round 14
// speedup vs baseline: 2.0298x; 1.0975x over previous
#include <cuda_runtime.h>
#include <cuda_bf16.h>
#include <cstdint>
#include <math.h>

// ---------------------------------------------------------------------------
// HSTU layer. Dense GEMMs + attention on warp-level mma.sync bf16 (hi/lo
// split -> ~fp32 accuracy). All fp32->bf16 conversion hoisted out of the
// attention loop (GEMM1 epilogue emits Q/K bf16; V transposed once).
// ---------------------------------------------------------------------------

#define MAXB 2
#define MAXT 1024
#define MAXD 1024
#define MAXH 16
#define NBUCKETS 32

__device__ float g_H4[(size_t)MAXB * MAXT * 4 * MAXD];   // U,V fp32 (Q,K regions unused)
__device__ float g_AV[(size_t)MAXB * MAXT * MAXD];
__device__ float g_denom[MAXB * MAXT];
__device__ unsigned char g_valid[MAXB * MAXT];
__device__ int g_bucket[MAXT];
__device__ float g_rabd[MAXH * MAXT];                    // rab value per (head, t-s)

__device__ __nv_bfloat16 g_xh[(size_t)MAXB * MAXT * MAXD];
__device__ __nv_bfloat16 g_xl[(size_t)MAXB * MAXT * MAXD];
__device__ __nv_bfloat16 g_wih[(size_t)4 * MAXD * MAXD];
__device__ __nv_bfloat16 g_wil[(size_t)4 * MAXD * MAXD];
__device__ __nv_bfloat16 g_woh[(size_t)MAXD * MAXD];
__device__ __nv_bfloat16 g_wol[(size_t)MAXD * MAXD];
__device__ __nv_bfloat16 g_zh[(size_t)MAXB * MAXT * MAXD];
__device__ __nv_bfloat16 g_zl[(size_t)MAXB * MAXT * MAXD];
// attention operands (bf16 hi/lo)
__device__ __nv_bfloat16 g_qh[(size_t)MAXB * MAXT * MAXD];
__device__ __nv_bfloat16 g_ql[(size_t)MAXB * MAXT * MAXD];
__device__ __nv_bfloat16 g_kh[(size_t)MAXB * MAXT * MAXD];
__device__ __nv_bfloat16 g_kl[(size_t)MAXB * MAXT * MAXD];
__device__ __nv_bfloat16 g_vth[(size_t)MAXB * MAXH * 64 * MAXT];  // [b][h][d][T]
__device__ __nv_bfloat16 g_vtl[(size_t)MAXB * MAXH * 64 * MAXT];

// ======================= helpers ===========================================

__device__ __forceinline__ uint32_t smem_to_u32(const void* smem_ptr) {
    uint32_t addr;
    asm("{ .reg .u64 tmp; cvta.to.shared.u64 tmp, %1; cvt.u32.u64 %0, tmp; }"
        : "=r"(addr) : "l"(smem_ptr));
    return addr;
}

#define CP_ASYNC16(dst, src) \
    asm volatile("cp.async.cg.shared.global [%0], [%1], 16;" :: "r"(dst), "l"(src) : "memory")
#define CP_ASYNC_COMMIT() asm volatile("cp.async.commit_group;" ::: "memory")
#define CP_ASYNC_WAIT0() asm volatile("cp.async.wait_group 0;" ::: "memory")
#define CP_ASYNC_WAIT1() asm volatile("cp.async.wait_group 1;" ::: "memory")

__device__ __forceinline__ void mma_bf16(float* c, const uint32_t* a, const uint32_t* b) {
    asm volatile(
        "mma.sync.aligned.m16n8k16.row.col.f32.bf16.bf16.f32 "
        "{%0,%1,%2,%3}, {%4,%5,%6,%7}, {%8,%9}, {%0,%1,%2,%3};"
        : "+f"(c[0]), "+f"(c[1]), "+f"(c[2]), "+f"(c[3])
        : "r"(a[0]), "r"(a[1]), "r"(a[2]), "r"(a[3]), "r"(b[0]), "r"(b[1]));
}

__device__ __forceinline__ uint32_t pk2(float x, float y) {
    unsigned short lo = __bfloat16_as_ushort(__float2bfloat16(x));
    unsigned short hi = __bfloat16_as_ushort(__float2bfloat16(y));
    return (uint32_t)lo | ((uint32_t)hi << 16);
}
__device__ __forceinline__ float rlo(float x) {
    return x - __bfloat162float(__float2bfloat16(x));
}

// ======================= split fp32 -> bf16 hi/lo ===========================
__global__ void split_kernel(const float* __restrict__ src, __nv_bfloat16* __restrict__ hi,
                             __nv_bfloat16* __restrict__ lo, int n) {
    int i = blockIdx.x * blockDim.x + threadIdx.x;
    if (i >= n / 4) return;
    float4 v = ((const float4*)src)[i];
    float a0 = v.x;
    float a1 = v.y;
    float a2 = v.z;
    float a3 = v.w;
    __nv_bfloat16 h0 = __float2bfloat16(a0);
    __nv_bfloat16 h1 = __float2bfloat16(a1);
    __nv_bfloat16 h2 = __float2bfloat16(a2);
    __nv_bfloat16 h3 = __float2bfloat16(a3);
    hi[4 * i + 0] = h0;
    hi[4 * i + 1] = h1;
    hi[4 * i + 2] = h2;
    hi[4 * i + 3] = h3;
    lo[4 * i + 0] = __float2bfloat16(a0 - __bfloat162float(h0));
    lo[4 * i + 1] = __float2bfloat16(a1 - __bfloat162float(h1));
    lo[4 * i + 2] = __float2bfloat16(a2 - __bfloat162float(h2));
    lo[4 * i + 3] = __float2bfloat16(a3 - __bfloat162float(h3));
}

// ======================= prep ==============================================
__global__ void prep_kernel(const void* __restrict__ kpm, const float* __restrict__ rab_emb,
                            int B, int T, int H) {
    const int M = B * T;
    __shared__ int oddbyte;
    if (threadIdx.x == 0) oddbyte = 0;
    __syncthreads();
    const unsigned char* bp = (const unsigned char*)kpm;
    int local = 0;
    for (int i = threadIdx.x; i < M; i += blockDim.x)
        if (bp[i] != 0 && (i & 3) != 0) local = 1;
    if (local) atomicOr(&oddbyte, 1);
    __syncthreads();
    const int isByte = oddbyte;
    const int* ip = (const int*)kpm;
    for (int i = threadIdx.x; i < M; i += blockDim.x) {
        int pad = isByte ? (bp[i] != 0) : (ip[i] != 0);
        g_valid[i] = pad ? 0 : 1;
    }
    for (int n = threadIdx.x; n < T; n += blockDim.x) {
        int bkt;
        if (n < 16) {
            bkt = n;
        } else {
            float v = logf((float)n / 16.0f + 1e-6f) / 2.0794415416798357f * 16.0f;
            int lg = 16 + (int)v;
            bkt = lg < (NBUCKETS - 1) ? lg : (NBUCKETS - 1);
        }
        g_bucket[n] = bkt;
    }
    __syncthreads();
    for (int i = threadIdx.x; i < H * T; i += blockDim.x) {
        int h = i / T;
        int n = i - h * T;
        g_rabd[i] = rab_emb[g_bucket[n] * H + h];
    }
}

// ======================= denom =============================================
__global__ void denom_kernel(const float* __restrict__ amask, int B, int T) {
    const int t = blockIdx.x;
    const int b = blockIdx.y;
    int cnt = 0;
    for (int s = threadIdx.x; s < T; s += blockDim.x)
        cnt += (amask[(size_t)t * T + s] == 0.0f && g_valid[b * T + s]) ? 1 : 0;
#pragma unroll
    for (int o = 16; o; o >>= 1) cnt += __shfl_xor_sync(0xffffffffu, cnt, o);
    __shared__ int red[8];
    if ((threadIdx.x & 31) == 0) red[threadIdx.x >> 5] = cnt;
    __syncthreads();
    if (threadIdx.x == 0) {
        int tot = 0;
#pragma unroll
        for (int i = 0; i < 8; i++) tot += red[i];
        if (tot < 1) tot = 1;
        g_denom[b * T + t] = (float)tot;
    }
}

// ======================= HMMA GEMM =========================================
// mode 0: silu; U,V regions -> fp32 C; Q,K regions -> bf16 hi/lo globals.
// mode 1: + resid -> fp32 C.
#define GS 40
#define TILE_B (128 * GS * 2)
#define OFF_AH 0
#define OFF_AL (TILE_B)
#define OFF_BH (2 * TILE_B)
#define OFF_BL (3 * TILE_B)
#define STAGE_B (4 * TILE_B)
#define GEMM_SMEM (2 * STAGE_B)

__global__ __launch_bounds__(256) void hgemm_kernel(
    const __nv_bfloat16* __restrict__ Ah, const __nv_bfloat16* __restrict__ Al,
    const __nv_bfloat16* __restrict__ Bh, const __nv_bfloat16* __restrict__ Bl,
    const float* __restrict__ bias, const float* __restrict__ resid, float* __restrict__ C,
    int M, int N, int K, int mode) {
    extern __shared__ char dynsmem[];
    const uint32_t sbase = smem_to_u32(dynsmem);
    const int tid = threadIdx.x;
    const int wid = tid >> 5;
    const int lane = tid & 31;
    const int wm = wid & 3;
    const int wn = wid >> 2;
    const int m0 = blockIdx.y * 128;
    const int n0 = blockIdx.x * 128;

    uint32_t adst[2];
    const __nv_bfloat16* aH[2];
    const __nv_bfloat16* aL[2];
    const __nv_bfloat16* bH[2];
    const __nv_bfloat16* bL[2];
#pragma unroll
    for (int i = 0; i < 2; i++) {
        int u = tid + 256 * i;
        int row = u >> 2;
        int un = u & 3;
        adst[i] = (uint32_t)(row * (GS * 2) + un * 16);
        aH[i] = Ah + (size_t)(m0 + row) * K + un * 8;
        aL[i] = Al + (size_t)(m0 + row) * K + un * 8;
        bH[i] = Bh + (size_t)(n0 + row) * K + un * 8;
        bL[i] = Bl + (size_t)(n0 + row) * K + un * 8;
    }

#define ISSUE_LOADS(ch, st)                                      \
    do {                                                         \
        uint32_t _sb = sbase + (uint32_t)((st) * STAGE_B);       \
        int _k0 = (ch) * 32;                                     \
        _Pragma("unroll") for (int _i = 0; _i < 2; _i++) {       \
            CP_ASYNC16(_sb + OFF_AH + adst[_i], aH[_i] + _k0);   \
            CP_ASYNC16(_sb + OFF_AL + adst[_i], aL[_i] + _k0);   \
            CP_ASYNC16(_sb + OFF_BH + adst[_i], bH[_i] + _k0);   \
            CP_ASYNC16(_sb + OFF_BL + adst[_i], bL[_i] + _k0);   \
        }                                                        \
        CP_ASYNC_COMMIT();                                       \
    } while (0)

    float acc[2][8][4];
#pragma unroll
    for (int mi = 0; mi < 2; mi++)
#pragma unroll
        for (int ni = 0; ni < 8; ni++)
#pragma unroll
            for (int j = 0; j < 4; j++) acc[mi][ni][j] = 0.0f;

    const int r = lane >> 2;
    const int kc = (lane & 3) * 2;

    const int NCH = K >> 5;
    ISSUE_LOADS(0, 0);
    for (int ch = 0; ch < NCH; ch++) {
        if (ch + 1 < NCH) {
            ISSUE_LOADS(ch + 1, (ch + 1) & 1);
            CP_ASYNC_WAIT1();
        } else {
            CP_ASYNC_WAIT0();
        }
        __syncthreads();

        const char* stb = dynsmem + (ch & 1) * STAGE_B;
        const __nv_bfloat16* sAh = (const __nv_bfloat16*)(stb + OFF_AH);
        const __nv_bfloat16* sAl = (const __nv_bfloat16*)(stb + OFF_AL);
        const __nv_bfloat16* sBh = (const __nv_bfloat16*)(stb + OFF_BH);
        const __nv_bfloat16* sBl = (const __nv_bfloat16*)(stb + OFF_BL);

#pragma unroll
        for (int ks = 0; ks < 2; ks++) {
            const int kb = ks * 16;
            uint32_t afh[2][4], afl[2][4];
#pragma unroll
            for (int mi = 0; mi < 2; mi++) {
                const int base = (wm * 32 + mi * 16 + r) * GS + kb + kc;
                afh[mi][0] = *(const uint32_t*)&sAh[base];
                afh[mi][1] = *(const uint32_t*)&sAh[base + 8 * GS];
                afh[mi][2] = *(const uint32_t*)&sAh[base + 8];
                afh[mi][3] = *(const uint32_t*)&sAh[base + 8 * GS + 8];
                afl[mi][0] = *(const uint32_t*)&sAl[base];
                afl[mi][1] = *(const uint32_t*)&sAl[base + 8 * GS];
                afl[mi][2] = *(const uint32_t*)&sAl[base + 8];
                afl[mi][3] = *(const uint32_t*)&sAl[base + 8 * GS + 8];
            }
            uint32_t bfh[8][2], bfl[8][2];
#pragma unroll
            for (int ni = 0; ni < 8; ni++) {
                const int bb = (wn * 64 + ni * 8 + r) * GS + kb + kc;
                bfh[ni][0] = *(const uint32_t*)&sBh[bb];
                bfh[ni][1] = *(const uint32_t*)&sBh[bb + 8];
                bfl[ni][0] = *(const uint32_t*)&sBl[bb];
                bfl[ni][1] = *(const uint32_t*)&sBl[bb + 8];
            }
#pragma unroll
            for (int mi = 0; mi < 2; mi++)
#pragma unroll
                for (int ni = 0; ni < 8; ni++) {
                    mma_bf16(acc[mi][ni], afh[mi], bfh[ni]);
                    mma_bf16(acc[mi][ni], afh[mi], bfl[ni]);
                    mma_bf16(acc[mi][ni], afl[mi], bfh[ni]);
                }
        }
        __syncthreads();
    }

    const int Dq = N >> 2;  // region width when mode==0 (N = 4D)
#pragma unroll
    for (int mi = 0; mi < 2; mi++) {
        const int r0 = m0 + wm * 32 + mi * 16 + r;
        const int r1 = r0 + 8;
#pragma unroll
        for (int ni = 0; ni < 8; ni++) {
            const int c0 = n0 + wn * 64 + ni * 8 + kc;
            float2 bv = *(const float2*)(bias + c0);
            float o0 = acc[mi][ni][0] + bv.x;
            float o1 = acc[mi][ni][1] + bv.y;
            float o2 = acc[mi][ni][2] + bv.x;
            float o3 = acc[mi][ni][3] + bv.y;
            if (mode == 0) {
                o0 = o0 / (1.0f + expf(-o0));
                o1 = o1 / (1.0f + expf(-o1));
                o2 = o2 / (1.0f + expf(-o2));
                o3 = o3 / (1.0f + expf(-o3));
                const int region = c0 / Dq;
                if (region >= 2) {
                    __nv_bfloat16* oh = (region == 2) ? g_qh : g_kh;
                    __nv_bfloat16* ol = (region == 2) ? g_ql : g_kl;
                    const int cc = c0 - region * Dq;
                    *(uint32_t*)&oh[(size_t)r0 * Dq + cc] = pk2(o0, o1);
                    *(uint32_t*)&ol[(size_t)r0 * Dq + cc] = pk2(rlo(o0), rlo(o1));
                    *(uint32_t*)&oh[(size_t)r1 * Dq + cc] = pk2(o2, o3);
                    *(uint32_t*)&ol[(size_t)r1 * Dq + cc] = pk2(rlo(o2), rlo(o3));
                    continue;
                }
            } else {
                float2 rv0 = *(const float2*)(resid + (size_t)r0 * N + c0);
                float2 rv1 = *(const float2*)(resid + (size_t)r1 * N + c0);
                o0 += rv0.x;
                o1 += rv0.y;
                o2 += rv1.x;
                o3 += rv1.y;
            }
            float2 w0;
            w0.x = o0;
            w0.y = o1;
            float2 w1;
            w1.x = o2;
            w1.y = o3;
            *(float2*)(C + (size_t)r0 * N + c0) = w0;
            *(float2*)(C + (size_t)r1 * N + c0) = w1;
        }
    }
}

// ======================= V transpose to [b][h][d][T] bf16 hi/lo ============
__global__ __launch_bounds__(256) void convert_vt_kernel(int T, int H, int D) {
    __shared__ float tr[64][65];
    const int s0 = blockIdx.x * 64;
    const int h = blockIdx.y;
    const int b = blockIdx.z;
    const int tid = threadIdx.x;
    const int D4 = 4 * D;
#pragma unroll
    for (int rr = 0; rr < 4; rr++) {
        int idx = rr * 256 + tid;
        int s = idx >> 4;
        int dg = (idx & 15) * 4;
        float4 v = *(const float4*)(g_H4 + (size_t)(b * T + s0 + s) * D4 + D + h * 64 + dg);
        tr[dg + 0][s] = v.x;
        tr[dg + 1][s] = v.y;
        tr[dg + 2][s] = v.z;
        tr[dg + 3][s] = v.w;
    }
    __syncthreads();
    const int d = tid >> 2;
    const int sg = (tid & 3) * 16;
    uint32_t hbuf[8], lbuf[8];
#pragma unroll
    for (int j = 0; j < 8; j++) {
        float f0 = tr[d][sg + 2 * j];
        float f1 = tr[d][sg + 2 * j + 1];
        hbuf[j] = pk2(f0, f1);
        lbuf[j] = pk2(rlo(f0), rlo(f1));
    }
    size_t base = ((size_t)(b * H + h) * 64 + d) * T + s0 + sg;
    *(uint4*)&g_vth[base] = *(uint4*)hbuf;
    *(uint4*)&g_vth[base + 8] = *(uint4*)(hbuf + 4);
    *(uint4*)&g_vtl[base] = *(uint4*)lbuf;
    *(uint4*)&g_vtl[base + 8] = *(uint4*)(lbuf + 4);
}

// ======================= HMMA attention ====================================
// Block = (64-q-tile, head, b), 8 warps: wm (16 q rows), wn (32-wide N).
// K/V tiles double-buffered via cp.async (bf16 pre-converted).
#define AST 72
#define ATB (64 * AST * 2)           // 9216 bytes per tile
#define AQH 0
#define AQL (ATB)
#define APH (2 * ATB)
#define APL (3 * ATB)
#define ASTG (4 * ATB)               // stage region base
#define SKH 0
#define SKL (ATB)
#define SVH (2 * ATB)
#define SVL (3 * ATB)
#define ASTGSZ (4 * ATB)             // 36864 per stage
#define ATTN_SMEM (4 * ATB + 2 * ASTGSZ)   // 110592

__global__ __launch_bounds__(256) void attn_kernel(
    const float* __restrict__ amask, int T, int H, int D, float alpha) {
    extern __shared__ char smc[];
    __nv_bfloat16* Qh = (__nv_bfloat16*)(smc + AQH);
    __nv_bfloat16* Ql = (__nv_bfloat16*)(smc + AQL);
    __nv_bfloat16* Ph = (__nv_bfloat16*)(smc + APH);
    __nv_bfloat16* Pl = (__nv_bfloat16*)(smc + APL);
    const uint32_t sb = smem_to_u32(smc);

    const int tid = threadIdx.x;
    const int wid = tid >> 5;
    const int lane = tid & 31;
    const int wm = wid & 3;
    const int wn = wid >> 2;
    const int r = lane >> 2;
    const int kc = (lane & 3) * 2;
    const int qt = blockIdx.x;
    const int head = blockIdx.y;
    const int b = blockIdx.z;
    const int q0 = qt * 64;

    // Q tile -> smem (bf16, pre-converted)
#pragma unroll
    for (int i = 0; i < 2; i++) {
        int c = tid + 256 * i;
        int q = c >> 3;
        int o = (c & 7) * 8;
        *(uint4*)&Qh[q * AST + o] =
            *(const uint4*)(g_qh + (size_t)(b * T + q0 + q) * D + head * 64 + o);
        *(uint4*)&Ql[q * AST + o] =
            *(const uint4*)(g_ql + (size_t)(b * T + q0 + q) * D + head * 64 + o);
    }

    // cp.async slot setup for K/V tiles
    uint32_t dstoff[2];
    const __nv_bfloat16* ksrcH[2];
    const __nv_bfloat16* ksrcL[2];
    const __nv_bfloat16* vsrcH[2];
    const __nv_bfloat16* vsrcL[2];
#pragma unroll
    for (int i = 0; i < 2; i++) {
        int c = tid + 256 * i;
        int row = c >> 3;
        int o8 = (c & 7) * 8;
        dstoff[i] = (uint32_t)(row * (AST * 2) + o8 * 2);
        ksrcH[i] = g_kh + (size_t)(b * T + row) * D + head * 64 + o8;
        ksrcL[i] = g_kl + (size_t)(b * T + row) * D + head * 64 + o8;
        vsrcH[i] = g_vth + ((size_t)(b * H + head) * 64 + row) * T + o8;
        vsrcL[i] = g_vtl + ((size_t)(b * H + head) * 64 + row) * T + o8;
    }

#define AISSUE(st)                                                          \
    do {                                                                    \
        uint32_t _sb2 = sb + ASTG + ((st) & 1) * ASTGSZ;                    \
        size_t _ko = (size_t)(st) * 64 * D;                                 \
        int _vo = (st) * 64;                                                \
        _Pragma("unroll") for (int _i = 0; _i < 2; _i++) {                  \
            CP_ASYNC16(_sb2 + SKH + dstoff[_i], ksrcH[_i] + _ko);           \
            CP_ASYNC16(_sb2 + SKL + dstoff[_i], ksrcL[_i] + _ko);           \
            CP_ASYNC16(_sb2 + SVH + dstoff[_i], vsrcH[_i] + _vo);           \
            CP_ASYNC16(_sb2 + SVL + dstoff[_i], vsrcL[_i] + _vo);           \
        }                                                                   \
        CP_ASYNC_COMMIT();                                                  \
    } while (0)

    float oacc[4][4];
#pragma unroll
    for (int i = 0; i < 4; i++)
#pragma unroll
        for (int j = 0; j < 4; j++) oacc[i][j] = 0.0f;

    const int t0 = q0 + wm * 16 + r;
    const int t1 = t0 + 8;
    const float den0 = g_denom[b * T + t0];
    const float den1 = g_denom[b * T + t1];
    const float* rabd = g_rabd + head * T;

    AISSUE(0);
    for (int st = 0; st <= qt; st++) {
        const int s0 = st * 64;
        // (A) everyone done reading the buffer the next prefetch will overwrite
        __syncthreads();
        if (st < qt) {
            AISSUE(st + 1);
            CP_ASYNC_WAIT1();   // outstanding {st, st+1} -> waits for stage st
        } else {
            CP_ASYNC_WAIT0();
        }
        // (B) stage st visible to all warps
        __syncthreads();

        const char* stg = smc + ASTG + (st & 1) * ASTGSZ;
        const __nv_bfloat16* Kh = (const __nv_bfloat16*)(stg + SKH);
        const __nv_bfloat16* Kl = (const __nv_bfloat16*)(stg + SKL);
        const __nv_bfloat16* Vh = (const __nv_bfloat16*)(stg + SVH);
        const __nv_bfloat16* Vl = (const __nv_bfloat16*)(stg + SVL);

        float sacc[4][4];
#pragma unroll
        for (int i = 0; i < 4; i++)
#pragma unroll
            for (int j = 0; j < 4; j++) sacc[i][j] = 0.0f;

#pragma unroll
        for (int ks = 0; ks < 4; ks++) {
            const int kb = ks * 16;
            uint32_t ah[4], al[4];
            const int abase = (wm * 16 + r) * AST + kb + kc;
            ah[0] = *(const uint32_t*)&Qh[abase];
            ah[1] = *(const uint32_t*)&Qh[abase + 8 * AST];
            ah[2] = *(const uint32_t*)&Qh[abase + 8];
            ah[3] = *(const uint32_t*)&Qh[abase + 8 * AST + 8];
            al[0] = *(const uint32_t*)&Ql[abase];
            al[1] = *(const uint32_t*)&Ql[abase + 8 * AST];
            al[2] = *(const uint32_t*)&Ql[abase + 8];
            al[3] = *(const uint32_t*)&Ql[abase + 8 * AST + 8];
#pragma unroll
            for (int nt = 0; nt < 4; nt++) {
                const int bb = (wn * 32 + nt * 8 + r) * AST + kb + kc;
                uint32_t bh[2], bl[2];
                bh[0] = *(const uint32_t*)&Kh[bb];
                bh[1] = *(const uint32_t*)&Kh[bb + 8];
                bl[0] = *(const uint32_t*)&Kl[bb];
                bl[1] = *(const uint32_t*)&Kl[bb + 8];
                mma_bf16(sacc[nt], ah, bh);
                mma_bf16(sacc[nt], ah, bl);
                mma_bf16(sacc[nt], al, bh);
            }
        }

        // pointwise epilogue -> P (hi/lo) in smem
        const bool diag = (st == qt);
#pragma unroll
        for (int nt = 0; nt < 4; nt++) {
            const int col = wn * 32 + nt * 8 + kc;
            const int sA = s0 + col;
            const int sB = sA + 1;
            float p00 = 0.0f, p01 = 0.0f, p10 = 0.0f, p11 = 0.0f;
            bool okA0 = (g_valid[b * T + sA] != 0);
            bool okB0 = (g_valid[b * T + sB] != 0);
            bool okA1 = okA0;
            bool okB1 = okB0;
            if (diag) {
                if (okA0) okA0 = (amask[(size_t)t0 * T + sA] == 0.0f);
                if (okB0) okB0 = (amask[(size_t)t0 * T + sB] == 0.0f);
                if (okA1) okA1 = (amask[(size_t)t1 * T + sA] == 0.0f);
                if (okB1) okB1 = (amask[(size_t)t1 * T + sB] == 0.0f);
            }
            if (okA0) {
                float xv = sacc[nt][0] * alpha + rabd[t0 - sA];
                p00 = xv / (1.0f + expf(-xv)) / den0;
            }
            if (okB0) {
                float xv = sacc[nt][1] * alpha + rabd[t0 - sB];
                p01 = xv / (1.0f + expf(-xv)) / den0;
            }
            if (okA1) {
                float xv = sacc[nt][2] * alpha + rabd[t1 - sA];
                p10 = xv / (1.0f + expf(-xv)) / den1;
            }
            if (okB1) {
                float xv = sacc[nt][3] * alpha + rabd[t1 - sB];
                p11 = xv / (1.0f + expf(-xv)) / den1;
            }
            *(uint32_t*)&Ph[(wm * 16 + r) * AST + col] = pk2(p00, p01);
            *(uint32_t*)&Ph[(wm * 16 + r + 8) * AST + col] = pk2(p10, p11);
            *(uint32_t*)&Pl[(wm * 16 + r) * AST + col] = pk2(rlo(p00), rlo(p01));
            *(uint32_t*)&Pl[(wm * 16 + r + 8) * AST + col] = pk2(rlo(p10), rlo(p11));
        }
        __syncthreads();

        // O += P V   (A = P [q][s], B = Vt [d][s])
#pragma unroll
        for (int ks = 0; ks < 4; ks++) {
            const int kb = ks * 16;
            uint32_t ah[4], al[4];
            const int abase = (wm * 16 + r) * AST + kb + kc;
            ah[0] = *(const uint32_t*)&Ph[abase];
            ah[1] = *(const uint32_t*)&Ph[abase + 8 * AST];
            ah[2] = *(const uint32_t*)&Ph[abase + 8];
            ah[3] = *(const uint32_t*)&Ph[abase + 8 * AST + 8];
            al[0] = *(const uint32_t*)&Pl[abase];
            al[1] = *(const uint32_t*)&Pl[abase + 8 * AST];
            al[2] = *(const uint32_t*)&Pl[abase + 8];
            al[3] = *(const uint32_t*)&Pl[abase + 8 * AST + 8];
#pragma unroll
            for (int nt = 0; nt < 4; nt++) {
                const int bb = (wn * 32 + nt * 8 + r) * AST + kb + kc;
                uint32_t bh[2], bl[2];
                bh[0] = *(const uint32_t*)&Vh[bb];
                bh[1] = *(const uint32_t*)&Vh[bb + 8];
                bl[0] = *(const uint32_t*)&Vl[bb];
                bl[1] = *(const uint32_t*)&Vl[bb + 8];
                mma_bf16(oacc[nt], ah, bh);
                mma_bf16(oacc[nt], ah, bl);
                mma_bf16(oacc[nt], al, bh);
            }
        }
    }

#pragma unroll
    for (int nt = 0; nt < 4; nt++) {
        const int d0 = head * 64 + wn * 32 + nt * 8 + kc;
        float2 w0;
        w0.x = oacc[nt][0];
        w0.y = oacc[nt][1];
        float2 w1;
        w1.x = oacc[nt][2];
        w1.y = oacc[nt][3];
        *(float2*)(g_AV + (size_t)(b * T + t0) * D + d0) = w0;
        *(float2*)(g_AV + (size_t)(b * T + t1) * D + d0) = w1;
    }
}

// ======================= LayerNorm * U -> zh/zl ============================
__global__ void ln_kernel(const float* __restrict__ gamma, const float* __restrict__ beta, int D) {
    const int row = blockIdx.x;
    const int tid = threadIdx.x;
    const int D4 = 4 * D;
    float4 v = *(const float4*)(g_AV + (size_t)row * D + tid * 4);
    __shared__ float red[8];
    float s = v.x + v.y + v.z + v.w;
#pragma unroll
    for (int o = 16; o; o >>= 1) s += __shfl_xor_sync(0xffffffffu, s, o);
    if ((tid & 31) == 0) red[tid >> 5] = s;
    __syncthreads();
    if (tid == 0) {
        float t = 0;
#pragma unroll
        for (int i = 0; i < 8; i++) t += red[i];
        red[0] = t;
    }
    __syncthreads();
    const float mean = red[0] / (float)D;
    __syncthreads();
    float dx = v.x - mean, dy = v.y - mean, dz = v.z - mean, dw = v.w - mean;
    float s2 = dx * dx + dy * dy + dz * dz + dw * dw;
#pragma unroll
    for (int o = 16; o; o >>= 1) s2 += __shfl_xor_sync(0xffffffffu, s2, o);
    if ((tid & 31) == 0) red[tid >> 5] = s2;
    __syncthreads();
    if (tid == 0) {
        float t = 0;
#pragma unroll
        for (int i = 0; i < 8; i++) t += red[i];
        red[0] = t;
    }
    __syncthreads();
    const float var = red[0] / (float)D;
    const float rstd = rsqrtf(var + 1e-5f);
    float4 g = *(const float4*)(gamma + tid * 4);
    float4 bb = *(const float4*)(beta + tid * 4);
    float4 u = *(const float4*)(g_H4 + (size_t)row * D4 + tid * 4);
    float z0 = ((v.x - mean) * rstd * g.x + bb.x) * u.x;
    float z1 = ((v.y - mean) * rstd * g.y + bb.y) * u.y;
    float z2 = ((v.z - mean) * rstd * g.z + bb.z) * u.z;
    float z3 = ((v.w - mean) * rstd * g.w + bb.w) * u.w;
    uint32_t* zh = (uint32_t*)(g_zh + (size_t)row * D + tid * 4);
    uint32_t* zl = (uint32_t*)(g_zl + (size_t)row * D + tid * 4);
    zh[0] = pk2(z0, z1);
    zh[1] = pk2(z2, z3);
    zl[0] = pk2(rlo(z0), rlo(z1));
    zl[1] = pk2(rlo(z2), rlo(z3));
}

// ---------------------------------------------------------------------------
extern "C" void kernel_launch(void* const* d_in, const int* in_sizes, int n_in,
                              void* d_out, int out_size) {
    (void)n_in;
    (void)out_size;
    const float* x = (const float*)d_in[0];
    const float* amask = (const float*)d_in[1];
    const void* kpm = d_in[2];
    const float* W_in = (const float*)d_in[3];
    const float* b_in = (const float*)d_in[4];
    const float* W_out = (const float*)d_in[5];
    const float* b_out = (const float*)d_in[6];
    const float* gamma = (const float*)d_in[7];
    const float* beta = (const float*)d_in[8];
    const float* rab = (const float*)d_in[9];
    float* out = (float*)d_out;

    const int D = in_sizes[7];
    int T = 1;
    while ((long long)T * T < (long long)in_sizes[1]) T++;
    const int B = in_sizes[0] / (T * D);
    const int H = in_sizes[9] / NBUCKETS;
    const int BT = B * T;
    const float alpha = rsqrtf((float)(D / H));

    float* pH4;
    cudaGetSymbolAddress((void**)&pH4, g_H4);
    __nv_bfloat16 *pxh, *pxl, *pwih, *pwil, *pwoh, *pwol, *pzh, *pzl;
    cudaGetSymbolAddress((void**)&pxh, g_xh);
    cudaGetSymbolAddress((void**)&pxl, g_xl);
    cudaGetSymbolAddress((void**)&pwih, g_wih);
    cudaGetSymbolAddress((void**)&pwil, g_wil);
    cudaGetSymbolAddress((void**)&pwoh, g_woh);
    cudaGetSymbolAddress((void**)&pwol, g_wol);
    cudaGetSymbolAddress((void**)&pzh, g_zh);
    cudaGetSymbolAddress((void**)&pzl, g_zl);

    cudaFuncSetAttribute(attn_kernel, cudaFuncAttributeMaxDynamicSharedMemorySize, ATTN_SMEM);
    cudaFuncSetAttribute(hgemm_kernel, cudaFuncAttributeMaxDynamicSharedMemorySize, GEMM_SMEM);

    split_kernel<<<(BT * D / 4 + 255) / 256, 256>>>(x, pxh, pxl, BT * D);
    split_kernel<<<(4 * D * D / 4 + 255) / 256, 256>>>(W_in, pwih, pwil, 4 * D * D);
    split_kernel<<<(D * D / 4 + 255) / 256, 256>>>(W_out, pwoh, pwol, D * D);

    prep_kernel<<<1, 1024>>>(kpm, rab, B, T, H);
    denom_kernel<<<dim3(T, B), 256>>>(amask, B, T);
    hgemm_kernel<<<dim3(4 * D / 128, BT / 128), 256, GEMM_SMEM>>>(
        pxh, pxl, pwih, pwil, b_in, nullptr, pH4, BT, 4 * D, D, 0);
    convert_vt_kernel<<<dim3(T / 64, H, B), 256>>>(T, H, D);
    attn_kernel<<<dim3(T / 64, H, B), 256, ATTN_SMEM>>>(amask, T, H, D, alpha);
    ln_kernel<<<BT, D / 4>>>(gamma, beta, D);
    hgemm_kernel<<<dim3(D / 128, BT / 128), 256, GEMM_SMEM>>>(
        pzh, pzl, pwoh, pwol, b_out, x, out, BT, D, D, 1);
}

// round 15
// speedup vs baseline: 2.2640x; 1.1153x over previous
#include <cuda_runtime.h>
#include <cuda_bf16.h>
#include <cstdint>
#include <math.h>

// ---------------------------------------------------------------------------
// HSTU layer. Dense GEMMs + attention on warp-level mma.sync bf16 (hi/lo
// split -> ~fp32 accuracy). ldmatrix fragment loads. Conversions hoisted.
// ---------------------------------------------------------------------------

#define MAXB 2
#define MAXT 1024
#define MAXD 1024
#define MAXH 16
#define NBUCKETS 32

__device__ float g_H4[(size_t)MAXB * MAXT * 4 * MAXD];
__device__ float g_AV[(size_t)MAXB * MAXT * MAXD];
__device__ float g_denom[MAXB * MAXT];
__device__ unsigned char g_valid[MAXB * MAXT];
__device__ float g_rabd[MAXH * MAXT];

__device__ __nv_bfloat16 g_xh[(size_t)MAXB * MAXT * MAXD];
__device__ __nv_bfloat16 g_xl[(size_t)MAXB * MAXT * MAXD];
__device__ __nv_bfloat16 g_wih[(size_t)4 * MAXD * MAXD];
__device__ __nv_bfloat16 g_wil[(size_t)4 * MAXD * MAXD];
__device__ __nv_bfloat16 g_woh[(size_t)MAXD * MAXD];
__device__ __nv_bfloat16 g_wol[(size_t)MAXD * MAXD];
__device__ __nv_bfloat16 g_zh[(size_t)MAXB * MAXT * MAXD];
__device__ __nv_bfloat16 g_zl[(size_t)MAXB * MAXT * MAXD];
__device__ __nv_bfloat16 g_qh[(size_t)MAXB * MAXT * MAXD];
__device__ __nv_bfloat16 g_ql[(size_t)MAXB * MAXT * MAXD];
__device__ __nv_bfloat16 g_kh[(size_t)MAXB * MAXT * MAXD];
__device__ __nv_bfloat16 g_kl[(size_t)MAXB * MAXT * MAXD];
__device__ __nv_bfloat16 g_vth[(size_t)MAXB * MAXH * 64 * MAXT];
__device__ __nv_bfloat16 g_vtl[(size_t)MAXB * MAXH * 64 * MAXT];

// ======================= helpers ===========================================

__device__ __forceinline__ uint32_t smem_to_u32(const void* smem_ptr) {
    uint32_t addr;
    asm("{ .reg .u64 tmp; cvta.to.shared.u64 tmp, %1; cvt.u32.u64 %0, tmp; }"
        : "=r"(addr) : "l"(smem_ptr));
    return addr;
}

#define CP_ASYNC16(dst, src) \
    asm volatile("cp.async.cg.shared.global [%0], [%1], 16;" :: "r"(dst), "l"(src) : "memory")
#define CP_ASYNC_COMMIT() asm volatile("cp.async.commit_group;" ::: "memory")
#define CP_ASYNC_WAIT0() asm volatile("cp.async.wait_group 0;" ::: "memory")
#define CP_ASYNC_WAIT1() asm volatile("cp.async.wait_group 1;" ::: "memory")

__device__ __forceinline__ void mma_bf16(float* c, const uint32_t* a, const uint32_t* b) {
    asm volatile(
        "mma.sync.aligned.m16n8k16.row.col.f32.bf16.bf16.f32 "
        "{%0,%1,%2,%3}, {%4,%5,%6,%7}, {%8,%9}, {%0,%1,%2,%3};"
        : "+f"(c[0]), "+f"(c[1]), "+f"(c[2]), "+f"(c[3])
        : "r"(a[0]), "r"(a[1]), "r"(a[2]), "r"(a[3]), "r"(b[0]), "r"(b[1]));
}

// ldmatrix x4: 4 fragment regs in one shot
__device__ __forceinline__ void ldsm4(uint32_t* r, uint32_t addr) {
    asm volatile("ldmatrix.sync.aligned.m8n8.x4.shared.b16 {%0,%1,%2,%3}, [%4];"
        : "=r"(r[0]), "=r"(r[1]), "=r"(r[2]), "=r"(r[3]) : "r"(addr));
}

__device__ __forceinline__ uint32_t pk2(float x, float y) {
    unsigned short lo = __bfloat16_as_ushort(__float2bfloat16(x));
    unsigned short hi = __bfloat16_as_ushort(__float2bfloat16(y));
    return (uint32_t)lo | ((uint32_t)hi << 16);
}
__device__ __forceinline__ float rlo(float x) {
    return x - __bfloat162float(__float2bfloat16(x));
}

// ======================= split fp32 -> bf16 hi/lo ===========================
__global__ void split_kernel(const float* __restrict__ src, __nv_bfloat16* __restrict__ hi,
                             __nv_bfloat16* __restrict__ lo, int n) {
    int i = blockIdx.x * blockDim.x + threadIdx.x;
    if (i >= n / 4) return;
    float4 v = ((const float4*)src)[i];
    float a0 = v.x;
    float a1 = v.y;
    float a2 = v.z;
    float a3 = v.w;
    __nv_bfloat16 h0 = __float2bfloat16(a0);
    __nv_bfloat16 h1 = __float2bfloat16(a1);
    __nv_bfloat16 h2 = __float2bfloat16(a2);
    __nv_bfloat16 h3 = __float2bfloat16(a3);
    hi[4 * i + 0] = h0;
    hi[4 * i + 1] = h1;
    hi[4 * i + 2] = h2;
    hi[4 * i + 3] = h3;
    lo[4 * i + 0] = __float2bfloat16(a0 - __bfloat162float(h0));
    lo[4 * i + 1] = __float2bfloat16(a1 - __bfloat162float(h1));
    lo[4 * i + 2] = __float2bfloat16(a2 - __bfloat162float(h2));
    lo[4 * i + 3] = __float2bfloat16(a3 - __bfloat162float(h3));
}

// ======================= prep (parallel: block0 valid, rest rabd) ==========
__global__ void prep_kernel(const void* __restrict__ kpm, const float* __restrict__ rab_emb,
                            int B, int T, int H) {
    if (blockIdx.x == 0) {
        const int M = B * T;
        __shared__ int oddbyte;
        if (threadIdx.x == 0) oddbyte = 0;
        __syncthreads();
        const unsigned char* bp = (const unsigned char*)kpm;
        int local = 0;
        for (int i = threadIdx.x; i < M; i += blockDim.x)
            if (bp[i] != 0 && (i & 3) != 0) local = 1;
        if (local) atomicOr(&oddbyte, 1);
        __syncthreads();
        const int isByte = oddbyte;
        const int* ip = (const int*)kpm;
        for (int i = threadIdx.x; i < M; i += blockDim.x) {
            int pad = isByte ? (bp[i] != 0) : (ip[i] != 0);
            g_valid[i] = pad ? 0 : 1;
        }
    } else {
        const int nb = gridDim.x - 1;
        const int total = H * T;
        const int per = (total + nb - 1) / nb;
        const int start = (blockIdx.x - 1) * per;
        const int end = (start + per < total) ? start + per : total;
        for (int i = start + threadIdx.x; i < end; i += blockDim.x) {
            int h = i / T;
            int n = i - h * T;
            int bkt;
            if (n < 16) {
                bkt = n;
            } else {
                float v = logf((float)n / 16.0f + 1e-6f) / 2.0794415416798357f * 16.0f;
                int lg = 16 + (int)v;
                bkt = lg < (NBUCKETS - 1) ? lg : (NBUCKETS - 1);
            }
            g_rabd[i] = rab_emb[bkt * H + h];
        }
    }
}

// ======================= denom =============================================
__global__ void denom_kernel(const float* __restrict__ amask, int B, int T) {
    const int t = blockIdx.x;
    const int b = blockIdx.y;
    int cnt = 0;
    for (int s = threadIdx.x; s < T; s += blockDim.x)
        cnt += (amask[(size_t)t * T + s] == 0.0f && g_valid[b * T + s]) ? 1 : 0;
#pragma unroll
    for (int o = 16; o; o >>= 1) cnt += __shfl_xor_sync(0xffffffffu, cnt, o);
    __shared__ int red[8];
    if ((threadIdx.x & 31) == 0) red[threadIdx.x >> 5] = cnt;
    __syncthreads();
    if (threadIdx.x == 0) {
        int tot = 0;
#pragma unroll
        for (int i = 0; i < 8; i++) tot += red[i];
        if (tot < 1) tot = 1;
        g_denom[b * T + t] = (float)tot;
    }
}

// ======================= HMMA GEMM =========================================
#define GS 40
#define TILE_B (128 * GS * 2)
#define OFF_AH 0
#define OFF_AL (TILE_B)
#define OFF_BH (2 * TILE_B)
#define OFF_BL (3 * TILE_B)
#define STAGE_B (4 * TILE_B)
#define GEMM_SMEM (2 * STAGE_B)

__global__ __launch_bounds__(256) void hgemm_kernel(
    const __nv_bfloat16* __restrict__ Ah, const __nv_bfloat16* __restrict__ Al,
    const __nv_bfloat16* __restrict__ Bh, const __nv_bfloat16* __restrict__ Bl,
    const float* __restrict__ bias, const float* __restrict__ resid, float* __restrict__ C,
    int M, int N, int K, int mode) {
    extern __shared__ char dynsmem[];
    const uint32_t sbase = smem_to_u32(dynsmem);
    const int tid = threadIdx.x;
    const int wid = tid >> 5;
    const int lane = tid & 31;
    const int wm = wid & 3;
    const int wn = wid >> 2;
    const int m0 = blockIdx.y * 128;
    const int n0 = blockIdx.x * 128;

    uint32_t adst[2];
    const __nv_bfloat16* aH[2];
    const __nv_bfloat16* aL[2];
    const __nv_bfloat16* bH[2];
    const __nv_bfloat16* bL[2];
#pragma unroll
    for (int i = 0; i < 2; i++) {
        int u = tid + 256 * i;
        int row = u >> 2;
        int un = u & 3;
        adst[i] = (uint32_t)(row * (GS * 2) + un * 16);
        aH[i] = Ah + (size_t)(m0 + row) * K + un * 8;
        aL[i] = Al + (size_t)(m0 + row) * K + un * 8;
        bH[i] = Bh + (size_t)(n0 + row) * K + un * 8;
        bL[i] = Bl + (size_t)(n0 + row) * K + un * 8;
    }

#define ISSUE_LOADS(ch, st)                                      \
    do {                                                         \
        uint32_t _sb = sbase + (uint32_t)((st) * STAGE_B);       \
        int _k0 = (ch) * 32;                                     \
        _Pragma("unroll") for (int _i = 0; _i < 2; _i++) {       \
            CP_ASYNC16(_sb + OFF_AH + adst[_i], aH[_i] + _k0);   \
            CP_ASYNC16(_sb + OFF_AL + adst[_i], aL[_i] + _k0);   \
            CP_ASYNC16(_sb + OFF_BH + adst[_i], bH[_i] + _k0);   \
            CP_ASYNC16(_sb + OFF_BL + adst[_i], bL[_i] + _k0);   \
        }                                                        \
        CP_ASYNC_COMMIT();                                       \
    } while (0)

    float acc[2][8][4];
#pragma unroll
    for (int mi = 0; mi < 2; mi++)
#pragma unroll
        for (int ni = 0; ni < 8; ni++)
#pragma unroll
            for (int j = 0; j < 4; j++) acc[mi][ni][j] = 0.0f;

    const int r = lane >> 2;
    const int kc = (lane & 3) * 2;
    // ldmatrix per-lane byte offsets
    const int row16 = (lane & 7) + ((lane >> 3) & 1) * 8;
    const int col8 = (lane >> 4) * 8;
    const uint32_t a_loff = (uint32_t)((row16 * GS + col8) * 2);
    const int bsel = lane >> 3;
    const uint32_t b_loff = (uint32_t)((((bsel >> 1) * 8 + (lane & 7)) * GS + (bsel & 1) * 8) * 2);

    const int NCH = K >> 5;
    ISSUE_LOADS(0, 0);
    for (int ch = 0; ch < NCH; ch++) {
        if (ch + 1 < NCH) {
            ISSUE_LOADS(ch + 1, (ch + 1) & 1);
            CP_ASYNC_WAIT1();
        } else {
            CP_ASYNC_WAIT0();
        }
        __syncthreads();

        const uint32_t stg = sbase + (uint32_t)((ch & 1) * STAGE_B);
        const uint32_t uAh = stg + OFF_AH;
        const uint32_t uAl = stg + OFF_AL;
        const uint32_t uBh = stg + OFF_BH;
        const uint32_t uBl = stg + OFF_BL;

#pragma unroll
        for (int ks = 0; ks < 2; ks++) {
            const int kb = ks * 16;
            uint32_t afh[2][4], afl[2][4];
#pragma unroll
            for (int mi = 0; mi < 2; mi++) {
                const uint32_t ab = (uint32_t)(((wm * 32 + mi * 16) * GS + kb) * 2) + a_loff;
                ldsm4(afh[mi], uAh + ab);
                ldsm4(afl[mi], uAl + ab);
            }
            uint32_t bfh[8][2], bfl[8][2];
#pragma unroll
            for (int nip = 0; nip < 4; nip++) {
                const uint32_t bb = (uint32_t)(((wn * 64 + nip * 16) * GS + kb) * 2) + b_loff;
                uint32_t t4[4];
                ldsm4(t4, uBh + bb);
                bfh[2 * nip][0] = t4[0];
                bfh[2 * nip][1] = t4[1];
                bfh[2 * nip + 1][0] = t4[2];
                bfh[2 * nip + 1][1] = t4[3];
                ldsm4(t4, uBl + bb);
                bfl[2 * nip][0] = t4[0];
                bfl[2 * nip][1] = t4[1];
                bfl[2 * nip + 1][0] = t4[2];
                bfl[2 * nip + 1][1] = t4[3];
            }
#pragma unroll
            for (int mi = 0; mi < 2; mi++)
#pragma unroll
                for (int ni = 0; ni < 8; ni++) {
                    mma_bf16(acc[mi][ni], afh[mi], bfh[ni]);
                    mma_bf16(acc[mi][ni], afh[mi], bfl[ni]);
                    mma_bf16(acc[mi][ni], afl[mi], bfh[ni]);
                }
        }
        __syncthreads();
    }

    const int Dq = N >> 2;
#pragma unroll
    for (int mi = 0; mi < 2; mi++) {
        const int r0 = m0 + wm * 32 + mi * 16 + r;
        const int r1 = r0 + 8;
#pragma unroll
        for (int ni = 0; ni < 8; ni++) {
            const int c0 = n0 + wn * 64 + ni * 8 + kc;
            float2 bv = *(const float2*)(bias + c0);
            float o0 = acc[mi][ni][0] + bv.x;
            float o1 = acc[mi][ni][1] + bv.y;
            float o2 = acc[mi][ni][2] + bv.x;
            float o3 = acc[mi][ni][3] + bv.y;
            if (mode == 0) {
                o0 = o0 / (1.0f + expf(-o0));
                o1 = o1 / (1.0f + expf(-o1));
                o2 = o2 / (1.0f + expf(-o2));
                o3 = o3 / (1.0f + expf(-o3));
                const int region = c0 / Dq;
                if (region >= 2) {
                    __nv_bfloat16* oh = (region == 2) ? g_qh : g_kh;
                    __nv_bfloat16* ol = (region == 2) ? g_ql : g_kl;
                    const int cc = c0 - region * Dq;
                    *(uint32_t*)&oh[(size_t)r0 * Dq + cc] = pk2(o0, o1);
                    *(uint32_t*)&ol[(size_t)r0 * Dq + cc] = pk2(rlo(o0), rlo(o1));
                    *(uint32_t*)&oh[(size_t)r1 * Dq + cc] = pk2(o2, o3);
                    *(uint32_t*)&ol[(size_t)r1 * Dq + cc] = pk2(rlo(o2), rlo(o3));
                    continue;
                }
            } else {
                float2 rv0 = *(const float2*)(resid + (size_t)r0 * N + c0);
                float2 rv1 = *(const float2*)(resid + (size_t)r1 * N + c0);
                o0 += rv0.x;
                o1 += rv0.y;
                o2 += rv1.x;
                o3 += rv1.y;
            }
            float2 w0;
            w0.x = o0;
            w0.y = o1;
            float2 w1;
            w1.x = o2;
            w1.y = o3;
            *(float2*)(C + (size_t)r0 * N + c0) = w0;
            *(float2*)(C + (size_t)r1 * N + c0) = w1;
        }
    }
}

// ======================= V transpose to [b][h][d][T] bf16 hi/lo ============
__global__ __launch_bounds__(256) void convert_vt_kernel(int T, int H, int D) {
    __shared__ float tr[64][65];
    const int s0 = blockIdx.x * 64;
    const int h = blockIdx.y;
    const int b = blockIdx.z;
    const int tid = threadIdx.x;
    const int D4 = 4 * D;
#pragma unroll
    for (int rr = 0; rr < 4; rr++) {
        int idx = rr * 256 + tid;
        int s = idx >> 4;
        int dg = (idx & 15) * 4;
        float4 v = *(const float4*)(g_H4 + (size_t)(b * T + s0 + s) * D4 + D + h * 64 + dg);
        tr[dg + 0][s] = v.x;
        tr[dg + 1][s] = v.y;
        tr[dg + 2][s] = v.z;
        tr[dg + 3][s] = v.w;
    }
    __syncthreads();
    const int d = tid >> 2;
    const int sg = (tid & 3) * 16;
    uint32_t hbuf[8], lbuf[8];
#pragma unroll
    for (int j = 0; j < 8; j++) {
        float f0 = tr[d][sg + 2 * j];
        float f1 = tr[d][sg + 2 * j + 1];
        hbuf[j] = pk2(f0, f1);
        lbuf[j] = pk2(rlo(f0), rlo(f1));
    }
    size_t base = ((size_t)(b * H + h) * 64 + d) * T + s0 + sg;
    *(uint4*)&g_vth[base] = *(uint4*)hbuf;
    *(uint4*)&g_vth[base + 8] = *(uint4*)(hbuf + 4);
    *(uint4*)&g_vtl[base] = *(uint4*)lbuf;
    *(uint4*)&g_vtl[base + 8] = *(uint4*)(lbuf + 4);
}

// ======================= HMMA attention ====================================
#define AST 72
#define ATB (64 * AST * 2)
#define AQH 0
#define AQL (ATB)
#define APH (2 * ATB)
#define APL (3 * ATB)
#define ASTG (4 * ATB)
#define SKH 0
#define SKL (ATB)
#define SVH (2 * ATB)
#define SVL (3 * ATB)
#define ASTGSZ (4 * ATB)
#define ATTN_SMEM (4 * ATB + 2 * ASTGSZ)

__global__ __launch_bounds__(256) void attn_kernel(
    const float* __restrict__ amask, int T, int H, int D, float alpha) {
    extern __shared__ char smc[];
    __nv_bfloat16* Qh = (__nv_bfloat16*)(smc + AQH);
    __nv_bfloat16* Ql = (__nv_bfloat16*)(smc + AQL);
    __nv_bfloat16* Ph = (__nv_bfloat16*)(smc + APH);
    __nv_bfloat16* Pl = (__nv_bfloat16*)(smc + APL);
    const uint32_t sb = smem_to_u32(smc);

    const int tid = threadIdx.x;
    const int wid = tid >> 5;
    const int lane = tid & 31;
    const int wm = wid & 3;
    const int wn = wid >> 2;
    const int r = lane >> 2;
    const int kc = (lane & 3) * 2;
    const int qt = blockIdx.x;
    const int head = blockIdx.y;
    const int b = blockIdx.z;
    const int q0 = qt * 64;

    // ldmatrix per-lane byte offsets (attention stride)
    const int row16 = (lane & 7) + ((lane >> 3) & 1) * 8;
    const int col8 = (lane >> 4) * 8;
    const uint32_t a_loff = (uint32_t)((row16 * AST + col8) * 2);
    const int bsel = lane >> 3;
    const uint32_t b_loff =
        (uint32_t)((((bsel >> 1) * 8 + (lane & 7)) * AST + (bsel & 1) * 8) * 2);

    // Q tile -> smem (bf16, pre-converted)
#pragma unroll
    for (int i = 0; i < 2; i++) {
        int c = tid + 256 * i;
        int q = c >> 3;
        int o = (c & 7) * 8;
        *(uint4*)&Qh[q * AST + o] =
            *(const uint4*)(g_qh + (size_t)(b * T + q0 + q) * D + head * 64 + o);
        *(uint4*)&Ql[q * AST + o] =
            *(const uint4*)(g_ql + (size_t)(b * T + q0 + q) * D + head * 64 + o);
    }

    uint32_t dstoff[2];
    const __nv_bfloat16* ksrcH[2];
    const __nv_bfloat16* ksrcL[2];
    const __nv_bfloat16* vsrcH[2];
    const __nv_bfloat16* vsrcL[2];
#pragma unroll
    for (int i = 0; i < 2; i++) {
        int c = tid + 256 * i;
        int row = c >> 3;
        int o8 = (c & 7) * 8;
        dstoff[i] = (uint32_t)(row * (AST * 2) + o8 * 2);
        ksrcH[i] = g_kh + (size_t)(b * T + row) * D + head * 64 + o8;
        ksrcL[i] = g_kl + (size_t)(b * T + row) * D + head * 64 + o8;
        vsrcH[i] = g_vth + ((size_t)(b * H + head) * 64 + row) * T + o8;
        vsrcL[i] = g_vtl + ((size_t)(b * H + head) * 64 + row) * T + o8;
    }

#define AISSUE(st)                                                          \
    do {                                                                    \
        uint32_t _sb2 = sb + ASTG + ((st) & 1) * ASTGSZ;                    \
        size_t _ko = (size_t)(st) * 64 * D;                                 \
        int _vo = (st) * 64;                                                \
        _Pragma("unroll") for (int _i = 0; _i < 2; _i++) {                  \
            CP_ASYNC16(_sb2 + SKH + dstoff[_i], ksrcH[_i] + _ko);           \
            CP_ASYNC16(_sb2 + SKL + dstoff[_i], ksrcL[_i] + _ko);           \
            CP_ASYNC16(_sb2 + SVH + dstoff[_i], vsrcH[_i] + _vo);           \
            CP_ASYNC16(_sb2 + SVL + dstoff[_i], vsrcL[_i] + _vo);           \
        }                                                                   \
        CP_ASYNC_COMMIT();                                                  \
    } while (0)

    float oacc[4][4];
#pragma unroll
    for (int i = 0; i < 4; i++)
#pragma unroll
        for (int j = 0; j < 4; j++) oacc[i][j] = 0.0f;

    const int t0 = q0 + wm * 16 + r;
    const int t1 = t0 + 8;
    const float den0 = g_denom[b * T + t0];
    const float den1 = g_denom[b * T + t1];
    const float* rabd = g_rabd + head * T;

    AISSUE(0);
    for (int st = 0; st <= qt; st++) {
        const int s0 = st * 64;
        __syncthreads();
        if (st < qt) {
            AISSUE(st + 1);
            CP_ASYNC_WAIT1();
        } else {
            CP_ASYNC_WAIT0();
        }
        __syncthreads();

        const uint32_t stg = sb + ASTG + (uint32_t)((st & 1) * ASTGSZ);
        const uint32_t uKh = stg + SKH;
        const uint32_t uKl = stg + SKL;
        const uint32_t uVh = stg + SVH;
        const uint32_t uVl = stg + SVL;

        float sacc[4][4];
#pragma unroll
        for (int i = 0; i < 4; i++)
#pragma unroll
            for (int j = 0; j < 4; j++) sacc[i][j] = 0.0f;

#pragma unroll
        for (int ks = 0; ks < 4; ks++) {
            const int kb = ks * 16;
            uint32_t ah[4], al[4];
            const uint32_t ab = (uint32_t)(((wm * 16) * AST + kb) * 2) + a_loff;
            ldsm4(ah, sb + AQH + ab);
            ldsm4(al, sb + AQL + ab);
            uint32_t bh[4][2], bl[4][2];
#pragma unroll
            for (int nip = 0; nip < 2; nip++) {
                const uint32_t bb = (uint32_t)(((wn * 32 + nip * 16) * AST + kb) * 2) + b_loff;
                uint32_t t4[4];
                ldsm4(t4, uKh + bb);
                bh[2 * nip][0] = t4[0];
                bh[2 * nip][1] = t4[1];
                bh[2 * nip + 1][0] = t4[2];
                bh[2 * nip + 1][1] = t4[3];
                ldsm4(t4, uKl + bb);
                bl[2 * nip][0] = t4[0];
                bl[2 * nip][1] = t4[1];
                bl[2 * nip + 1][0] = t4[2];
                bl[2 * nip + 1][1] = t4[3];
            }
#pragma unroll
            for (int nt = 0; nt < 4; nt++) {
                mma_bf16(sacc[nt], ah, bh[nt]);
                mma_bf16(sacc[nt], ah, bl[nt]);
                mma_bf16(sacc[nt], al, bh[nt]);
            }
        }

        // pointwise epilogue -> P (hi/lo) in smem
        const bool diag = (st == qt);
#pragma unroll
        for (int nt = 0; nt < 4; nt++) {
            const int col = wn * 32 + nt * 8 + kc;
            const int sA = s0 + col;
            const int sB = sA + 1;
            float p00 = 0.0f, p01 = 0.0f, p10 = 0.0f, p11 = 0.0f;
            bool okA0 = (g_valid[b * T + sA] != 0);
            bool okB0 = (g_valid[b * T + sB] != 0);
            bool okA1 = okA0;
            bool okB1 = okB0;
            if (diag) {
                if (okA0) okA0 = (amask[(size_t)t0 * T + sA] == 0.0f);
                if (okB0) okB0 = (amask[(size_t)t0 * T + sB] == 0.0f);
                if (okA1) okA1 = (amask[(size_t)t1 * T + sA] == 0.0f);
                if (okB1) okB1 = (amask[(size_t)t1 * T + sB] == 0.0f);
            }
            if (okA0) {
                float xv = sacc[nt][0] * alpha + rabd[t0 - sA];
                p00 = xv / (1.0f + expf(-xv)) / den0;
            }
            if (okB0) {
                float xv = sacc[nt][1] * alpha + rabd[t0 - sB];
                p01 = xv / (1.0f + expf(-xv)) / den0;
            }
            if (okA1) {
                float xv = sacc[nt][2] * alpha + rabd[t1 - sA];
                p10 = xv / (1.0f + expf(-xv)) / den1;
            }
            if (okB1) {
                float xv = sacc[nt][3] * alpha + rabd[t1 - sB];
                p11 = xv / (1.0f + expf(-xv)) / den1;
            }
            *(uint32_t*)&Ph[(wm * 16 + r) * AST + col] = pk2(p00, p01);
            *(uint32_t*)&Ph[(wm * 16 + r + 8) * AST + col] = pk2(p10, p11);
            *(uint32_t*)&Pl[(wm * 16 + r) * AST + col] = pk2(rlo(p00), rlo(p01));
            *(uint32_t*)&Pl[(wm * 16 + r + 8) * AST + col] = pk2(rlo(p10), rlo(p11));
        }
        __syncthreads();

        // O += P V
#pragma unroll
        for (int ks = 0; ks < 4; ks++) {
            const int kb = ks * 16;
            uint32_t ah[4], al[4];
            const uint32_t ab = (uint32_t)(((wm * 16) * AST + kb) * 2) + a_loff;
            ldsm4(ah, sb + APH + ab);
            ldsm4(al, sb + APL + ab);
            uint32_t bh[4][2], bl[4][2];
#pragma unroll
            for (int nip = 0; nip < 2; nip++) {
                const uint32_t bb = (uint32_t)(((wn * 32 + nip * 16) * AST + kb) * 2) + b_loff;
                uint32_t t4[4];
                ldsm4(t4, uVh + bb);
                bh[2 * nip][0] = t4[0];
                bh[2 * nip][1] = t4[1];
                bh[2 * nip + 1][0] = t4[2];
                bh[2 * nip + 1][1] = t4[3];
                ldsm4(t4, uVl + bb);
                bl[2 * nip][0] = t4[0];
                bl[2 * nip][1] = t4[1];
                bl[2 * nip + 1][0] = t4[2];
                bl[2 * nip + 1][1] = t4[3];
            }
#pragma unroll
            for (int nt = 0; nt < 4; nt++) {
                mma_bf16(oacc[nt], ah, bh[nt]);
                mma_bf16(oacc[nt], ah, bl[nt]);
                mma_bf16(oacc[nt], al, bh[nt]);
            }
        }
    }

#pragma unroll
    for (int nt = 0; nt < 4; nt++) {
        const int d0 = head * 64 + wn * 32 + nt * 8 + kc;
        float2 w0;
        w0.x = oacc[nt][0];
        w0.y = oacc[nt][1];
        float2 w1;
        w1.x = oacc[nt][2];
        w1.y = oacc[nt][3];
        *(float2*)(g_AV + (size_t)(b * T + t0) * D + d0) = w0;
        *(float2*)(g_AV + (size_t)(b * T + t1) * D + d0) = w1;
    }
}

// ======================= LayerNorm * U -> zh/zl ============================
__global__ void ln_kernel(const float* __restrict__ gamma, const float* __restrict__ beta, int D) {
    const int row = blockIdx.x;
    const int tid = threadIdx.x;
    const int D4 = 4 * D;
    float4 v = *(const float4*)(g_AV + (size_t)row * D + tid * 4);
    __shared__ float red[8];
    float s = v.x + v.y + v.z + v.w;
#pragma unroll
    for (int o = 16; o; o >>= 1) s += __shfl_xor_sync(0xffffffffu, s, o);
    if ((tid & 31) == 0) red[tid >> 5] = s;
    __syncthreads();
    if (tid == 0) {
        float t = 0;
#pragma unroll
        for (int i = 0; i < 8; i++) t += red[i];
        red[0] = t;
    }
    __syncthreads();
    const float mean = red[0] / (float)D;
    __syncthreads();
    float dx = v.x - mean, dy = v.y - mean, dz = v.z - mean, dw = v.w - mean;
    float s2 = dx * dx + dy * dy + dz * dz + dw * dw;
#pragma unroll
    for (int o = 16; o; o >>= 1) s2 += __shfl_xor_sync(0xffffffffu, s2, o);
    if ((tid & 31) == 0) red[tid >> 5] = s2;
    __syncthreads();
    if (tid == 0) {
        float t = 0;
#pragma unroll
        for (int i = 0; i < 8; i++) t += red[i];
        red[0] = t;
    }
    __syncthreads();
    const float var = red[0] / (float)D;
    const float rstd = rsqrtf(var + 1e-5f);
    float4 g = *(const float4*)(gamma + tid * 4);
    float4 bb = *(const float4*)(beta + tid * 4);
    float4 u = *(const float4*)(g_H4 + (size_t)row * D4 + tid * 4);
    float z0 = ((v.x - mean) * rstd * g.x + bb.x) * u.x;
    float z1 = ((v.y - mean) * rstd * g.y + bb.y) * u.y;
    float z2 = ((v.z - mean) * rstd * g.z + bb.z) * u.z;
    float z3 = ((v.w - mean) * rstd * g.w + bb.w) * u.w;
    uint32_t* zh = (uint32_t*)(g_zh + (size_t)row * D + tid * 4);
    uint32_t* zl = (uint32_t*)(g_zl + (size_t)row * D + tid * 4);
    zh[0] = pk2(z0, z1);
    zh[1] = pk2(z2, z3);
    zl[0] = pk2(rlo(z0), rlo(z1));
    zl[1] = pk2(rlo(z2), rlo(z3));
}

// ---------------------------------------------------------------------------
extern "C" void kernel_launch(void* const* d_in, const int* in_sizes, int n_in,
                              void* d_out, int out_size) {
    (void)n_in;
    (void)out_size;
    const float* x = (const float*)d_in[0];
    const float* amask = (const float*)d_in[1];
    const void* kpm = d_in[2];
    const float* W_in = (const float*)d_in[3];
    const float* b_in = (const float*)d_in[4];
    const float* W_out = (const float*)d_in[5];
    const float* b_out = (const float*)d_in[6];
    const float* gamma = (const float*)d_in[7];
    const float* beta = (const float*)d_in[8];
    const float* rab = (const float*)d_in[9];
    float* out = (float*)d_out;

    const int D = in_sizes[7];
    int T = 1;
    while ((long long)T * T < (long long)in_sizes[1]) T++;
    const int B = in_sizes[0] / (T * D);
    const int H = in_sizes[9] / NBUCKETS;
    const int BT = B * T;
    const float alpha = rsqrtf((float)(D / H));

    float* pH4;
    cudaGetSymbolAddress((void**)&pH4, g_H4);
    __nv_bfloat16 *pxh, *pxl, *pwih, *pwil, *pwoh, *pwol, *pzh, *pzl;
    cudaGetSymbolAddress((void**)&pxh, g_xh);
    cudaGetSymbolAddress((void**)&pxl, g_xl);
    cudaGetSymbolAddress((void**)&pwih, g_wih);
    cudaGetSymbolAddress((void**)&pwil, g_wil);
    cudaGetSymbolAddress((void**)&pwoh, g_woh);
    cudaGetSymbolAddress((void**)&pwol, g_wol);
    cudaGetSymbolAddress((void**)&pzh, g_zh);
    cudaGetSymbolAddress((void**)&pzl, g_zl);

    cudaFuncSetAttribute(attn_kernel, cudaFuncAttributeMaxDynamicSharedMemorySize, ATTN_SMEM);
    cudaFuncSetAttribute(hgemm_kernel, cudaFuncAttributeMaxDynamicSharedMemorySize, GEMM_SMEM);

    split_kernel<<<(BT * D / 4 + 255) / 256, 256>>>(x, pxh, pxl, BT * D);
    split_kernel<<<(4 * D * D / 4 + 255) / 256, 256>>>(W_in, pwih, pwil, 4 * D * D);
    split_kernel<<<(D * D / 4 + 255) / 256, 256>>>(W_out, pwoh, pwol, D * D);

    prep_kernel<<<9, 256>>>(kpm, rab, B, T, H);
    denom_kernel<<<dim3(T, B), 256>>>(amask, B, T);
    hgemm_kernel<<<dim3(4 * D / 128, BT / 128), 256, GEMM_SMEM>>>(
        pxh, pxl, pwih, pwil, b_in, nullptr, pH4, BT, 4 * D, D, 0);
    convert_vt_kernel<<<dim3(T / 64, H, B), 256>>>(T, H, D);
    attn_kernel<<<dim3(T / 64, H, B), 256, ATTN_SMEM>>>(amask, T, H, D, alpha);
    ln_kernel<<<BT, D / 4>>>(gamma, beta, D);
    hgemm_kernel<<<dim3(D / 128, BT / 128), 256, GEMM_SMEM>>>(
        pzh, pzl, pwoh, pwol, b_out, x, out, BT, D, D, 1);
}

// round 16
// speedup vs baseline: 2.5131x; 1.1100x over previous
#include <cuda_runtime.h>
#include <cuda_bf16.h>
#include <cstdint>
#include <math.h>

// ---------------------------------------------------------------------------
// HSTU layer. Dense GEMMs + attention on warp-level mma.sync bf16 (hi/lo
// split -> ~fp32 accuracy). ldmatrix fragment loads. Fast-path sigmoid.
// ---------------------------------------------------------------------------

#define MAXB 2
#define MAXT 1024
#define MAXD 1024
#define MAXH 16
#define NBUCKETS 32

__device__ float g_H4[(size_t)MAXB * MAXT * 4 * MAXD];
__device__ float g_AV[(size_t)MAXB * MAXT * MAXD];
__device__ float g_denom[MAXB * MAXT];          // stores 1/denom
__device__ unsigned char g_valid[MAXB * MAXT];
__device__ float g_rabd[MAXH * MAXT];

__device__ __nv_bfloat16 g_xh[(size_t)MAXB * MAXT * MAXD];
__device__ __nv_bfloat16 g_xl[(size_t)MAXB * MAXT * MAXD];
__device__ __nv_bfloat16 g_wih[(size_t)4 * MAXD * MAXD];
__device__ __nv_bfloat16 g_wil[(size_t)4 * MAXD * MAXD];
__device__ __nv_bfloat16 g_woh[(size_t)MAXD * MAXD];
__device__ __nv_bfloat16 g_wol[(size_t)MAXD * MAXD];
__device__ __nv_bfloat16 g_zh[(size_t)MAXB * MAXT * MAXD];
__device__ __nv_bfloat16 g_zl[(size_t)MAXB * MAXT * MAXD];
__device__ __nv_bfloat16 g_qh[(size_t)MAXB * MAXT * MAXD];
__device__ __nv_bfloat16 g_ql[(size_t)MAXB * MAXT * MAXD];
__device__ __nv_bfloat16 g_kh[(size_t)MAXB * MAXT * MAXD];
__device__ __nv_bfloat16 g_kl[(size_t)MAXB * MAXT * MAXD];
__device__ __nv_bfloat16 g_vth[(size_t)MAXB * MAXH * 64 * MAXT];
__device__ __nv_bfloat16 g_vtl[(size_t)MAXB * MAXH * 64 * MAXT];

// ======================= helpers ===========================================

__device__ __forceinline__ uint32_t smem_to_u32(const void* smem_ptr) {
    uint32_t addr;
    asm("{ .reg .u64 tmp; cvta.to.shared.u64 tmp, %1; cvt.u32.u64 %0, tmp; }"
        : "=r"(addr) : "l"(smem_ptr));
    return addr;
}

#define CP_ASYNC16(dst, src) \
    asm volatile("cp.async.cg.shared.global [%0], [%1], 16;" :: "r"(dst), "l"(src) : "memory")
#define CP_ASYNC_COMMIT() asm volatile("cp.async.commit_group;" ::: "memory")
#define CP_ASYNC_WAIT0() asm volatile("cp.async.wait_group 0;" ::: "memory")
#define CP_ASYNC_WAIT1() asm volatile("cp.async.wait_group 1;" ::: "memory")

__device__ __forceinline__ void mma_bf16(float* c, const uint32_t* a, const uint32_t* b) {
    asm volatile(
        "mma.sync.aligned.m16n8k16.row.col.f32.bf16.bf16.f32 "
        "{%0,%1,%2,%3}, {%4,%5,%6,%7}, {%8,%9}, {%0,%1,%2,%3};"
        : "+f"(c[0]), "+f"(c[1]), "+f"(c[2]), "+f"(c[3])
        : "r"(a[0]), "r"(a[1]), "r"(a[2]), "r"(a[3]), "r"(b[0]), "r"(b[1]));
}

__device__ __forceinline__ void ldsm4(uint32_t* r, uint32_t addr) {
    asm volatile("ldmatrix.sync.aligned.m8n8.x4.shared.b16 {%0,%1,%2,%3}, [%4];"
        : "=r"(r[0]), "=r"(r[1]), "=r"(r[2]), "=r"(r[3]) : "r"(addr));
}

__device__ __forceinline__ uint32_t pk2(float x, float y) {
    unsigned short lo = __bfloat16_as_ushort(__float2bfloat16(x));
    unsigned short hi = __bfloat16_as_ushort(__float2bfloat16(y));
    return (uint32_t)lo | ((uint32_t)hi << 16);
}
__device__ __forceinline__ float rlo(float x) {
    return x - __bfloat162float(__float2bfloat16(x));
}
// fast silu: x * sigmoid(x), 2 MUFU
__device__ __forceinline__ float fsilu(float x) {
    return __fdividef(x, 1.0f + __expf(-x));
}

// ======================= split fp32 -> bf16 hi/lo ===========================
__global__ void split_kernel(const float* __restrict__ src, __nv_bfloat16* __restrict__ hi,
                             __nv_bfloat16* __restrict__ lo, int n) {
    int i = blockIdx.x * blockDim.x + threadIdx.x;
    if (i >= n / 4) return;
    float4 v = ((const float4*)src)[i];
    float a0 = v.x;
    float a1 = v.y;
    float a2 = v.z;
    float a3 = v.w;
    __nv_bfloat16 h0 = __float2bfloat16(a0);
    __nv_bfloat16 h1 = __float2bfloat16(a1);
    __nv_bfloat16 h2 = __float2bfloat16(a2);
    __nv_bfloat16 h3 = __float2bfloat16(a3);
    hi[4 * i + 0] = h0;
    hi[4 * i + 1] = h1;
    hi[4 * i + 2] = h2;
    hi[4 * i + 3] = h3;
    lo[4 * i + 0] = __float2bfloat16(a0 - __bfloat162float(h0));
    lo[4 * i + 1] = __float2bfloat16(a1 - __bfloat162float(h1));
    lo[4 * i + 2] = __float2bfloat16(a2 - __bfloat162float(h2));
    lo[4 * i + 3] = __float2bfloat16(a3 - __bfloat162float(h3));
}

// ======================= prep (parallel: block0 valid, rest rabd) ==========
__global__ void prep_kernel(const void* __restrict__ kpm, const float* __restrict__ rab_emb,
                            int B, int T, int H) {
    if (blockIdx.x == 0) {
        const int M = B * T;
        __shared__ int oddbyte;
        if (threadIdx.x == 0) oddbyte = 0;
        __syncthreads();
        const unsigned char* bp = (const unsigned char*)kpm;
        int local = 0;
        for (int i = threadIdx.x; i < M; i += blockDim.x)
            if (bp[i] != 0 && (i & 3) != 0) local = 1;
        if (local) atomicOr(&oddbyte, 1);
        __syncthreads();
        const int isByte = oddbyte;
        const int* ip = (const int*)kpm;
        for (int i = threadIdx.x; i < M; i += blockDim.x) {
            int pad = isByte ? (bp[i] != 0) : (ip[i] != 0);
            g_valid[i] = pad ? 0 : 1;
        }
    } else {
        const int nb = gridDim.x - 1;
        const int total = H * T;
        const int per = (total + nb - 1) / nb;
        const int start = (blockIdx.x - 1) * per;
        const int end = (start + per < total) ? start + per : total;
        for (int i = start + threadIdx.x; i < end; i += blockDim.x) {
            int h = i / T;
            int n = i - h * T;
            int bkt;
            if (n < 16) {
                bkt = n;
            } else {
                float v = logf((float)n / 16.0f + 1e-6f) / 2.0794415416798357f * 16.0f;
                int lg = 16 + (int)v;
                bkt = lg < (NBUCKETS - 1) ? lg : (NBUCKETS - 1);
            }
            g_rabd[i] = rab_emb[bkt * H + h];
        }
    }
}

// ======================= denom (stores reciprocal) =========================
__global__ void denom_kernel(const float* __restrict__ amask, int B, int T) {
    const int t = blockIdx.x;
    const int b = blockIdx.y;
    int cnt = 0;
    for (int s = threadIdx.x; s < T; s += blockDim.x)
        cnt += (amask[(size_t)t * T + s] == 0.0f && g_valid[b * T + s]) ? 1 : 0;
#pragma unroll
    for (int o = 16; o; o >>= 1) cnt += __shfl_xor_sync(0xffffffffu, cnt, o);
    __shared__ int red[8];
    if ((threadIdx.x & 31) == 0) red[threadIdx.x >> 5] = cnt;
    __syncthreads();
    if (threadIdx.x == 0) {
        int tot = 0;
#pragma unroll
        for (int i = 0; i < 8; i++) tot += red[i];
        if (tot < 1) tot = 1;
        g_denom[b * T + t] = 1.0f / (float)tot;
    }
}

// ======================= HMMA GEMM =========================================
#define GS 40
#define TILE_B (128 * GS * 2)
#define OFF_AH 0
#define OFF_AL (TILE_B)
#define OFF_BH (2 * TILE_B)
#define OFF_BL (3 * TILE_B)
#define STAGE_B (4 * TILE_B)
#define GEMM_SMEM (2 * STAGE_B)

__global__ __launch_bounds__(256) void hgemm_kernel(
    const __nv_bfloat16* __restrict__ Ah, const __nv_bfloat16* __restrict__ Al,
    const __nv_bfloat16* __restrict__ Bh, const __nv_bfloat16* __restrict__ Bl,
    const float* __restrict__ bias, const float* __restrict__ resid, float* __restrict__ C,
    int M, int N, int K, int mode) {
    extern __shared__ char dynsmem[];
    const uint32_t sbase = smem_to_u32(dynsmem);
    const int tid = threadIdx.x;
    const int wid = tid >> 5;
    const int lane = tid & 31;
    const int wm = wid & 3;
    const int wn = wid >> 2;
    const int m0 = blockIdx.y * 128;
    const int n0 = blockIdx.x * 128;

    uint32_t adst[2];
    const __nv_bfloat16* aH[2];
    const __nv_bfloat16* aL[2];
    const __nv_bfloat16* bH[2];
    const __nv_bfloat16* bL[2];
#pragma unroll
    for (int i = 0; i < 2; i++) {
        int u = tid + 256 * i;
        int row = u >> 2;
        int un = u & 3;
        adst[i] = (uint32_t)(row * (GS * 2) + un * 16);
        aH[i] = Ah + (size_t)(m0 + row) * K + un * 8;
        aL[i] = Al + (size_t)(m0 + row) * K + un * 8;
        bH[i] = Bh + (size_t)(n0 + row) * K + un * 8;
        bL[i] = Bl + (size_t)(n0 + row) * K + un * 8;
    }

#define ISSUE_LOADS(ch, st)                                      \
    do {                                                         \
        uint32_t _sb = sbase + (uint32_t)((st) * STAGE_B);       \
        int _k0 = (ch) * 32;                                     \
        _Pragma("unroll") for (int _i = 0; _i < 2; _i++) {       \
            CP_ASYNC16(_sb + OFF_AH + adst[_i], aH[_i] + _k0);   \
            CP_ASYNC16(_sb + OFF_AL + adst[_i], aL[_i] + _k0);   \
            CP_ASYNC16(_sb + OFF_BH + adst[_i], bH[_i] + _k0);   \
            CP_ASYNC16(_sb + OFF_BL + adst[_i], bL[_i] + _k0);   \
        }                                                        \
        CP_ASYNC_COMMIT();                                       \
    } while (0)

    float acc[2][8][4];
#pragma unroll
    for (int mi = 0; mi < 2; mi++)
#pragma unroll
        for (int ni = 0; ni < 8; ni++)
#pragma unroll
            for (int j = 0; j < 4; j++) acc[mi][ni][j] = 0.0f;

    const int r = lane >> 2;
    const int kc = (lane & 3) * 2;
    const int row16 = (lane & 7) + ((lane >> 3) & 1) * 8;
    const int col8 = (lane >> 4) * 8;
    const uint32_t a_loff = (uint32_t)((row16 * GS + col8) * 2);
    const int bsel = lane >> 3;
    const uint32_t b_loff = (uint32_t)((((bsel >> 1) * 8 + (lane & 7)) * GS + (bsel & 1) * 8) * 2);

    const int NCH = K >> 5;
    ISSUE_LOADS(0, 0);
    for (int ch = 0; ch < NCH; ch++) {
        if (ch + 1 < NCH) {
            ISSUE_LOADS(ch + 1, (ch + 1) & 1);
            CP_ASYNC_WAIT1();
        } else {
            CP_ASYNC_WAIT0();
        }
        __syncthreads();

        const uint32_t stg = sbase + (uint32_t)((ch & 1) * STAGE_B);
        const uint32_t uAh = stg + OFF_AH;
        const uint32_t uAl = stg + OFF_AL;
        const uint32_t uBh = stg + OFF_BH;
        const uint32_t uBl = stg + OFF_BL;

#pragma unroll
        for (int ks = 0; ks < 2; ks++) {
            const int kb = ks * 16;
            uint32_t afh[2][4], afl[2][4];
#pragma unroll
            for (int mi = 0; mi < 2; mi++) {
                const uint32_t ab = (uint32_t)(((wm * 32 + mi * 16) * GS + kb) * 2) + a_loff;
                ldsm4(afh[mi], uAh + ab);
                ldsm4(afl[mi], uAl + ab);
            }
            uint32_t bfh[8][2], bfl[8][2];
#pragma unroll
            for (int nip = 0; nip < 4; nip++) {
                const uint32_t bb = (uint32_t)(((wn * 64 + nip * 16) * GS + kb) * 2) + b_loff;
                uint32_t t4[4];
                ldsm4(t4, uBh + bb);
                bfh[2 * nip][0] = t4[0];
                bfh[2 * nip][1] = t4[1];
                bfh[2 * nip + 1][0] = t4[2];
                bfh[2 * nip + 1][1] = t4[3];
                ldsm4(t4, uBl + bb);
                bfl[2 * nip][0] = t4[0];
                bfl[2 * nip][1] = t4[1];
                bfl[2 * nip + 1][0] = t4[2];
                bfl[2 * nip + 1][1] = t4[3];
            }
#pragma unroll
            for (int mi = 0; mi < 2; mi++)
#pragma unroll
                for (int ni = 0; ni < 8; ni++) {
                    mma_bf16(acc[mi][ni], afh[mi], bfh[ni]);
                    mma_bf16(acc[mi][ni], afh[mi], bfl[ni]);
                    mma_bf16(acc[mi][ni], afl[mi], bfh[ni]);
                }
        }
        __syncthreads();
    }

    const int Dq = N >> 2;
#pragma unroll
    for (int mi = 0; mi < 2; mi++) {
        const int r0 = m0 + wm * 32 + mi * 16 + r;
        const int r1 = r0 + 8;
#pragma unroll
        for (int ni = 0; ni < 8; ni++) {
            const int c0 = n0 + wn * 64 + ni * 8 + kc;
            float2 bv = *(const float2*)(bias + c0);
            float o0 = acc[mi][ni][0] + bv.x;
            float o1 = acc[mi][ni][1] + bv.y;
            float o2 = acc[mi][ni][2] + bv.x;
            float o3 = acc[mi][ni][3] + bv.y;
            if (mode == 0) {
                o0 = fsilu(o0);
                o1 = fsilu(o1);
                o2 = fsilu(o2);
                o3 = fsilu(o3);
                const int region = c0 / Dq;
                if (region >= 2) {
                    __nv_bfloat16* oh = (region == 2) ? g_qh : g_kh;
                    __nv_bfloat16* ol = (region == 2) ? g_ql : g_kl;
                    const int cc = c0 - region * Dq;
                    *(uint32_t*)&oh[(size_t)r0 * Dq + cc] = pk2(o0, o1);
                    *(uint32_t*)&ol[(size_t)r0 * Dq + cc] = pk2(rlo(o0), rlo(o1));
                    *(uint32_t*)&oh[(size_t)r1 * Dq + cc] = pk2(o2, o3);
                    *(uint32_t*)&ol[(size_t)r1 * Dq + cc] = pk2(rlo(o2), rlo(o3));
                    continue;
                }
            } else {
                float2 rv0 = *(const float2*)(resid + (size_t)r0 * N + c0);
                float2 rv1 = *(const float2*)(resid + (size_t)r1 * N + c0);
                o0 += rv0.x;
                o1 += rv0.y;
                o2 += rv1.x;
                o3 += rv1.y;
            }
            float2 w0;
            w0.x = o0;
            w0.y = o1;
            float2 w1;
            w1.x = o2;
            w1.y = o3;
            *(float2*)(C + (size_t)r0 * N + c0) = w0;
            *(float2*)(C + (size_t)r1 * N + c0) = w1;
        }
    }
}

// ======================= V transpose to [b][h][d][T] bf16 hi/lo ============
__global__ __launch_bounds__(256) void convert_vt_kernel(int T, int H, int D) {
    __shared__ float tr[64][65];
    const int s0 = blockIdx.x * 64;
    const int h = blockIdx.y;
    const int b = blockIdx.z;
    const int tid = threadIdx.x;
    const int D4 = 4 * D;
#pragma unroll
    for (int rr = 0; rr < 4; rr++) {
        int idx = rr * 256 + tid;
        int s = idx >> 4;
        int dg = (idx & 15) * 4;
        float4 v = *(const float4*)(g_H4 + (size_t)(b * T + s0 + s) * D4 + D + h * 64 + dg);
        tr[dg + 0][s] = v.x;
        tr[dg + 1][s] = v.y;
        tr[dg + 2][s] = v.z;
        tr[dg + 3][s] = v.w;
    }
    __syncthreads();
    const int d = tid >> 2;
    const int sg = (tid & 3) * 16;
    uint32_t hbuf[8], lbuf[8];
#pragma unroll
    for (int j = 0; j < 8; j++) {
        float f0 = tr[d][sg + 2 * j];
        float f1 = tr[d][sg + 2 * j + 1];
        hbuf[j] = pk2(f0, f1);
        lbuf[j] = pk2(rlo(f0), rlo(f1));
    }
    size_t base = ((size_t)(b * H + h) * 64 + d) * T + s0 + sg;
    *(uint4*)&g_vth[base] = *(uint4*)hbuf;
    *(uint4*)&g_vth[base + 8] = *(uint4*)(hbuf + 4);
    *(uint4*)&g_vtl[base] = *(uint4*)lbuf;
    *(uint4*)&g_vtl[base + 8] = *(uint4*)(lbuf + 4);
}

// ======================= HMMA attention ====================================
#define AST 72
#define ATB (64 * AST * 2)
#define AQH 0
#define AQL (ATB)
#define APH (2 * ATB)
#define APL (3 * ATB)
#define ASTG (4 * ATB)
#define SKH 0
#define SKL (ATB)
#define SVH (2 * ATB)
#define SVL (3 * ATB)
#define ASTGSZ (4 * ATB)
#define ATTN_SMEM (4 * ATB + 2 * ASTGSZ)

__global__ __launch_bounds__(256) void attn_kernel(
    const float* __restrict__ amask, int T, int H, int D, float alpha) {
    extern __shared__ char smc[];
    __nv_bfloat16* Qh = (__nv_bfloat16*)(smc + AQH);
    __nv_bfloat16* Ql = (__nv_bfloat16*)(smc + AQL);
    __nv_bfloat16* Ph = (__nv_bfloat16*)(smc + APH);
    __nv_bfloat16* Pl = (__nv_bfloat16*)(smc + APL);
    const uint32_t sb = smem_to_u32(smc);

    const int tid = threadIdx.x;
    const int wid = tid >> 5;
    const int lane = tid & 31;
    const int wm = wid & 3;
    const int wn = wid >> 2;
    const int r = lane >> 2;
    const int kc = (lane & 3) * 2;
    const int qt = blockIdx.x;
    const int head = blockIdx.y;
    const int b = blockIdx.z;
    const int q0 = qt * 64;

    const int row16 = (lane & 7) + ((lane >> 3) & 1) * 8;
    const int col8 = (lane >> 4) * 8;
    const uint32_t a_loff = (uint32_t)((row16 * AST + col8) * 2);
    const int bsel = lane >> 3;
    const uint32_t b_loff =
        (uint32_t)((((bsel >> 1) * 8 + (lane & 7)) * AST + (bsel & 1) * 8) * 2);

#pragma unroll
    for (int i = 0; i < 2; i++) {
        int c = tid + 256 * i;
        int q = c >> 3;
        int o = (c & 7) * 8;
        *(uint4*)&Qh[q * AST + o] =
            *(const uint4*)(g_qh + (size_t)(b * T + q0 + q) * D + head * 64 + o);
        *(uint4*)&Ql[q * AST + o] =
            *(const uint4*)(g_ql + (size_t)(b * T + q0 + q) * D + head * 64 + o);
    }

    uint32_t dstoff[2];
    const __nv_bfloat16* ksrcH[2];
    const __nv_bfloat16* ksrcL[2];
    const __nv_bfloat16* vsrcH[2];
    const __nv_bfloat16* vsrcL[2];
#pragma unroll
    for (int i = 0; i < 2; i++) {
        int c = tid + 256 * i;
        int row = c >> 3;
        int o8 = (c & 7) * 8;
        dstoff[i] = (uint32_t)(row * (AST * 2) + o8 * 2);
        ksrcH[i] = g_kh + (size_t)(b * T + row) * D + head * 64 + o8;
        ksrcL[i] = g_kl + (size_t)(b * T + row) * D + head * 64 + o8;
        vsrcH[i] = g_vth + ((size_t)(b * H + head) * 64 + row) * T + o8;
        vsrcL[i] = g_vtl + ((size_t)(b * H + head) * 64 + row) * T + o8;
    }

#define AISSUE(st)                                                          \
    do {                                                                    \
        uint32_t _sb2 = sb + ASTG + ((st) & 1) * ASTGSZ;                    \
        size_t _ko = (size_t)(st) * 64 * D;                                 \
        int _vo = (st) * 64;                                                \
        _Pragma("unroll") for (int _i = 0; _i < 2; _i++) {                  \
            CP_ASYNC16(_sb2 + SKH + dstoff[_i], ksrcH[_i] + _ko);           \
            CP_ASYNC16(_sb2 + SKL + dstoff[_i], ksrcL[_i] + _ko);           \
            CP_ASYNC16(_sb2 + SVH + dstoff[_i], vsrcH[_i] + _vo);           \
            CP_ASYNC16(_sb2 + SVL + dstoff[_i], vsrcL[_i] + _vo);           \
        }                                                                   \
        CP_ASYNC_COMMIT();                                                  \
    } while (0)

    float oacc[4][4];
#pragma unroll
    for (int i = 0; i < 4; i++)
#pragma unroll
        for (int j = 0; j < 4; j++) oacc[i][j] = 0.0f;

    const int t0 = q0 + wm * 16 + r;
    const int t1 = t0 + 8;
    const float iden0 = g_denom[b * T + t0];   // reciprocal
    const float iden1 = g_denom[b * T + t1];
    const float* rabd = g_rabd + head * T;

    AISSUE(0);
    for (int st = 0; st <= qt; st++) {
        const int s0 = st * 64;
        __syncthreads();
        if (st < qt) {
            AISSUE(st + 1);
            CP_ASYNC_WAIT1();
        } else {
            CP_ASYNC_WAIT0();
        }
        __syncthreads();

        const uint32_t stg = sb + ASTG + (uint32_t)((st & 1) * ASTGSZ);
        const uint32_t uKh = stg + SKH;
        const uint32_t uKl = stg + SKL;
        const uint32_t uVh = stg + SVH;
        const uint32_t uVl = stg + SVL;

        float sacc[4][4];
#pragma unroll
        for (int i = 0; i < 4; i++)
#pragma unroll
            for (int j = 0; j < 4; j++) sacc[i][j] = 0.0f;

#pragma unroll
        for (int ks = 0; ks < 4; ks++) {
            const int kb = ks * 16;
            uint32_t ah[4], al[4];
            const uint32_t ab = (uint32_t)(((wm * 16) * AST + kb) * 2) + a_loff;
            ldsm4(ah, sb + AQH + ab);
            ldsm4(al, sb + AQL + ab);
            uint32_t bh[4][2], bl[4][2];
#pragma unroll
            for (int nip = 0; nip < 2; nip++) {
                const uint32_t bb = (uint32_t)(((wn * 32 + nip * 16) * AST + kb) * 2) + b_loff;
                uint32_t t4[4];
                ldsm4(t4, uKh + bb);
                bh[2 * nip][0] = t4[0];
                bh[2 * nip][1] = t4[1];
                bh[2 * nip + 1][0] = t4[2];
                bh[2 * nip + 1][1] = t4[3];
                ldsm4(t4, uKl + bb);
                bl[2 * nip][0] = t4[0];
                bl[2 * nip][1] = t4[1];
                bl[2 * nip + 1][0] = t4[2];
                bl[2 * nip + 1][1] = t4[3];
            }
#pragma unroll
            for (int nt = 0; nt < 4; nt++) {
                mma_bf16(sacc[nt], ah, bh[nt]);
                mma_bf16(sacc[nt], ah, bl[nt]);
                mma_bf16(sacc[nt], al, bh[nt]);
            }
        }

        // pointwise epilogue -> P (hi/lo) in smem
        const bool diag = (st == qt);
#pragma unroll
        for (int nt = 0; nt < 4; nt++) {
            const int col = wn * 32 + nt * 8 + kc;
            const int sA = s0 + col;
            const int sB = sA + 1;
            float p00 = 0.0f, p01 = 0.0f, p10 = 0.0f, p11 = 0.0f;
            bool okA0 = (g_valid[b * T + sA] != 0);
            bool okB0 = (g_valid[b * T + sB] != 0);
            bool okA1 = okA0;
            bool okB1 = okB0;
            if (diag) {
                if (okA0) okA0 = (amask[(size_t)t0 * T + sA] == 0.0f);
                if (okB0) okB0 = (amask[(size_t)t0 * T + sB] == 0.0f);
                if (okA1) okA1 = (amask[(size_t)t1 * T + sA] == 0.0f);
                if (okB1) okB1 = (amask[(size_t)t1 * T + sB] == 0.0f);
            }
            if (okA0) {
                float xv = sacc[nt][0] * alpha + rabd[t0 - sA];
                p00 = fsilu(xv) * iden0;
            }
            if (okB0) {
                float xv = sacc[nt][1] * alpha + rabd[t0 - sB];
                p01 = fsilu(xv) * iden0;
            }
            if (okA1) {
                float xv = sacc[nt][2] * alpha + rabd[t1 - sA];
                p10 = fsilu(xv) * iden1;
            }
            if (okB1) {
                float xv = sacc[nt][3] * alpha + rabd[t1 - sB];
                p11 = fsilu(xv) * iden1;
            }
            *(uint32_t*)&Ph[(wm * 16 + r) * AST + col] = pk2(p00, p01);
            *(uint32_t*)&Ph[(wm * 16 + r + 8) * AST + col] = pk2(p10, p11);
            *(uint32_t*)&Pl[(wm * 16 + r) * AST + col] = pk2(rlo(p00), rlo(p01));
            *(uint32_t*)&Pl[(wm * 16 + r + 8) * AST + col] = pk2(rlo(p10), rlo(p11));
        }
        __syncthreads();

        // O += P V
#pragma unroll
        for (int ks = 0; ks < 4; ks++) {
            const int kb = ks * 16;
            uint32_t ah[4], al[4];
            const uint32_t ab = (uint32_t)(((wm * 16) * AST + kb) * 2) + a_loff;
            ldsm4(ah, sb + APH + ab);
            ldsm4(al, sb + APL + ab);
            uint32_t bh[4][2], bl[4][2];
#pragma unroll
            for (int nip = 0; nip < 2; nip++) {
                const uint32_t bb = (uint32_t)(((wn * 32 + nip * 16) * AST + kb) * 2) + b_loff;
                uint32_t t4[4];
                ldsm4(t4, uVh + bb);
                bh[2 * nip][0] = t4[0];
                bh[2 * nip][1] = t4[1];
                bh[2 * nip + 1][0] = t4[2];
                bh[2 * nip + 1][1] = t4[3];
                ldsm4(t4, uVl + bb);
                bl[2 * nip][0] = t4[0];
                bl[2 * nip][1] = t4[1];
                bl[2 * nip + 1][0] = t4[2];
                bl[2 * nip + 1][1] = t4[3];
            }
#pragma unroll
            for (int nt = 0; nt < 4; nt++) {
                mma_bf16(oacc[nt], ah, bh[nt]);
                mma_bf16(oacc[nt], ah, bl[nt]);
                mma_bf16(oacc[nt], al, bh[nt]);
            }
        }
    }

#pragma unroll
    for (int nt = 0; nt < 4; nt++) {
        const int d0 = head * 64 + wn * 32 + nt * 8 + kc;
        float2 w0;
        w0.x = oacc[nt][0];
        w0.y = oacc[nt][1];
        float2 w1;
        w1.x = oacc[nt][2];
        w1.y = oacc[nt][3];
        *(float2*)(g_AV + (size_t)(b * T + t0) * D + d0) = w0;
        *(float2*)(g_AV + (size_t)(b * T + t1) * D + d0) = w1;
    }
}

// ======================= LayerNorm * U -> zh/zl ============================
__global__ void ln_kernel(const float* __restrict__ gamma, const float* __restrict__ beta, int D) {
    const int row = blockIdx.x;
    const int tid = threadIdx.x;
    const int D4 = 4 * D;
    float4 v = *(const float4*)(g_AV + (size_t)row * D + tid * 4);
    __shared__ float red[8];
    float s = v.x + v.y + v.z + v.w;
#pragma unroll
    for (int o = 16; o; o >>= 1) s += __shfl_xor_sync(0xffffffffu, s, o);
    if ((tid & 31) == 0) red[tid >> 5] = s;
    __syncthreads();
    if (tid == 0) {
        float t = 0;
#pragma unroll
        for (int i = 0; i < 8; i++) t += red[i];
        red[0] = t;
    }
    __syncthreads();
    const float mean = red[0] / (float)D;
    __syncthreads();
    float dx = v.x - mean, dy = v.y - mean, dz = v.z - mean, dw = v.w - mean;
    float s2 = dx * dx + dy * dy + dz * dz + dw * dw;
#pragma unroll
    for (int o = 16; o; o >>= 1) s2 += __shfl_xor_sync(0xffffffffu, s2, o);
    if ((tid & 31) == 0) red[tid >> 5] = s2;
    __syncthreads();
    if (tid == 0) {
        float t = 0;
#pragma unroll
        for (int i = 0; i < 8; i++) t += red[i];
        red[0] = t;
    }
    __syncthreads();
    const float var = red[0] / (float)D;
    const float rstd = rsqrtf(var + 1e-5f);
    float4 g = *(const float4*)(gamma + tid * 4);
    float4 bb = *(const float4*)(beta + tid * 4);
    float4 u = *(const float4*)(g_H4 + (size_t)row * D4 + tid * 4);
    float z0 = ((v.x - mean) * rstd * g.x + bb.x) * u.x;
    float z1 = ((v.y - mean) * rstd * g.y + bb.y) * u.y;
    float z2 = ((v.z - mean) * rstd * g.z + bb.z) * u.z;
    float z3 = ((v.w - mean) * rstd * g.w + bb.w) * u.w;
    uint32_t* zh = (uint32_t*)(g_zh + (size_t)row * D + tid * 4);
    uint32_t* zl = (uint32_t*)(g_zl + (size_t)row * D + tid * 4);
    zh[0] = pk2(z0, z1);
    zh[1] = pk2(z2, z3);
    zl[0] = pk2(rlo(z0), rlo(z1));
    zl[1] = pk2(rlo(z2), rlo(z3));
}

// ---------------------------------------------------------------------------
extern "C" void kernel_launch(void* const* d_in, const int* in_sizes, int n_in,
                              void* d_out, int out_size) {
    (void)n_in;
    (void)out_size;
    const float* x = (const float*)d_in[0];
    const float* amask = (const float*)d_in[1];
    const void* kpm = d_in[2];
    const float* W_in = (const float*)d_in[3];
    const float* b_in = (const float*)d_in[4];
    const float* W_out = (const float*)d_in[5];
    const float* b_out = (const float*)d_in[6];
    const float* gamma = (const float*)d_in[7];
    const float* beta = (const float*)d_in[8];
    const float* rab = (const float*)d_in[9];
    float* out = (float*)d_out;

    const int D = in_sizes[7];
    int T = 1;
    while ((long long)T * T < (long long)in_sizes[1]) T++;
    const int B = in_sizes[0] / (T * D);
    const int H = in_sizes[9] / NBUCKETS;
    const int BT = B * T;
    const float alpha = rsqrtf((float)(D / H));

    float* pH4;
    cudaGetSymbolAddress((void**)&pH4, g_H4);
    __nv_bfloat16 *pxh, *pxl, *pwih, *pwil, *pwoh, *pwol, *pzh, *pzl;
    cudaGetSymbolAddress((void**)&pxh, g_xh);
    cudaGetSymbolAddress((void**)&pxl, g_xl);
    cudaGetSymbolAddress((void**)&pwih, g_wih);
    cudaGetSymbolAddress((void**)&pwil, g_wil);
    cudaGetSymbolAddress((void**)&pwoh, g_woh);
    cudaGetSymbolAddress((void**)&pwol, g_wol);
    cudaGetSymbolAddress((void**)&pzh, g_zh);
    cudaGetSymbolAddress((void**)&pzl, g_zl);

    cudaFuncSetAttribute(attn_kernel, cudaFuncAttributeMaxDynamicSharedMemorySize, ATTN_SMEM);
    cudaFuncSetAttribute(hgemm_kernel, cudaFuncAttributeMaxDynamicSharedMemorySize, GEMM_SMEM);

    split_kernel<<<(BT * D / 4 + 255) / 256, 256>>>(x, pxh, pxl, BT * D);
    split_kernel<<<(4 * D * D / 4 + 255) / 256, 256>>>(W_in, pwih, pwil, 4 * D * D);
    split_kernel<<<(D * D / 4 + 255) / 256, 256>>>(W_out, pwoh, pwol, D * D);

    prep_kernel<<<9, 256>>>(kpm, rab, B, T, H);
    denom_kernel<<<dim3(T, B), 256>>>(amask, B, T);
    hgemm_kernel<<<dim3(4 * D / 128, BT / 128), 256, GEMM_SMEM>>>(
        pxh, pxl, pwih, pwil, b_in, nullptr, pH4, BT, 4 * D, D, 0);
    convert_vt_kernel<<<dim3(T / 64, H, B), 256>>>(T, H, D);
    attn_kernel<<<dim3(T / 64, H, B), 256, ATTN_SMEM>>>(amask, T, H, D, alpha);
    ln_kernel<<<BT, D / 4>>>(gamma, beta, D);
    hgemm_kernel<<<dim3(D / 128, BT / 128), 256, GEMM_SMEM>>>(
        pzh, pzl, pwoh, pwol, b_out, x, out, BT, D, D, 1);
}

// round 17
// speedup vs baseline: 2.5360x; 1.0091x over previous
#include <cuda_runtime.h>
#include <cuda_bf16.h>
#include <cstdint>
#include <math.h>

// ---------------------------------------------------------------------------
// HSTU layer. Dense GEMMs + attention on warp-level mma.sync bf16 (hi/lo
// split -> ~fp32 accuracy). ldmatrix fragment loads. Fast-path sigmoid.
// R17: __launch_bounds__(256,2) for 2 CTA/SM residency; reversed qt order
// for causal load balance.
// ---------------------------------------------------------------------------

#define MAXB 2
#define MAXT 1024
#define MAXD 1024
#define MAXH 16
#define NBUCKETS 32

__device__ float g_H4[(size_t)MAXB * MAXT * 4 * MAXD];
__device__ float g_AV[(size_t)MAXB * MAXT * MAXD];
__device__ float g_denom[MAXB * MAXT];          // stores 1/denom
__device__ unsigned char g_valid[MAXB * MAXT];
__device__ float g_rabd[MAXH * MAXT];

__device__ __nv_bfloat16 g_xh[(size_t)MAXB * MAXT * MAXD];
__device__ __nv_bfloat16 g_xl[(size_t)MAXB * MAXT * MAXD];
__device__ __nv_bfloat16 g_wih[(size_t)4 * MAXD * MAXD];
__device__ __nv_bfloat16 g_wil[(size_t)4 * MAXD * MAXD];
__device__ __nv_bfloat16 g_woh[(size_t)MAXD * MAXD];
__device__ __nv_bfloat16 g_wol[(size_t)MAXD * MAXD];
__device__ __nv_bfloat16 g_zh[(size_t)MAXB * MAXT * MAXD];
__device__ __nv_bfloat16 g_zl[(size_t)MAXB * MAXT * MAXD];
__device__ __nv_bfloat16 g_qh[(size_t)MAXB * MAXT * MAXD];
__device__ __nv_bfloat16 g_ql[(size_t)MAXB * MAXT * MAXD];
__device__ __nv_bfloat16 g_kh[(size_t)MAXB * MAXT * MAXD];
__device__ __nv_bfloat16 g_kl[(size_t)MAXB * MAXT * MAXD];
__device__ __nv_bfloat16 g_vth[(size_t)MAXB * MAXH * 64 * MAXT];
__device__ __nv_bfloat16 g_vtl[(size_t)MAXB * MAXH * 64 * MAXT];

// ======================= helpers ===========================================

__device__ __forceinline__ uint32_t smem_to_u32(const void* smem_ptr) {
    uint32_t addr;
    asm("{ .reg .u64 tmp; cvta.to.shared.u64 tmp, %1; cvt.u32.u64 %0, tmp; }"
        : "=r"(addr) : "l"(smem_ptr));
    return addr;
}

#define CP_ASYNC16(dst, src) \
    asm volatile("cp.async.cg.shared.global [%0], [%1], 16;" :: "r"(dst), "l"(src) : "memory")
#define CP_ASYNC_COMMIT() asm volatile("cp.async.commit_group;" ::: "memory")
#define CP_ASYNC_WAIT0() asm volatile("cp.async.wait_group 0;" ::: "memory")
#define CP_ASYNC_WAIT1() asm volatile("cp.async.wait_group 1;" ::: "memory")

__device__ __forceinline__ void mma_bf16(float* c, const uint32_t* a, const uint32_t* b) {
    asm volatile(
        "mma.sync.aligned.m16n8k16.row.col.f32.bf16.bf16.f32 "
        "{%0,%1,%2,%3}, {%4,%5,%6,%7}, {%8,%9}, {%0,%1,%2,%3};"
        : "+f"(c[0]), "+f"(c[1]), "+f"(c[2]), "+f"(c[3])
        : "r"(a[0]), "r"(a[1]), "r"(a[2]), "r"(a[3]), "r"(b[0]), "r"(b[1]));
}

__device__ __forceinline__ void ldsm4(uint32_t* r, uint32_t addr) {
    asm volatile("ldmatrix.sync.aligned.m8n8.x4.shared.b16 {%0,%1,%2,%3}, [%4];"
        : "=r"(r[0]), "=r"(r[1]), "=r"(r[2]), "=r"(r[3]) : "r"(addr));
}

__device__ __forceinline__ uint32_t pk2(float x, float y) {
    unsigned short lo = __bfloat16_as_ushort(__float2bfloat16(x));
    unsigned short hi = __bfloat16_as_ushort(__float2bfloat16(y));
    return (uint32_t)lo | ((uint32_t)hi << 16);
}
__device__ __forceinline__ float rlo(float x) {
    return x - __bfloat162float(__float2bfloat16(x));
}
__device__ __forceinline__ float fsilu(float x) {
    return __fdividef(x, 1.0f + __expf(-x));
}

// ======================= split fp32 -> bf16 hi/lo ===========================
__global__ void split_kernel(const float* __restrict__ src, __nv_bfloat16* __restrict__ hi,
                             __nv_bfloat16* __restrict__ lo, int n) {
    int i = blockIdx.x * blockDim.x + threadIdx.x;
    if (i >= n / 4) return;
    float4 v = ((const float4*)src)[i];
    float a0 = v.x;
    float a1 = v.y;
    float a2 = v.z;
    float a3 = v.w;
    __nv_bfloat16 h0 = __float2bfloat16(a0);
    __nv_bfloat16 h1 = __float2bfloat16(a1);
    __nv_bfloat16 h2 = __float2bfloat16(a2);
    __nv_bfloat16 h3 = __float2bfloat16(a3);
    hi[4 * i + 0] = h0;
    hi[4 * i + 1] = h1;
    hi[4 * i + 2] = h2;
    hi[4 * i + 3] = h3;
    lo[4 * i + 0] = __float2bfloat16(a0 - __bfloat162float(h0));
    lo[4 * i + 1] = __float2bfloat16(a1 - __bfloat162float(h1));
    lo[4 * i + 2] = __float2bfloat16(a2 - __bfloat162float(h2));
    lo[4 * i + 3] = __float2bfloat16(a3 - __bfloat162float(h3));
}

// ======================= prep (parallel: block0 valid, rest rabd) ==========
__global__ void prep_kernel(const void* __restrict__ kpm, const float* __restrict__ rab_emb,
                            int B, int T, int H) {
    if (blockIdx.x == 0) {
        const int M = B * T;
        __shared__ int oddbyte;
        if (threadIdx.x == 0) oddbyte = 0;
        __syncthreads();
        const unsigned char* bp = (const unsigned char*)kpm;
        int local = 0;
        for (int i = threadIdx.x; i < M; i += blockDim.x)
            if (bp[i] != 0 && (i & 3) != 0) local = 1;
        if (local) atomicOr(&oddbyte, 1);
        __syncthreads();
        const int isByte = oddbyte;
        const int* ip = (const int*)kpm;
        for (int i = threadIdx.x; i < M; i += blockDim.x) {
            int pad = isByte ? (bp[i] != 0) : (ip[i] != 0);
            g_valid[i] = pad ? 0 : 1;
        }
    } else {
        const int nb = gridDim.x - 1;
        const int total = H * T;
        const int per = (total + nb - 1) / nb;
        const int start = (blockIdx.x - 1) * per;
        const int end = (start + per < total) ? start + per : total;
        for (int i = start + threadIdx.x; i < end; i += blockDim.x) {
            int h = i / T;
            int n = i - h * T;
            int bkt;
            if (n < 16) {
                bkt = n;
            } else {
                float v = logf((float)n / 16.0f + 1e-6f) / 2.0794415416798357f * 16.0f;
                int lg = 16 + (int)v;
                bkt = lg < (NBUCKETS - 1) ? lg : (NBUCKETS - 1);
            }
            g_rabd[i] = rab_emb[bkt * H + h];
        }
    }
}

// ======================= denom (stores reciprocal) =========================
__global__ void denom_kernel(const float* __restrict__ amask, int B, int T) {
    const int t = blockIdx.x;
    const int b = blockIdx.y;
    int cnt = 0;
    for (int s = threadIdx.x; s < T; s += blockDim.x)
        cnt += (amask[(size_t)t * T + s] == 0.0f && g_valid[b * T + s]) ? 1 : 0;
#pragma unroll
    for (int o = 16; o; o >>= 1) cnt += __shfl_xor_sync(0xffffffffu, cnt, o);
    __shared__ int red[8];
    if ((threadIdx.x & 31) == 0) red[threadIdx.x >> 5] = cnt;
    __syncthreads();
    if (threadIdx.x == 0) {
        int tot = 0;
#pragma unroll
        for (int i = 0; i < 8; i++) tot += red[i];
        if (tot < 1) tot = 1;
        g_denom[b * T + t] = 1.0f / (float)tot;
    }
}

// ======================= HMMA GEMM =========================================
#define GS 40
#define TILE_B (128 * GS * 2)
#define OFF_AH 0
#define OFF_AL (TILE_B)
#define OFF_BH (2 * TILE_B)
#define OFF_BL (3 * TILE_B)
#define STAGE_B (4 * TILE_B)
#define GEMM_SMEM (2 * STAGE_B)

__global__ __launch_bounds__(256, 2) void hgemm_kernel(
    const __nv_bfloat16* __restrict__ Ah, const __nv_bfloat16* __restrict__ Al,
    const __nv_bfloat16* __restrict__ Bh, const __nv_bfloat16* __restrict__ Bl,
    const float* __restrict__ bias, const float* __restrict__ resid, float* __restrict__ C,
    int M, int N, int K, int mode) {
    extern __shared__ char dynsmem[];
    const uint32_t sbase = smem_to_u32(dynsmem);
    const int tid = threadIdx.x;
    const int wid = tid >> 5;
    const int lane = tid & 31;
    const int wm = wid & 3;
    const int wn = wid >> 2;
    const int m0 = blockIdx.y * 128;
    const int n0 = blockIdx.x * 128;

    uint32_t adst[2];
    const __nv_bfloat16* aH[2];
    const __nv_bfloat16* aL[2];
    const __nv_bfloat16* bH[2];
    const __nv_bfloat16* bL[2];
#pragma unroll
    for (int i = 0; i < 2; i++) {
        int u = tid + 256 * i;
        int row = u >> 2;
        int un = u & 3;
        adst[i] = (uint32_t)(row * (GS * 2) + un * 16);
        aH[i] = Ah + (size_t)(m0 + row) * K + un * 8;
        aL[i] = Al + (size_t)(m0 + row) * K + un * 8;
        bH[i] = Bh + (size_t)(n0 + row) * K + un * 8;
        bL[i] = Bl + (size_t)(n0 + row) * K + un * 8;
    }

#define ISSUE_LOADS(ch, st)                                      \
    do {                                                         \
        uint32_t _sb = sbase + (uint32_t)((st) * STAGE_B);       \
        int _k0 = (ch) * 32;                                     \
        _Pragma("unroll") for (int _i = 0; _i < 2; _i++) {       \
            CP_ASYNC16(_sb + OFF_AH + adst[_i], aH[_i] + _k0);   \
            CP_ASYNC16(_sb + OFF_AL + adst[_i], aL[_i] + _k0);   \
            CP_ASYNC16(_sb + OFF_BH + adst[_i], bH[_i] + _k0);   \
            CP_ASYNC16(_sb + OFF_BL + adst[_i], bL[_i] + _k0);   \
        }                                                        \
        CP_ASYNC_COMMIT();                                       \
    } while (0)

    float acc[2][8][4];
#pragma unroll
    for (int mi = 0; mi < 2; mi++)
#pragma unroll
        for (int ni = 0; ni < 8; ni++)
#pragma unroll
            for (int j = 0; j < 4; j++) acc[mi][ni][j] = 0.0f;

    const int r = lane >> 2;
    const int kc = (lane & 3) * 2;
    const int row16 = (lane & 7) + ((lane >> 3) & 1) * 8;
    const int col8 = (lane >> 4) * 8;
    const uint32_t a_loff = (uint32_t)((row16 * GS + col8) * 2);
    const int bsel = lane >> 3;
    const uint32_t b_loff = (uint32_t)((((bsel >> 1) * 8 + (lane & 7)) * GS + (bsel & 1) * 8) * 2);

    const int NCH = K >> 5;
    ISSUE_LOADS(0, 0);
    for (int ch = 0; ch < NCH; ch++) {
        if (ch + 1 < NCH) {
            ISSUE_LOADS(ch + 1, (ch + 1) & 1);
            CP_ASYNC_WAIT1();
        } else {
            CP_ASYNC_WAIT0();
        }
        __syncthreads();

        const uint32_t stg = sbase + (uint32_t)((ch & 1) * STAGE_B);
        const uint32_t uAh = stg + OFF_AH;
        const uint32_t uAl = stg + OFF_AL;
        const uint32_t uBh = stg + OFF_BH;
        const uint32_t uBl = stg + OFF_BL;

#pragma unroll
        for (int ks = 0; ks < 2; ks++) {
            const int kb = ks * 16;
            uint32_t afh[2][4], afl[2][4];
#pragma unroll
            for (int mi = 0; mi < 2; mi++) {
                const uint32_t ab = (uint32_t)(((wm * 32 + mi * 16) * GS + kb) * 2) + a_loff;
                ldsm4(afh[mi], uAh + ab);
                ldsm4(afl[mi], uAl + ab);
            }
            uint32_t bfh[8][2], bfl[8][2];
#pragma unroll
            for (int nip = 0; nip < 4; nip++) {
                const uint32_t bb = (uint32_t)(((wn * 64 + nip * 16) * GS + kb) * 2) + b_loff;
                uint32_t t4[4];
                ldsm4(t4, uBh + bb);
                bfh[2 * nip][0] = t4[0];
                bfh[2 * nip][1] = t4[1];
                bfh[2 * nip + 1][0] = t4[2];
                bfh[2 * nip + 1][1] = t4[3];
                ldsm4(t4, uBl + bb);
                bfl[2 * nip][0] = t4[0];
                bfl[2 * nip][1] = t4[1];
                bfl[2 * nip + 1][0] = t4[2];
                bfl[2 * nip + 1][1] = t4[3];
            }
#pragma unroll
            for (int mi = 0; mi < 2; mi++)
#pragma unroll
                for (int ni = 0; ni < 8; ni++) {
                    mma_bf16(acc[mi][ni], afh[mi], bfh[ni]);
                    mma_bf16(acc[mi][ni], afh[mi], bfl[ni]);
                    mma_bf16(acc[mi][ni], afl[mi], bfh[ni]);
                }
        }
        __syncthreads();
    }

    const int Dq = N >> 2;
#pragma unroll
    for (int mi = 0; mi < 2; mi++) {
        const int r0 = m0 + wm * 32 + mi * 16 + r;
        const int r1 = r0 + 8;
#pragma unroll
        for (int ni = 0; ni < 8; ni++) {
            const int c0 = n0 + wn * 64 + ni * 8 + kc;
            float2 bv = *(const float2*)(bias + c0);
            float o0 = acc[mi][ni][0] + bv.x;
            float o1 = acc[mi][ni][1] + bv.y;
            float o2 = acc[mi][ni][2] + bv.x;
            float o3 = acc[mi][ni][3] + bv.y;
            if (mode == 0) {
                o0 = fsilu(o0);
                o1 = fsilu(o1);
                o2 = fsilu(o2);
                o3 = fsilu(o3);
                const int region = c0 / Dq;
                if (region >= 2) {
                    __nv_bfloat16* oh = (region == 2) ? g_qh : g_kh;
                    __nv_bfloat16* ol = (region == 2) ? g_ql : g_kl;
                    const int cc = c0 - region * Dq;
                    *(uint32_t*)&oh[(size_t)r0 * Dq + cc] = pk2(o0, o1);
                    *(uint32_t*)&ol[(size_t)r0 * Dq + cc] = pk2(rlo(o0), rlo(o1));
                    *(uint32_t*)&oh[(size_t)r1 * Dq + cc] = pk2(o2, o3);
                    *(uint32_t*)&ol[(size_t)r1 * Dq + cc] = pk2(rlo(o2), rlo(o3));
                    continue;
                }
            } else {
                float2 rv0 = *(const float2*)(resid + (size_t)r0 * N + c0);
                float2 rv1 = *(const float2*)(resid + (size_t)r1 * N + c0);
                o0 += rv0.x;
                o1 += rv0.y;
                o2 += rv1.x;
                o3 += rv1.y;
            }
            float2 w0;
            w0.x = o0;
            w0.y = o1;
            float2 w1;
            w1.x = o2;
            w1.y = o3;
            *(float2*)(C + (size_t)r0 * N + c0) = w0;
            *(float2*)(C + (size_t)r1 * N + c0) = w1;
        }
    }
}

// ======================= V transpose to [b][h][d][T] bf16 hi/lo ============
__global__ __launch_bounds__(256) void convert_vt_kernel(int T, int H, int D) {
    __shared__ float tr[64][65];
    const int s0 = blockIdx.x * 64;
    const int h = blockIdx.y;
    const int b = blockIdx.z;
    const int tid = threadIdx.x;
    const int D4 = 4 * D;
#pragma unroll
    for (int rr = 0; rr < 4; rr++) {
        int idx = rr * 256 + tid;
        int s = idx >> 4;
        int dg = (idx & 15) * 4;
        float4 v = *(const float4*)(g_H4 + (size_t)(b * T + s0 + s) * D4 + D + h * 64 + dg);
        tr[dg + 0][s] = v.x;
        tr[dg + 1][s] = v.y;
        tr[dg + 2][s] = v.z;
        tr[dg + 3][s] = v.w;
    }
    __syncthreads();
    const int d = tid >> 2;
    const int sg = (tid & 3) * 16;
    uint32_t hbuf[8], lbuf[8];
#pragma unroll
    for (int j = 0; j < 8; j++) {
        float f0 = tr[d][sg + 2 * j];
        float f1 = tr[d][sg + 2 * j + 1];
        hbuf[j] = pk2(f0, f1);
        lbuf[j] = pk2(rlo(f0), rlo(f1));
    }
    size_t base = ((size_t)(b * H + h) * 64 + d) * T + s0 + sg;
    *(uint4*)&g_vth[base] = *(uint4*)hbuf;
    *(uint4*)&g_vth[base + 8] = *(uint4*)(hbuf + 4);
    *(uint4*)&g_vtl[base] = *(uint4*)lbuf;
    *(uint4*)&g_vtl[base + 8] = *(uint4*)(lbuf + 4);
}

// ======================= HMMA attention ====================================
#define AST 72
#define ATB (64 * AST * 2)
#define AQH 0
#define AQL (ATB)
#define APH (2 * ATB)
#define APL (3 * ATB)
#define ASTG (4 * ATB)
#define SKH 0
#define SKL (ATB)
#define SVH (2 * ATB)
#define SVL (3 * ATB)
#define ASTGSZ (4 * ATB)
#define ATTN_SMEM (4 * ATB + 2 * ASTGSZ)

__global__ __launch_bounds__(256, 2) void attn_kernel(
    const float* __restrict__ amask, int T, int H, int D, float alpha) {
    extern __shared__ char smc[];
    __nv_bfloat16* Qh = (__nv_bfloat16*)(smc + AQH);
    __nv_bfloat16* Ql = (__nv_bfloat16*)(smc + AQL);
    __nv_bfloat16* Ph = (__nv_bfloat16*)(smc + APH);
    __nv_bfloat16* Pl = (__nv_bfloat16*)(smc + APL);
    const uint32_t sb = smem_to_u32(smc);

    const int tid = threadIdx.x;
    const int wid = tid >> 5;
    const int lane = tid & 31;
    const int wm = wid & 3;
    const int wn = wid >> 2;
    const int r = lane >> 2;
    const int kc = (lane & 3) * 2;
    // reversed order: heavy (large-qt) blocks scheduled first (LPT balance)
    const int qt = gridDim.x - 1 - blockIdx.x;
    const int head = blockIdx.y;
    const int b = blockIdx.z;
    const int q0 = qt * 64;

    const int row16 = (lane & 7) + ((lane >> 3) & 1) * 8;
    const int col8 = (lane >> 4) * 8;
    const uint32_t a_loff = (uint32_t)((row16 * AST + col8) * 2);
    const int bsel = lane >> 3;
    const uint32_t b_loff =
        (uint32_t)((((bsel >> 1) * 8 + (lane & 7)) * AST + (bsel & 1) * 8) * 2);

#pragma unroll
    for (int i = 0; i < 2; i++) {
        int c = tid + 256 * i;
        int q = c >> 3;
        int o = (c & 7) * 8;
        *(uint4*)&Qh[q * AST + o] =
            *(const uint4*)(g_qh + (size_t)(b * T + q0 + q) * D + head * 64 + o);
        *(uint4*)&Ql[q * AST + o] =
            *(const uint4*)(g_ql + (size_t)(b * T + q0 + q) * D + head * 64 + o);
    }

    uint32_t dstoff[2];
    const __nv_bfloat16* ksrcH[2];
    const __nv_bfloat16* ksrcL[2];
    const __nv_bfloat16* vsrcH[2];
    const __nv_bfloat16* vsrcL[2];
#pragma unroll
    for (int i = 0; i < 2; i++) {
        int c = tid + 256 * i;
        int row = c >> 3;
        int o8 = (c & 7) * 8;
        dstoff[i] = (uint32_t)(row * (AST * 2) + o8 * 2);
        ksrcH[i] = g_kh + (size_t)(b * T + row) * D + head * 64 + o8;
        ksrcL[i] = g_kl + (size_t)(b * T + row) * D + head * 64 + o8;
        vsrcH[i] = g_vth + ((size_t)(b * H + head) * 64 + row) * T + o8;
        vsrcL[i] = g_vtl + ((size_t)(b * H + head) * 64 + row) * T + o8;
    }

#define AISSUE(st)                                                          \
    do {                                                                    \
        uint32_t _sb2 = sb + ASTG + ((st) & 1) * ASTGSZ;                    \
        size_t _ko = (size_t)(st) * 64 * D;                                 \
        int _vo = (st) * 64;                                                \
        _Pragma("unroll") for (int _i = 0; _i < 2; _i++) {                  \
            CP_ASYNC16(_sb2 + SKH + dstoff[_i], ksrcH[_i] + _ko);           \
            CP_ASYNC16(_sb2 + SKL + dstoff[_i], ksrcL[_i] + _ko);           \
            CP_ASYNC16(_sb2 + SVH + dstoff[_i], vsrcH[_i] + _vo);           \
            CP_ASYNC16(_sb2 + SVL + dstoff[_i], vsrcL[_i] + _vo);           \
        }                                                                   \
        CP_ASYNC_COMMIT();                                                  \
    } while (0)

    float oacc[4][4];
#pragma unroll
    for (int i = 0; i < 4; i++)
#pragma unroll
        for (int j = 0; j < 4; j++) oacc[i][j] = 0.0f;

    const int t0 = q0 + wm * 16 + r;
    const int t1 = t0 + 8;
    const float iden0 = g_denom[b * T + t0];
    const float iden1 = g_denom[b * T + t1];
    const float* rabd = g_rabd + head * T;

    AISSUE(0);
    for (int st = 0; st <= qt; st++) {
        const int s0 = st * 64;
        __syncthreads();
        if (st < qt) {
            AISSUE(st + 1);
            CP_ASYNC_WAIT1();
        } else {
            CP_ASYNC_WAIT0();
        }
        __syncthreads();

        const uint32_t stg = sb + ASTG + (uint32_t)((st & 1) * ASTGSZ);
        const uint32_t uKh = stg + SKH;
        const uint32_t uKl = stg + SKL;
        const uint32_t uVh = stg + SVH;
        const uint32_t uVl = stg + SVL;

        float sacc[4][4];
#pragma unroll
        for (int i = 0; i < 4; i++)
#pragma unroll
            for (int j = 0; j < 4; j++) sacc[i][j] = 0.0f;

#pragma unroll
        for (int ks = 0; ks < 4; ks++) {
            const int kb = ks * 16;
            uint32_t ah[4], al[4];
            const uint32_t ab = (uint32_t)(((wm * 16) * AST + kb) * 2) + a_loff;
            ldsm4(ah, sb + AQH + ab);
            ldsm4(al, sb + AQL + ab);
            uint32_t bh[4][2], bl[4][2];
#pragma unroll
            for (int nip = 0; nip < 2; nip++) {
                const uint32_t bb = (uint32_t)(((wn * 32 + nip * 16) * AST + kb) * 2) + b_loff;
                uint32_t t4[4];
                ldsm4(t4, uKh + bb);
                bh[2 * nip][0] = t4[0];
                bh[2 * nip][1] = t4[1];
                bh[2 * nip + 1][0] = t4[2];
                bh[2 * nip + 1][1] = t4[3];
                ldsm4(t4, uKl + bb);
                bl[2 * nip][0] = t4[0];
                bl[2 * nip][1] = t4[1];
                bl[2 * nip + 1][0] = t4[2];
                bl[2 * nip + 1][1] = t4[3];
            }
#pragma unroll
            for (int nt = 0; nt < 4; nt++) {
                mma_bf16(sacc[nt], ah, bh[nt]);
                mma_bf16(sacc[nt], ah, bl[nt]);
                mma_bf16(sacc[nt], al, bh[nt]);
            }
        }

        const bool diag = (st == qt);
#pragma unroll
        for (int nt = 0; nt < 4; nt++) {
            const int col = wn * 32 + nt * 8 + kc;
            const int sA = s0 + col;
            const int sB = sA + 1;
            float p00 = 0.0f, p01 = 0.0f, p10 = 0.0f, p11 = 0.0f;
            bool okA0 = (g_valid[b * T + sA] != 0);
            bool okB0 = (g_valid[b * T + sB] != 0);
            bool okA1 = okA0;
            bool okB1 = okB0;
            if (diag) {
                if (okA0) okA0 = (amask[(size_t)t0 * T + sA] == 0.0f);
                if (okB0) okB0 = (amask[(size_t)t0 * T + sB] == 0.0f);
                if (okA1) okA1 = (amask[(size_t)t1 * T + sA] == 0.0f);
                if (okB1) okB1 = (amask[(size_t)t1 * T + sB] == 0.0f);
            }
            if (okA0) {
                float xv = sacc[nt][0] * alpha + rabd[t0 - sA];
                p00 = fsilu(xv) * iden0;
            }
            if (okB0) {
                float xv = sacc[nt][1] * alpha + rabd[t0 - sB];
                p01 = fsilu(xv) * iden0;
            }
            if (okA1) {
                float xv = sacc[nt][2] * alpha + rabd[t1 - sA];
                p10 = fsilu(xv) * iden1;
            }
            if (okB1) {
                float xv = sacc[nt][3] * alpha + rabd[t1 - sB];
                p11 = fsilu(xv) * iden1;
            }
            *(uint32_t*)&Ph[(wm * 16 + r) * AST + col] = pk2(p00, p01);
            *(uint32_t*)&Ph[(wm * 16 + r + 8) * AST + col] = pk2(p10, p11);
            *(uint32_t*)&Pl[(wm * 16 + r) * AST + col] = pk2(rlo(p00), rlo(p01));
            *(uint32_t*)&Pl[(wm * 16 + r + 8) * AST + col] = pk2(rlo(p10), rlo(p11));
        }
        __syncthreads();

#pragma unroll
        for (int ks = 0; ks < 4; ks++) {
            const int kb = ks * 16;
            uint32_t ah[4], al[4];
            const uint32_t ab = (uint32_t)(((wm * 16) * AST + kb) * 2) + a_loff;
            ldsm4(ah, sb + APH + ab);
            ldsm4(al, sb + APL + ab);
            uint32_t bh[4][2], bl[4][2];
#pragma unroll
            for (int nip = 0; nip < 2; nip++) {
                const uint32_t bb = (uint32_t)(((wn * 32 + nip * 16) * AST + kb) * 2) + b_loff;
                uint32_t t4[4];
                ldsm4(t4, uVh + bb);
                bh[2 * nip][0] = t4[0];
                bh[2 * nip][1] = t4[1];
                bh[2 * nip + 1][0] = t4[2];
                bh[2 * nip + 1][1] = t4[3];
                ldsm4(t4, uVl + bb);
                bl[2 * nip][0] = t4[0];
                bl[2 * nip][1] = t4[1];
                bl[2 * nip + 1][0] = t4[2];
                bl[2 * nip + 1][1] = t4[3];
            }
#pragma unroll
            for (int nt = 0; nt < 4; nt++) {
                mma_bf16(oacc[nt], ah, bh[nt]);
                mma_bf16(oacc[nt], ah, bl[nt]);
                mma_bf16(oacc[nt], al, bh[nt]);
            }
        }
    }

#pragma unroll
    for (int nt = 0; nt < 4; nt++) {
        const int d0 = head * 64 + wn * 32 + nt * 8 + kc;
        float2 w0;
        w0.x = oacc[nt][0];
        w0.y = oacc[nt][1];
        float2 w1;
        w1.x = oacc[nt][2];
        w1.y = oacc[nt][3];
        *(float2*)(g_AV + (size_t)(b * T + t0) * D + d0) = w0;
        *(float2*)(g_AV + (size_t)(b * T + t1) * D + d0) = w1;
    }
}

// ======================= LayerNorm * U -> zh/zl ============================
__global__ void ln_kernel(const float* __restrict__ gamma, const float* __restrict__ beta, int D) {
    const int row = blockIdx.x;
    const int tid = threadIdx.x;
    const int D4 = 4 * D;
    float4 v = *(const float4*)(g_AV + (size_t)row * D + tid * 4);
    __shared__ float red[8];
    float s = v.x + v.y + v.z + v.w;
#pragma unroll
    for (int o = 16; o; o >>= 1) s += __shfl_xor_sync(0xffffffffu, s, o);
    if ((tid & 31) == 0) red[tid >> 5] = s;
    __syncthreads();
    if (tid == 0) {
        float t = 0;
#pragma unroll
        for (int i = 0; i < 8; i++) t += red[i];
        red[0] = t;
    }
    __syncthreads();
    const float mean = red[0] / (float)D;
    __syncthreads();
    float dx = v.x - mean, dy = v.y - mean, dz = v.z - mean, dw = v.w - mean;
    float s2 = dx * dx + dy * dy + dz * dz + dw * dw;
#pragma unroll
    for (int o = 16; o; o >>= 1) s2 += __shfl_xor_sync(0xffffffffu, s2, o);
    if ((tid & 31) == 0) red[tid >> 5] = s2;
    __syncthreads();
    if (tid == 0) {
        float t = 0;
#pragma unroll
        for (int i = 0; i < 8; i++) t += red[i];
        red[0] = t;
    }
    __syncthreads();
    const float var = red[0] / (float)D;
    const float rstd = rsqrtf(var + 1e-5f);
    float4 g = *(const float4*)(gamma + tid * 4);
    float4 bb = *(const float4*)(beta + tid * 4);
    float4 u = *(const float4*)(g_H4 + (size_t)row * D4 + tid * 4);
    float z0 = ((v.x - mean) * rstd * g.x + bb.x) * u.x;
    float z1 = ((v.y - mean) * rstd * g.y + bb.y) * u.y;
    float z2 = ((v.z - mean) * rstd * g.z + bb.z) * u.z;
    float z3 = ((v.w - mean) * rstd * g.w + bb.w) * u.w;
    uint32_t* zh = (uint32_t*)(g_zh + (size_t)row * D + tid * 4);
    uint32_t* zl = (uint32_t*)(g_zl + (size_t)row * D + tid * 4);
    zh[0] = pk2(z0, z1);
    zh[1] = pk2(z2, z3);
    zl[0] = pk2(rlo(z0), rlo(z1));
    zl[1] = pk2(rlo(z2), rlo(z3));
}

// ---------------------------------------------------------------------------
extern "C" void kernel_launch(void* const* d_in, const int* in_sizes, int n_in,
                              void* d_out, int out_size) {
    (void)n_in;
    (void)out_size;
    const float* x = (const float*)d_in[0];
    const float* amask = (const float*)d_in[1];
    const void* kpm = d_in[2];
    const float* W_in = (const float*)d_in[3];
    const float* b_in = (const float*)d_in[4];
    const float* W_out = (const float*)d_in[5];
    const float* b_out = (const float*)d_in[6];
    const float* gamma = (const float*)d_in[7];
    const float* beta = (const float*)d_in[8];
    const float* rab = (const float*)d_in[9];
    float* out = (float*)d_out;

    const int D = in_sizes[7];
    int T = 1;
    while ((long long)T * T < (long long)in_sizes[1]) T++;
    const int B = in_sizes[0] / (T * D);
    const int H = in_sizes[9] / NBUCKETS;
    const int BT = B * T;
    const float alpha = rsqrtf((float)(D / H));

    float* pH4;
    cudaGetSymbolAddress((void**)&pH4, g_H4);
    __nv_bfloat16 *pxh, *pxl, *pwih, *pwil, *pwoh, *pwol, *pzh, *pzl;
    cudaGetSymbolAddress((void**)&pxh, g_xh);
    cudaGetSymbolAddress((void**)&pxl, g_xl);
    cudaGetSymbolAddress((void**)&pwih, g_wih);
    cudaGetSymbolAddress((void**)&pwil, g_wil);
    cudaGetSymbolAddress((void**)&pwoh, g_woh);
    cudaGetSymbolAddress((void**)&pwol, g_wol);
    cudaGetSymbolAddress((void**)&pzh, g_zh);
    cudaGetSymbolAddress((void**)&pzl, g_zl);

    cudaFuncSetAttribute(attn_kernel, cudaFuncAttributeMaxDynamicSharedMemorySize, ATTN_SMEM);
    cudaFuncSetAttribute(hgemm_kernel, cudaFuncAttributeMaxDynamicSharedMemorySize, GEMM_SMEM);

    split_kernel<<<(BT * D / 4 + 255) / 256, 256>>>(x, pxh, pxl, BT * D);
    split_kernel<<<(4 * D * D / 4 + 255) / 256, 256>>>(W_in, pwih, pwil, 4 * D * D);
    split_kernel<<<(D * D / 4 + 255) / 256, 256>>>(W_out, pwoh, pwol, D * D);

    prep_kernel<<<9, 256>>>(kpm, rab, B, T, H);
    denom_kernel<<<dim3(T, B), 256>>>(amask, B, T);
    hgemm_kernel<<<dim3(4 * D / 128, BT / 128), 256, GEMM_SMEM>>>(
        pxh, pxl, pwih, pwil, b_in, nullptr, pH4, BT, 4 * D, D, 0);
    convert_vt_kernel<<<dim3(T / 64, H, B), 256>>>(T, H, D);
    attn_kernel<<<dim3(T / 64, H, B), 256, ATTN_SMEM>>>(amask, T, H, D, alpha);
    ln_kernel<<<BT, D / 4>>>(gamma, beta, D);
    hgemm_kernel<<<dim3(D / 128, BT / 128), 256, GEMM_SMEM>>>(
        pzh, pzl, pwoh, pwol, b_out, x, out, BT, D, D, 1);
}